// round 2
// baseline (speedup 1.0000x reference)
#include <cuda_runtime.h>
#include <cstdint>
#include <cmath>

#define BATCH 4
#define SEQ   2048
#define DIM   1024
#define NH    16
#define DH    64
#define MTOK  (BATCH*SEQ)
#define N1    3200
#define NQKV  3072
#define NGATE 48

__device__ float g_xn  [MTOK * DIM];
__device__ float g_w1  [DIM * N1];
__device__ float g_w2  [DIM * DIM];
__device__ float g_qkv [MTOK * NQKV];
__device__ float g_gates[MTOK * NGATE];
__device__ float g_h   [MTOK * DIM];

__device__ __forceinline__ float to_tf32(float x) {
    uint32_t u; asm("cvt.rna.tf32.f32 %0, %1;\n" : "=r"(u) : "f"(x));
    return __uint_as_float(u);
}
__device__ __forceinline__ uint32_t smem_u32(const void* p) {
    return (uint32_t)__cvta_generic_to_shared(p);
}
__device__ __forceinline__ void cp16(uint32_t s, const void* g) {
    asm volatile("cp.async.cg.shared.global [%0], [%1], 16;\n" :: "r"(s), "l"(g));
}
__device__ __forceinline__ void cp4(uint32_t s, const void* g) {
    asm volatile("cp.async.ca.shared.global [%0], [%1], 4;\n" :: "r"(s), "l"(g));
}
__device__ __forceinline__ void cp_commit() {
    asm volatile("cp.async.commit_group;\n" ::: "memory");
}
template<int N> __device__ __forceinline__ void cp_wait() {
    asm volatile("cp.async.wait_group %0;\n" :: "n"(N) : "memory");
}
__device__ __forceinline__ void mma_tf32(float c[4],
        uint32_t a0, uint32_t a1, uint32_t a2, uint32_t a3,
        uint32_t b0, uint32_t b1) {
    asm volatile(
        "mma.sync.aligned.m16n8k8.row.col.f32.tf32.tf32.f32 "
        "{%0,%1,%2,%3},{%4,%5,%6,%7},{%8,%9},{%0,%1,%2,%3};\n"
        : "+f"(c[0]), "+f"(c[1]), "+f"(c[2]), "+f"(c[3])
        : "r"(a0), "r"(a1), "r"(a2), "r"(a3), "r"(b0), "r"(b1));
}

__global__ void __launch_bounds__(256) prep_weights_kernel(
        const float* __restrict__ wqkv, const float* __restrict__ wgate,
        const float* __restrict__ wout) {
    int idx = blockIdx.x * 256 + threadIdx.x;
    const int W1 = DIM * N1;
    if (idx < W1) {
        int k = idx / N1, n = idx - k * N1;
        float v = 0.f;
        if (n < NQKV)              v = wqkv[k * NQKV + n];
        else if (n < NQKV + NGATE) v = wgate[k * NGATE + (n - NQKV)];
        g_w1[idx] = to_tf32(v);
    } else {
        int j = idx - W1;
        if (j < DIM * DIM) g_w2[j] = to_tf32(wout[j]);
    }
}

__global__ void __launch_bounds__(256) rmsnorm_kernel(
        const float* __restrict__ x, const float* __restrict__ w) {
    const int row = blockIdx.x;
    const int tid = threadIdx.x;
    const float4 xv = ((const float4*)(x + (size_t)row * DIM))[tid];
    float ss = xv.x*xv.x + xv.y*xv.y + xv.z*xv.z + xv.w*xv.w;
    #pragma unroll
    for (int off = 16; off > 0; off >>= 1)
        ss += __shfl_xor_sync(0xffffffffu, ss, off);
    __shared__ float wsum[8];
    const int lane = tid & 31, wid = tid >> 5;
    if (lane == 0) wsum[wid] = ss;
    __syncthreads();
    if (tid == 0) {
        float t = 0.f;
        #pragma unroll
        for (int i = 0; i < 8; ++i) t += wsum[i];
        wsum[0] = rsqrtf(t * (1.0f / DIM) + 1e-6f);
    }
    __syncthreads();
    const float scale = wsum[0];
    const float4 wv = ((const float4*)w)[tid];
    float4 o;
    o.x = to_tf32(wv.x * (xv.x * scale));
    o.y = to_tf32(wv.y * (xv.y * scale));
    o.z = to_tf32(wv.z * (xv.z * scale));
    o.w = to_tf32(wv.w * (xv.w * scale));
    ((float4*)(g_xn + (size_t)row * DIM))[tid] = o;
}

// MODE 0: A=g_xn, B=g_w1 [1024xN1] -> g_qkv + g_gates
// MODE 1: A=g_h,  B=g_w2 [1024x1024] -> Out = X + A@B
template<int MODE>
__global__ void __launch_bounds__(256) gemm_tf32_kernel(
        const float* __restrict__ X, float* __restrict__ Out) {
    constexpr int K = DIM, KT = K / 32;
    constexpr int N = (MODE == 0) ? N1 : DIM;
    const float* __restrict__ Ap = (MODE == 0) ? g_xn : g_h;
    const float* __restrict__ Bp = (MODE == 0) ? g_w1 : g_w2;

    extern __shared__ float smem[];
    const int tid = threadIdx.x;
    const int m0 = blockIdx.y * 128, n0 = blockIdx.x * 128;
    const uint32_t smem_base = smem_u32(smem);

    auto issue = [&](int kt) {
        if (kt < KT) {
            const int stage = kt % 3;
            uint32_t sA = smem_base + (uint32_t)stage * 32768u;
            uint32_t sB = sA + 16384u;
            const float* Ag = Ap + (size_t)m0 * K + kt * 32;
            #pragma unroll
            for (int i = 0; i < 4; ++i) {
                int c = tid + 256 * i; int am = c >> 3, akc = c & 7;
                cp16(sA + (uint32_t)((am * 32 + ((akc ^ (am & 7)) << 2)) << 2),
                     Ag + am * K + akc * 4);
            }
            const float* Bg = Bp + (size_t)kt * 32 * N + n0;
            #pragma unroll
            for (int i = 0; i < 4; ++i) {
                int c = tid + 256 * i; int bk = c >> 5, bnc = c & 31;
                cp16(sB + (uint32_t)((bk * 128 + ((bnc ^ ((bk << 1) & 7)) << 2)) << 2),
                     Bg + bk * N + bnc * 4);
            }
        }
        cp_commit();
    };

    float acc[4][4][4];
    #pragma unroll
    for (int i = 0; i < 4; ++i)
        #pragma unroll
        for (int j = 0; j < 4; ++j)
            #pragma unroll
            for (int q = 0; q < 4; ++q) acc[i][j][q] = 0.f;

    issue(0); issue(1);

    const int lane = tid & 31, wid = tid >> 5;
    const int wm = (wid >> 2) * 64, wn = (wid & 3) * 32;
    const int gr = lane >> 2, tg = lane & 3;

    for (int kt = 0; kt < KT; ++kt) {
        cp_wait<1>();
        __syncthreads();
        issue(kt + 2);
        const float* As = smem + (kt % 3) * 8192;
        const float* Bs = As + 4096;
        #pragma unroll
        for (int kg = 0; kg < 4; ++kg) {
            const int k0 = kg * 8;
            uint32_t a[4][4], bb[4][2];
            const int kc0 = k0 + tg, kc1 = k0 + 4 + tg;
            #pragma unroll
            for (int i = 0; i < 4; ++i) {
                int r = wm + i * 16 + gr;
                a[i][0] = __float_as_uint(As[r     * 32 + (((kc0 >> 2) ^ (r & 7)) << 2) + (kc0 & 3)]);
                a[i][1] = __float_as_uint(As[(r+8) * 32 + (((kc0 >> 2) ^ ((r+8) & 7)) << 2) + (kc0 & 3)]);
                a[i][2] = __float_as_uint(As[r     * 32 + (((kc1 >> 2) ^ (r & 7)) << 2) + (kc1 & 3)]);
                a[i][3] = __float_as_uint(As[(r+8) * 32 + (((kc1 >> 2) ^ ((r+8) & 7)) << 2) + (kc1 & 3)]);
            }
            #pragma unroll
            for (int j = 0; j < 4; ++j) {
                int n = wn + j * 8 + gr;
                bb[j][0] = __float_as_uint(Bs[kc0 * 128 + (((n >> 2) ^ ((kc0 << 1) & 7)) << 2) + (n & 3)]);
                bb[j][1] = __float_as_uint(Bs[kc1 * 128 + (((n >> 2) ^ ((kc1 << 1) & 7)) << 2) + (n & 3)]);
            }
            #pragma unroll
            for (int i = 0; i < 4; ++i)
                #pragma unroll
                for (int j = 0; j < 4; ++j)
                    mma_tf32(acc[i][j], a[i][0], a[i][1], a[i][2], a[i][3],
                             bb[j][0], bb[j][1]);
        }
    }

    #pragma unroll
    for (int i = 0; i < 4; ++i) {
        #pragma unroll
        for (int j = 0; j < 4; ++j) {
            const int r0 = m0 + wm + i * 16 + gr;
            const int c0 = n0 + wn + j * 8 + tg * 2;
            #pragma unroll
            for (int q = 0; q < 4; ++q) {
                const int r = r0 + (q >> 1) * 8;
                const int c = c0 + (q & 1);
                const float v = acc[i][j][q];
                if (MODE == 0) {
                    if (c < NQKV) {
                        g_qkv[(size_t)r * NQKV + c] = v;
                    } else if (c < NQKV + NGATE) {
                        float t = tanhf(v * (1.0f / 15.0f));
                        g_gates[r * NGATE + (c - NQKV)] = 1.0f / (1.0f + expf(-15.0f * t));
                    }
                } else {
                    Out[(size_t)r * DIM + c] = X[(size_t)r * DIM + c] + v;
                }
            }
        }
    }
}

// Recurrence: block = (chain = b*16+h, e-half). 256 thr: e_local=tid>>3, dc=tid&7.
__global__ void __launch_bounds__(256) recur_kernel(const float* __restrict__ hidden) {
    constexpr int RS = 164;  // k[64] q[64] vhalf[32] gates[3] pad
    __shared__ float ring[16 * RS];
    const int tid = threadIdx.x;
    const int half = blockIdx.x & 1;
    const int chain = blockIdx.x >> 1;
    const int b = chain >> 4, hh = chain & 15;
    const int e_local = tid >> 3, dc = tid & 7;
    const int e = half * 32 + e_local;
    const int dbase = dc * 8;
    const int mbase = b * SEQ;

    float s[8];
    #pragma unroll
    for (int j = 0; j < 8; ++j)
        s[j] = hidden[(size_t)(((b * NH + hh) * DH) + dbase + j) * DH + e];

    auto issue = [&](int grp) {
        if (grp < SEQ / 4 && tid < 172) {
            const int slot_s = tid / 43;
            const int op = tid - slot_s * 43;
            const int t = grp * 4 + slot_s;
            float* sl = ring + (t & 15) * RS;
            const int m = mbase + t;
            const float* qkvrow = g_qkv + (size_t)m * NQKV;
            if (op < 16)
                cp16(smem_u32(sl + op * 4),              qkvrow + 1024 + hh * 64 + op * 4);
            else if (op < 32)
                cp16(smem_u32(sl + 64 + (op - 16) * 4),  qkvrow + hh * 64 + (op - 16) * 4);
            else if (op < 40)
                cp16(smem_u32(sl + 128 + (op - 32) * 4), qkvrow + 2048 + hh * 64 + half * 32 + (op - 32) * 4);
            else
                cp4(smem_u32(sl + 160 + (op - 40)),      g_gates + m * NGATE + (op - 40) * 16 + hh);
        }
        cp_commit();
    };

    issue(0); issue(1);

    for (int g = 0; g < SEQ / 4; ++g) {
        cp_wait<1>();
        __syncthreads();
        issue(g + 2);
        #pragma unroll
        for (int ss4 = 0; ss4 < 4; ++ss4) {
            const int t = g * 4 + ss4;
            const float* sl = ring + (t & 15) * RS;
            const float ig = sl[160], fg = sl[161], og = sl[162];
            const float ve = sl[128 + e_local];
            const float4 k0 = *(const float4*)(sl + dbase);
            const float4 k1 = *(const float4*)(sl + dbase + 4);
            const float4 q0 = *(const float4*)(sl + 64 + dbase);
            const float4 q1 = *(const float4*)(sl + 64 + dbase + 4);
            const float iv = ig * ve;
            float a0, a1;
            s[0] = fg * s[0] + iv * k0.x; a0  = q0.x * s[0];
            s[1] = fg * s[1] + iv * k0.y; a1  = q0.y * s[1];
            s[2] = fg * s[2] + iv * k0.z; a0 += q0.z * s[2];
            s[3] = fg * s[3] + iv * k0.w; a1 += q0.w * s[3];
            s[4] = fg * s[4] + iv * k1.x; a0 += q1.x * s[4];
            s[5] = fg * s[5] + iv * k1.y; a1 += q1.y * s[5];
            s[6] = fg * s[6] + iv * k1.z; a0 += q1.z * s[6];
            s[7] = fg * s[7] + iv * k1.w; a1 += q1.w * s[7];
            float accv = a0 + a1;
            accv += __shfl_down_sync(0xffffffffu, accv, 4, 8);
            accv += __shfl_down_sync(0xffffffffu, accv, 2, 8);
            accv += __shfl_down_sync(0xffffffffu, accv, 1, 8);
            if (dc == 0)
                g_h[(size_t)(mbase + t) * DIM + hh * 64 + e] = to_tf32(accv * og);
        }
    }
}

extern "C" void kernel_launch(void* const* d_in, const int* in_sizes, int n_in,
                              void* d_out, int out_size) {
    const float* x      = (const float*)d_in[0];
    const float* hidden = (const float*)d_in[1];
    const float* w_rms  = (const float*)d_in[2];
    const float* w_qkv  = (const float*)d_in[3];
    const float* w_gate = (const float*)d_in[4];
    const float* w_out  = (const float*)d_in[5];
    float* out = (float*)d_out;

    static bool attr_done = false;
    if (!attr_done) {
        cudaFuncSetAttribute(gemm_tf32_kernel<0>,
            cudaFuncAttributeMaxDynamicSharedMemorySize, 98304);
        cudaFuncSetAttribute(gemm_tf32_kernel<1>,
            cudaFuncAttributeMaxDynamicSharedMemorySize, 98304);
        attr_done = true;
    }

    prep_weights_kernel<<<(DIM * N1 + DIM * DIM) / 256, 256>>>(w_qkv, w_gate, w_out);
    rmsnorm_kernel<<<MTOK, 256>>>(x, w_rms);
    {
        dim3 grid(N1 / 128, MTOK / 128);
        gemm_tf32_kernel<0><<<grid, 256, 98304>>>(nullptr, nullptr);
    }
    recur_kernel<<<BATCH * NH * 2, 256>>>(hidden);
    {
        dim3 grid(DIM / 128, MTOK / 128);
        gemm_tf32_kernel<1><<<grid, 256, 98304>>>(x, out);
    }
}

// round 3
// speedup vs baseline: 2.0609x; 2.0609x over previous
#include <cuda_runtime.h>
#include <cstdint>
#include <cmath>

#define BATCH 4
#define SEQ   2048
#define DIM   1024
#define NH    16
#define DH    64
#define MTOK  (BATCH*SEQ)
#define N1    3200
#define NQKV  3072
#define NGATE 48
#define CHUNK 64
#define NCHUNK (SEQ/CHUNK)              // 32
#define TOTCHUNK (BATCH*NH*NCHUNK)      // 2048

__device__ float g_xn  [MTOK * DIM];
__device__ float g_w1  [DIM * N1];
__device__ float g_w2  [DIM * DIM];
__device__ float g_qkv [MTOK * NQKV];
__device__ float g_gates[MTOK * NGATE];
__device__ float g_h   [MTOK * DIM];
__device__ float g_qs  [MTOK * DIM];          // exp(LF_t) * q_t
__device__ float g_U   [TOTCHUNK * 64 * 64];  // per-chunk state increment
__device__ float g_Fc  [TOTCHUNK];            // per-chunk total decay

__device__ __forceinline__ float to_tf32(float x) {
    uint32_t u; asm("cvt.rna.tf32.f32 %0, %1;\n" : "=r"(u) : "f"(x));
    return __uint_as_float(u);
}
__device__ __forceinline__ uint32_t smem_u32(const void* p) {
    return (uint32_t)__cvta_generic_to_shared(p);
}
__device__ __forceinline__ void cp16(uint32_t s, const void* g) {
    asm volatile("cp.async.cg.shared.global [%0], [%1], 16;\n" :: "r"(s), "l"(g));
}
__device__ __forceinline__ void cp4(uint32_t s, const void* g) {
    asm volatile("cp.async.ca.shared.global [%0], [%1], 4;\n" :: "r"(s), "l"(g));
}
__device__ __forceinline__ void cp_commit() {
    asm volatile("cp.async.commit_group;\n" ::: "memory");
}
template<int N> __device__ __forceinline__ void cp_wait() {
    asm volatile("cp.async.wait_group %0;\n" :: "n"(N) : "memory");
}
__device__ __forceinline__ void mma_tf32(float c[4],
        uint32_t a0, uint32_t a1, uint32_t a2, uint32_t a3,
        uint32_t b0, uint32_t b1) {
    asm volatile(
        "mma.sync.aligned.m16n8k8.row.col.f32.tf32.tf32.f32 "
        "{%0,%1,%2,%3},{%4,%5,%6,%7},{%8,%9},{%0,%1,%2,%3};\n"
        : "+f"(c[0]), "+f"(c[1]), "+f"(c[2]), "+f"(c[3])
        : "r"(a0), "r"(a1), "r"(a2), "r"(a3), "r"(b0), "r"(b1));
}

__global__ void __launch_bounds__(256) prep_weights_kernel(
        const float* __restrict__ wqkv, const float* __restrict__ wgate,
        const float* __restrict__ wout) {
    int idx = blockIdx.x * 256 + threadIdx.x;
    const int W1 = DIM * N1;
    if (idx < W1) {
        int k = idx / N1, n = idx - k * N1;
        float v = 0.f;
        if (n < NQKV)              v = wqkv[k * NQKV + n];
        else if (n < NQKV + NGATE) v = wgate[k * NGATE + (n - NQKV)];
        g_w1[idx] = to_tf32(v);
    } else {
        int j = idx - W1;
        if (j < DIM * DIM) g_w2[j] = to_tf32(wout[j]);
    }
}

__global__ void __launch_bounds__(256) rmsnorm_kernel(
        const float* __restrict__ x, const float* __restrict__ w) {
    const int row = blockIdx.x;
    const int tid = threadIdx.x;
    const float4 xv = ((const float4*)(x + (size_t)row * DIM))[tid];
    float ss = xv.x*xv.x + xv.y*xv.y + xv.z*xv.z + xv.w*xv.w;
    #pragma unroll
    for (int off = 16; off > 0; off >>= 1)
        ss += __shfl_xor_sync(0xffffffffu, ss, off);
    __shared__ float wsum[8];
    const int lane = tid & 31, wid = tid >> 5;
    if (lane == 0) wsum[wid] = ss;
    __syncthreads();
    if (tid == 0) {
        float t = 0.f;
        #pragma unroll
        for (int i = 0; i < 8; ++i) t += wsum[i];
        wsum[0] = rsqrtf(t * (1.0f / DIM) + 1e-6f);
    }
    __syncthreads();
    const float scale = wsum[0];
    const float4 wv = ((const float4*)w)[tid];
    float4 o;
    o.x = to_tf32(wv.x * (xv.x * scale));
    o.y = to_tf32(wv.y * (xv.y * scale));
    o.z = to_tf32(wv.z * (xv.z * scale));
    o.w = to_tf32(wv.w * (xv.w * scale));
    ((float4*)(g_xn + (size_t)row * DIM))[tid] = o;
}

template<int MODE>
__global__ void __launch_bounds__(256) gemm_tf32_kernel(
        const float* __restrict__ X, float* __restrict__ Out) {
    constexpr int K = DIM, KT = K / 32;
    constexpr int N = (MODE == 0) ? N1 : DIM;
    const float* __restrict__ Ap = (MODE == 0) ? g_xn : g_h;
    const float* __restrict__ Bp = (MODE == 0) ? g_w1 : g_w2;

    extern __shared__ float smem[];
    const int tid = threadIdx.x;
    const int m0 = blockIdx.y * 128, n0 = blockIdx.x * 128;
    const uint32_t smem_base = smem_u32(smem);

    auto issue = [&](int kt) {
        if (kt < KT) {
            const int stage = kt % 3;
            uint32_t sA = smem_base + (uint32_t)stage * 32768u;
            uint32_t sB = sA + 16384u;
            const float* Ag = Ap + (size_t)m0 * K + kt * 32;
            #pragma unroll
            for (int i = 0; i < 4; ++i) {
                int c = tid + 256 * i; int am = c >> 3, akc = c & 7;
                cp16(sA + (uint32_t)((am * 32 + ((akc ^ (am & 7)) << 2)) << 2),
                     Ag + am * K + akc * 4);
            }
            const float* Bg = Bp + (size_t)kt * 32 * N + n0;
            #pragma unroll
            for (int i = 0; i < 4; ++i) {
                int c = tid + 256 * i; int bk = c >> 5, bnc = c & 31;
                cp16(sB + (uint32_t)((bk * 128 + ((bnc ^ ((bk << 1) & 7)) << 2)) << 2),
                     Bg + bk * N + bnc * 4);
            }
        }
        cp_commit();
    };

    float acc[4][4][4];
    #pragma unroll
    for (int i = 0; i < 4; ++i)
        #pragma unroll
        for (int j = 0; j < 4; ++j)
            #pragma unroll
            for (int q = 0; q < 4; ++q) acc[i][j][q] = 0.f;

    issue(0); issue(1);

    const int lane = tid & 31, wid = tid >> 5;
    const int wm = (wid >> 2) * 64, wn = (wid & 3) * 32;
    const int gr = lane >> 2, tg = lane & 3;

    for (int kt = 0; kt < KT; ++kt) {
        cp_wait<1>();
        __syncthreads();
        issue(kt + 2);
        const float* As = smem + (kt % 3) * 8192;
        const float* Bs = As + 4096;
        #pragma unroll
        for (int kg = 0; kg < 4; ++kg) {
            const int k0 = kg * 8;
            uint32_t a[4][4], bb[4][2];
            const int kc0 = k0 + tg, kc1 = k0 + 4 + tg;
            #pragma unroll
            for (int i = 0; i < 4; ++i) {
                int r = wm + i * 16 + gr;
                a[i][0] = __float_as_uint(As[r     * 32 + (((kc0 >> 2) ^ (r & 7)) << 2) + (kc0 & 3)]);
                a[i][1] = __float_as_uint(As[(r+8) * 32 + (((kc0 >> 2) ^ ((r+8) & 7)) << 2) + (kc0 & 3)]);
                a[i][2] = __float_as_uint(As[r     * 32 + (((kc1 >> 2) ^ (r & 7)) << 2) + (kc1 & 3)]);
                a[i][3] = __float_as_uint(As[(r+8) * 32 + (((kc1 >> 2) ^ ((r+8) & 7)) << 2) + (kc1 & 3)]);
            }
            #pragma unroll
            for (int j = 0; j < 4; ++j) {
                int n = wn + j * 8 + gr;
                bb[j][0] = __float_as_uint(Bs[kc0 * 128 + (((n >> 2) ^ ((kc0 << 1) & 7)) << 2) + (n & 3)]);
                bb[j][1] = __float_as_uint(Bs[kc1 * 128 + (((n >> 2) ^ ((kc1 << 1) & 7)) << 2) + (n & 3)]);
            }
            #pragma unroll
            for (int i = 0; i < 4; ++i)
                #pragma unroll
                for (int j = 0; j < 4; ++j)
                    mma_tf32(acc[i][j], a[i][0], a[i][1], a[i][2], a[i][3],
                             bb[j][0], bb[j][1]);
        }
    }

    #pragma unroll
    for (int i = 0; i < 4; ++i) {
        #pragma unroll
        for (int j = 0; j < 4; ++j) {
            const int r0 = m0 + wm + i * 16 + gr;
            const int c0 = n0 + wn + j * 8 + tg * 2;
            #pragma unroll
            for (int q = 0; q < 4; ++q) {
                const int r = r0 + (q >> 1) * 8;
                const int c = c0 + (q & 1);
                const float v = acc[i][j][q];
                if (MODE == 0) {
                    if (c < NQKV) {
                        g_qkv[(size_t)r * NQKV + c] = v;
                    } else if (c < NQKV + NGATE) {
                        float t = tanhf(v * (1.0f / 15.0f));
                        g_gates[r * NGATE + (c - NQKV)] = 1.0f / (1.0f + expf(-15.0f * t));
                    }
                } else {
                    Out[(size_t)r * DIM + c] = X[(size_t)r * DIM + c] + v;
                }
            }
        }
    }
}

// ---------------- chunkwise recurrence, phase 1 (parallel over 2048 chunks) ----
// Per chunk (b,h,c): h_intra, chunk increment U, total decay Fc, scaled q (qs).
#define RST 68
__global__ void __launch_bounds__(256) chunk_intra_kernel() {
    extern __shared__ float sm[];
    float* Q  = sm;                  // [64][RST] row layout (t, d)
    float* Kt = Q  + 64 * RST;       // [64][RST] TRANSPOSED (d, s)
    float* V  = Kt + 64 * RST;       // [64][RST] (s, e)
    float* A  = V  + 64 * RST;       // [64][RST] (t, s)
    float* LF = A  + 64 * RST;       // [64] cumulative log f
    float* Wi = LF + 64;             // [64] i gate
    float* Wc = Wi + 64;             // [64] exp(LF63-LFs)*i_s

    const int cidx = blockIdx.x;
    const int c = cidx & (NCHUNK - 1);
    const int bh = cidx >> 5;
    const int h = bh & 15, b = bh >> 4;
    const int m0 = b * SEQ + c * CHUNK;
    const int tid = threadIdx.x;

    // Q, V via cp.async (row layout)
    for (int idx = tid; idx < 1024; idx += 256) {
        int t = idx >> 4, dq = (idx & 15) << 2;
        const float* row = g_qkv + (size_t)(m0 + t) * NQKV + h * 64 + dq;
        cp16(smem_u32(Q + t * RST + dq), row);
        cp16(smem_u32(V + t * RST + dq), row + 2048);
    }
    cp_commit();
    // K transposed via scalar loads (coalesced global, 4-way STS once)
    for (int idx = tid; idx < 4096; idx += 256) {
        int t = idx >> 6, d = idx & 63;
        Kt[d * RST + t] = g_qkv[(size_t)(m0 + t) * NQKV + 1024 + h * 64 + d];
    }
    if (tid < 64) {
        Wi[tid] = g_gates[(size_t)(m0 + tid) * NGATE + h];          // i
        LF[tid] = g_gates[(size_t)(m0 + tid) * NGATE + 16 + h];     // f (temp)
    }
    cp_wait<0>();
    __syncthreads();

    if (tid < 64) LF[tid] = __logf(LF[tid]);
    __syncthreads();
    if (tid == 0) {
        float r = 0.f;
        for (int t = 0; t < 64; ++t) { r += LF[t]; LF[t] = r; }
    }
    __syncthreads();
    if (tid < 64) Wc[tid] = __expf(LF[63] - LF[tid]) * Wi[tid];

    const int tx = tid & 15, ty = tid >> 4;
    const int t0 = ty * 4, s0 = tx * 4;

    // GEMM1: raw = q_t . k_s  (Kt conflict-free float4 over s)
    float acc[4][4];
    #pragma unroll
    for (int i = 0; i < 4; ++i)
        #pragma unroll
        for (int j = 0; j < 4; ++j) acc[i][j] = 0.f;
    #pragma unroll 4
    for (int d = 0; d < 64; ++d) {
        float4 kv = *(const float4*)(Kt + d * RST + s0);
        float kvv[4] = {kv.x, kv.y, kv.z, kv.w};
        #pragma unroll
        for (int i = 0; i < 4; ++i) {
            float qv = Q[(t0 + i) * RST + d];
            #pragma unroll
            for (int j = 0; j < 4; ++j) acc[i][j] += qv * kvv[j];
        }
    }
    // scale + causal mask, store A
    #pragma unroll
    for (int i = 0; i < 4; ++i) {
        const int t = t0 + i;
        float4 st;
        float* p = &st.x;
        #pragma unroll
        for (int j = 0; j < 4; ++j) {
            const int s = s0 + j;
            p[j] = (s <= t) ? acc[i][j] * __expf(LF[t] - LF[s]) * Wi[s] : 0.f;
        }
        *(float4*)(A + t * RST + s0) = st;
    }
    __syncthreads();

    // GEMM2+3 fused: h_intra[t][e] = sum_s A[t][s] V[s][e]
    //                U[d][e]       = sum_s Wc[s] Kt[d][s]... (kk via Kt broadcast)
    const int e0 = s0, d0 = t0;
    float hacc[4][4], uacc[4][4];
    #pragma unroll
    for (int i = 0; i < 4; ++i)
        #pragma unroll
        for (int j = 0; j < 4; ++j) { hacc[i][j] = 0.f; uacc[i][j] = 0.f; }
    #pragma unroll 4
    for (int s = 0; s < 64; ++s) {
        float4 vv = *(const float4*)(V + s * RST + e0);
        float ve[4] = {vv.x, vv.y, vv.z, vv.w};
        const float w = Wc[s];
        float av[4], kk[4];
        #pragma unroll
        for (int j = 0; j < 4; ++j) {
            av[j] = A[(t0 + j) * RST + s];
            kk[j] = w * Kt[(d0 + j) * RST + s];
        }
        #pragma unroll
        for (int i = 0; i < 4; ++i)
            #pragma unroll
            for (int j = 0; j < 4; ++j) {
                hacc[i][j] += av[i] * ve[j];
                uacc[i][j] += kk[i] * ve[j];
            }
    }
    #pragma unroll
    for (int i = 0; i < 4; ++i) {
        float4 hs = {hacc[i][0], hacc[i][1], hacc[i][2], hacc[i][3]};
        *(float4*)(g_h + (size_t)(m0 + t0 + i) * DIM + h * 64 + e0) = hs;
        float4 us = {uacc[i][0], uacc[i][1], uacc[i][2], uacc[i][3]};
        *(float4*)(g_U + (size_t)cidx * 4096 + (d0 + i) * 64 + e0) = us;
    }
    // qs = exp(LF_t) * q_t
    for (int idx = tid; idx < 1024; idx += 256) {
        int t = idx >> 4, dq = (idx & 15) << 2;
        float4 qv = *(const float4*)(Q + t * RST + dq);
        const float sc = __expf(LF[t]);
        qv.x *= sc; qv.y *= sc; qv.z *= sc; qv.w *= sc;
        *(float4*)(g_qs + (size_t)(m0 + t) * DIM + h * 64 + dq) = qv;
    }
    if (tid == 0) g_Fc[cidx] = __expf(LF[63]);
}

// ---------------- chunkwise recurrence, phase 2 (scan over 32 chunks) ---------
// Block = (bh, e-half). S[64][32] in smem; 3-deep cp.async ring for qs/U/h/o.
__global__ void __launch_bounds__(256) chunk_scan_kernel(const float* __restrict__ hidden) {
    extern __shared__ float sm2[];
    float* S    = sm2;                 // [64][32]
    float* QS   = S   + 2048;          // 3 x [64][64]
    float* Ub   = QS  + 3 * 4096;      // 3 x [64][32]
    float* Hb   = Ub  + 3 * 2048;      // 3 x [64][32]
    float* Ob   = Hb  + 3 * 2048;      // 3 x [64]

    const int eh = blockIdx.x & 1;
    const int bh = blockIdx.x >> 1;
    const int h = bh & 15, b = bh >> 4;
    const int tid = threadIdx.x;
    const int tx = tid & 15, ty = tid >> 4;
    const int t0 = ty * 4, el = tx * 2;

    // init S half from hidden state
    for (int idx = tid; idx < 512; idx += 256) {
        int d = idx >> 3, e4 = (idx & 7) << 2;
        *(float4*)(S + d * 32 + e4) =
            *(const float4*)(hidden + (size_t)(bh * 64 + d) * 64 + eh * 32 + e4);
    }

    auto prefetch = [&](int c) {
        if (c < NCHUNK) {
            const int st = c % 3;
            const int m0 = b * SEQ + c * CHUNK;
            const int cidx = bh * NCHUNK + c;
            float* qb = QS + st * 4096;
            float* ub = Ub + st * 2048;
            float* hb = Hb + st * 2048;
            float* ob = Ob + st * 64;
            for (int idx = tid; idx < 1024; idx += 256) {
                int t = idx >> 4, d4 = (idx & 15) << 2;
                cp16(smem_u32(qb + t * 64 + d4),
                     g_qs + (size_t)(m0 + t) * DIM + h * 64 + d4);
            }
            for (int idx = tid; idx < 512; idx += 256) {
                int t = idx >> 3, e4 = (idx & 7) << 2;
                cp16(smem_u32(ub + t * 32 + e4),
                     g_U + (size_t)cidx * 4096 + t * 64 + eh * 32 + e4);
                cp16(smem_u32(hb + t * 32 + e4),
                     g_h + (size_t)(m0 + t) * DIM + h * 64 + eh * 32 + e4);
            }
            if (tid < 64)
                cp4(smem_u32(ob + tid),
                    g_gates + (size_t)(m0 + tid) * NGATE + 32 + h);
        }
        cp_commit();
    };

    prefetch(0);
    prefetch(1);

    for (int c = 0; c < NCHUNK; ++c) {
        cp_wait<1>();
        __syncthreads();
        prefetch(c + 2);
        const int st = c % 3;
        const int m0 = b * SEQ + c * CHUNK;
        const float* qb = QS + st * 4096;
        const float* ub = Ub + st * 2048;
        const float* hb = Hb + st * 2048;
        const float* ob = Ob + st * 64;

        float acc[4][2];
        #pragma unroll
        for (int i = 0; i < 4; ++i) {
            float2 hv = *(const float2*)(hb + (t0 + i) * 32 + el);
            acc[i][0] = hv.x; acc[i][1] = hv.y;
        }
        #pragma unroll 4
        for (int d = 0; d < 64; ++d) {
            float2 Sv = *(const float2*)(S + d * 32 + el);
            #pragma unroll
            for (int i = 0; i < 4; ++i) {
                const float qd = qb[(t0 + i) * 64 + d];
                acc[i][0] += qd * Sv.x;
                acc[i][1] += qd * Sv.y;
            }
        }
        #pragma unroll
        for (int i = 0; i < 4; ++i) {
            const float og = ob[t0 + i];
            float2 o2 = {acc[i][0] * og, acc[i][1] * og};
            *(float2*)(g_h + (size_t)(m0 + t0 + i) * DIM + h * 64 + eh * 32 + el) = o2;
        }
        __syncthreads();   // all S reads done before update
        const float Fc = g_Fc[bh * NCHUNK + c];
        for (int idx = tid; idx < 512; idx += 256) {
            float4 s4 = ((float4*)S)[idx];
            float4 u4 = ((const float4*)ub)[idx];
            s4.x = Fc * s4.x + u4.x;
            s4.y = Fc * s4.y + u4.y;
            s4.z = Fc * s4.z + u4.z;
            s4.w = Fc * s4.w + u4.w;
            ((float4*)S)[idx] = s4;
        }
    }
}

extern "C" void kernel_launch(void* const* d_in, const int* in_sizes, int n_in,
                              void* d_out, int out_size) {
    const float* x      = (const float*)d_in[0];
    const float* hidden = (const float*)d_in[1];
    const float* w_rms  = (const float*)d_in[2];
    const float* w_qkv  = (const float*)d_in[3];
    const float* w_gate = (const float*)d_in[4];
    const float* w_out  = (const float*)d_in[5];
    float* out = (float*)d_out;

    static bool attr_done = false;
    if (!attr_done) {
        cudaFuncSetAttribute(gemm_tf32_kernel<0>,
            cudaFuncAttributeMaxDynamicSharedMemorySize, 98304);
        cudaFuncSetAttribute(gemm_tf32_kernel<1>,
            cudaFuncAttributeMaxDynamicSharedMemorySize, 98304);
        cudaFuncSetAttribute(chunk_intra_kernel,
            cudaFuncAttributeMaxDynamicSharedMemorySize, 71000);
        cudaFuncSetAttribute(chunk_scan_kernel,
            cudaFuncAttributeMaxDynamicSharedMemorySize, 108000);
        attr_done = true;
    }

    prep_weights_kernel<<<(DIM * N1 + DIM * DIM) / 256, 256>>>(w_qkv, w_gate, w_out);
    rmsnorm_kernel<<<MTOK, 256>>>(x, w_rms);
    {
        dim3 grid(N1 / 128, MTOK / 128);
        gemm_tf32_kernel<0><<<grid, 256, 98304>>>(nullptr, nullptr);
    }
    chunk_intra_kernel<<<TOTCHUNK, 256, 71000>>>();
    chunk_scan_kernel<<<BATCH * NH * 2, 256, 108000>>>(hidden);
    {
        dim3 grid(DIM / 128, MTOK / 128);
        gemm_tf32_kernel<1><<<grid, 256, 98304>>>(x, out);
    }
}

// round 4
// speedup vs baseline: 2.2955x; 1.1139x over previous
#include <cuda_runtime.h>
#include <cstdint>
#include <cmath>

#define BATCH 4
#define SEQ   2048
#define DIM   1024
#define NH    16
#define DH    64
#define MTOK  (BATCH*SEQ)
#define N1    3200
#define NQKV  3072
#define NGATE 48
#define CHUNK 64
#define NCHUNK (SEQ/CHUNK)              // 32
#define TOTCHUNK (BATCH*NH*NCHUNK)      // 2048

// fragment-packed buffers
__device__ float g_xn  [MTOK * DIM];          // A-fragments of rmsnormed x
__device__ float g_w1  [DIM * N1];            // B-fragments of [wqkv|wgate|0]
__device__ float g_w2  [DIM * DIM];           // B-fragments of w_out
__device__ float g_hf  [MTOK * DIM];          // A-fragments of final h
// plain buffers
__device__ float g_qkv [MTOK * NQKV];
__device__ float g_gates[MTOK * NGATE];
__device__ float g_h   [MTOK * DIM];          // h_intra (plain)
__device__ float g_qs  [MTOK * DIM];
__device__ float g_U   [TOTCHUNK * 64 * 64];
__device__ float g_Fc  [TOTCHUNK];

__device__ __forceinline__ float to_tf32(float x) {
    uint32_t u; asm("cvt.rna.tf32.f32 %0, %1;\n" : "=r"(u) : "f"(x));
    return __uint_as_float(u);
}
__device__ __forceinline__ uint32_t smem_u32(const void* p) {
    return (uint32_t)__cvta_generic_to_shared(p);
}
__device__ __forceinline__ void cp16(uint32_t s, const void* g) {
    asm volatile("cp.async.cg.shared.global [%0], [%1], 16;\n" :: "r"(s), "l"(g));
}
__device__ __forceinline__ void cp4(uint32_t s, const void* g) {
    asm volatile("cp.async.ca.shared.global [%0], [%1], 4;\n" :: "r"(s), "l"(g));
}
__device__ __forceinline__ void cp_commit() {
    asm volatile("cp.async.commit_group;\n" ::: "memory");
}
template<int N> __device__ __forceinline__ void cp_wait() {
    asm volatile("cp.async.wait_group %0;\n" :: "n"(N) : "memory");
}
__device__ __forceinline__ void mma_tf32(float c[4],
        uint32_t a0, uint32_t a1, uint32_t a2, uint32_t a3,
        uint32_t b0, uint32_t b1) {
    asm volatile(
        "mma.sync.aligned.m16n8k8.row.col.f32.tf32.tf32.f32 "
        "{%0,%1,%2,%3},{%4,%5,%6,%7},{%8,%9},{%0,%1,%2,%3};\n"
        : "+f"(c[0]), "+f"(c[1]), "+f"(c[2]), "+f"(c[3])
        : "r"(a0), "r"(a1), "r"(a2), "r"(a3), "r"(b0), "r"(b1));
}
#define FU(x) __float_as_uint(x)

// ---- prep: pack weights into B-fragment layout ----
// B_f[kt][nb][kg][lane(32)][2] floats; lane=(gr<<2)|tg; pair={B[k0+tg][n],B[k0+4+tg][n]}
__global__ void __launch_bounds__(256) prep_weights_kernel(
        const float* __restrict__ wqkv, const float* __restrict__ wgate,
        const float* __restrict__ wout) {
    const int P1 = DIM * N1 / 2;
    const int P2 = DIM * DIM / 2;
    int idx = blockIdx.x * 256 + threadIdx.x;
    if (idx < P1) {
        const int ppk = N1 * 16;                 // pairs per k-tile
        int kt = idx / ppk, r = idx - kt * ppk;
        int nb = r >> 7, r2 = r & 127;
        int kg = r2 >> 5, lane = r2 & 31, gr = lane >> 2, tg = lane & 3;
        int k0 = kt * 32 + kg * 8 + tg;
        int n  = nb * 8 + gr;
        float v0 = 0.f, v1 = 0.f;
        if (n < NQKV)              { v0 = wqkv[k0 * NQKV + n];       v1 = wqkv[(k0+4) * NQKV + n]; }
        else if (n < NQKV + NGATE) { v0 = wgate[k0 * NGATE + n-NQKV]; v1 = wgate[(k0+4) * NGATE + n-NQKV]; }
        g_w1[idx*2]   = to_tf32(v0);
        g_w1[idx*2+1] = to_tf32(v1);
    } else if (idx < P1 + P2) {
        int j = idx - P1;
        const int ppk = DIM * 16;
        int kt = j / ppk, r = j - kt * ppk;
        int nb = r >> 7, r2 = r & 127;
        int kg = r2 >> 5, lane = r2 & 31, gr = lane >> 2, tg = lane & 3;
        int k0 = kt * 32 + kg * 8 + tg;
        int n  = nb * 8 + gr;
        g_w2[j*2]   = to_tf32(wout[k0 * DIM + n]);
        g_w2[j*2+1] = to_tf32(wout[(k0+4) * DIM + n]);
    }
}

// ---- rmsnorm -> A-fragment layout of g_xn ----
// A_f offset(m,k): ((((m>>7)*32 + (k>>5))*8 + ((m>>4)&7))*4 + ((k>>3)&3))*128
//                  + (m&7)*16 + (k&3)*4 + ((k>>2)&1) + 2*((m>>3)&1)
__global__ void __launch_bounds__(256) rmsnorm_kernel(
        const float* __restrict__ x, const float* __restrict__ w) {
    const int row = blockIdx.x;
    const int tid = threadIdx.x;
    const float4 xv = ((const float4*)(x + (size_t)row * DIM))[tid];
    float ss = xv.x*xv.x + xv.y*xv.y + xv.z*xv.z + xv.w*xv.w;
    #pragma unroll
    for (int off = 16; off > 0; off >>= 1)
        ss += __shfl_xor_sync(0xffffffffu, ss, off);
    __shared__ float wsum[8];
    const int lane = tid & 31, wid = tid >> 5;
    if (lane == 0) wsum[wid] = ss;
    __syncthreads();
    if (tid == 0) {
        float t = 0.f;
        #pragma unroll
        for (int i = 0; i < 8; ++i) t += wsum[i];
        wsum[0] = rsqrtf(t * (1.0f / DIM) + 1e-6f);
    }
    __syncthreads();
    const float scale = wsum[0];
    const float4 wv = ((const float4*)w)[tid];
    float o[4];
    o[0] = to_tf32(wv.x * (xv.x * scale));
    o[1] = to_tf32(wv.y * (xv.y * scale));
    o[2] = to_tf32(wv.z * (xv.z * scale));
    o[3] = to_tf32(wv.w * (xv.w * scale));
    const int mb = row >> 7, R = (row >> 4) & 7, gr = row & 7, half = (row >> 3) & 1;
    const int kt = tid >> 3, kg = (tid >> 1) & 3, sel = tid & 1;
    size_t base = (((size_t)(mb*32 + kt)*8 + R)*4 + kg)*128 + gr*16 + 2*half + sel;
    #pragma unroll
    for (int c = 0; c < 4; ++c) g_xn[base + c*4] = o[c];
}

// ---- fragment-packed tf32 GEMM (128x128x32, 8 warps, 2 CTA/SM) ----
template<int MODE>
__global__ void __launch_bounds__(256) gemm_tf32_kernel(
        const float* __restrict__ X, float* __restrict__ Out) {
    constexpr int K = DIM, KT = K / 32;
    constexpr int N = (MODE == 0) ? N1 : DIM;
    const float* __restrict__ Af = (MODE == 0) ? g_xn : g_hf;
    const float* __restrict__ Bf = (MODE == 0) ? g_w1 : g_w2;

    extern __shared__ float smem[];
    const int tid = threadIdx.x;
    const int mb = blockIdx.y, n0 = blockIdx.x * 128;
    const int m0 = mb * 128;
    const uint32_t smem_base = smem_u32(smem);

    auto issue = [&](int kt) {
        if (kt < KT) {
            const int stage = kt % 3;
            uint32_t sA = smem_base + (uint32_t)stage * 32768u;
            uint32_t sB = sA + 16384u;
            const float* srcA = Af + ((size_t)(mb * 32 + kt)) * 4096;
            const float* srcB = Bf + ((size_t)kt * (N >> 3) + (n0 >> 3)) * 256;
            #pragma unroll
            for (int q = 0; q < 4; ++q)
                cp16(sA + (uint32_t)(tid + q*256) * 16u, srcA + (tid + q*256) * 4);
            #pragma unroll
            for (int q = 0; q < 4; ++q)
                cp16(sB + (uint32_t)(tid + q*256) * 16u, srcB + (tid + q*256) * 4);
        }
        cp_commit();
    };

    float acc[4][4][4];
    #pragma unroll
    for (int i = 0; i < 4; ++i)
        #pragma unroll
        for (int j = 0; j < 4; ++j)
            #pragma unroll
            for (int q = 0; q < 4; ++q) acc[i][j][q] = 0.f;

    issue(0); issue(1);

    const int lane = tid & 31, wid = tid >> 5;
    const int R0 = (wid >> 2) * 4;     // warp m-offset in 16-row blocks
    const int nb0 = (wid & 3) * 4;     // warp n-offset in 8-col blocks
    const int wm = R0 * 16, wn = nb0 * 8;
    const int gr = lane >> 2, tg = lane & 3;

    for (int kt = 0; kt < KT; ++kt) {
        cp_wait<1>();
        __syncthreads();
        issue(kt + 2);
        const float* As = smem + (kt % 3) * 8192;
        const float* Bs = As + 4096;
        #pragma unroll
        for (int kg = 0; kg < 4; ++kg) {
            float4 af[4]; float2 bf[4];
            #pragma unroll
            for (int i = 0; i < 4; ++i)
                af[i] = *(const float4*)(As + ((R0 + i)*4 + kg)*128 + lane*4);
            #pragma unroll
            for (int j = 0; j < 4; ++j)
                bf[j] = *(const float2*)(Bs + ((nb0 + j)*4 + kg)*64 + lane*2);
            #pragma unroll
            for (int i = 0; i < 4; ++i)
                #pragma unroll
                for (int j = 0; j < 4; ++j)
                    mma_tf32(acc[i][j], FU(af[i].x), FU(af[i].z), FU(af[i].y), FU(af[i].w),
                             FU(bf[j].x), FU(bf[j].y));
        }
    }

    #pragma unroll
    for (int i = 0; i < 4; ++i) {
        #pragma unroll
        for (int j = 0; j < 4; ++j) {
            const int r0 = m0 + wm + i * 16 + gr;
            const int c0 = n0 + wn + j * 8 + tg * 2;
            #pragma unroll
            for (int q = 0; q < 4; ++q) {
                const int r = r0 + (q >> 1) * 8;
                const int c = c0 + (q & 1);
                const float v = acc[i][j][q];
                if (MODE == 0) {
                    if (c < NQKV) {
                        g_qkv[(size_t)r * NQKV + c] = v;
                    } else if (c < NQKV + NGATE) {
                        float t = tanhf(v * (1.0f / 15.0f));
                        g_gates[r * NGATE + (c - NQKV)] = 1.0f / (1.0f + expf(-15.0f * t));
                    }
                } else {
                    Out[(size_t)r * DIM + c] = X[(size_t)r * DIM + c] + v;
                }
            }
        }
    }
}

// ---- chunkwise phase 1 with tensor cores ----
#define RST 68
__global__ void __launch_bounds__(256) chunk_intra_kernel() {
    extern __shared__ float sm[];
    float* Q  = sm;                  // [64][68] (t,d) tf32; reused as Vw (s,e)
    float* Kt = Q  + 64 * RST;       // [64][68] (d,s) tf32
    float* V  = Kt + 64 * RST;       // [64][68] (s,e) tf32
    float* A  = V  + 64 * RST;       // [64][68] (t,s) tf32
    float* LF = A  + 64 * RST;
    float* Wi = LF + 64;
    float* Wc = Wi + 64;

    const int cidx = blockIdx.x;
    const int c = cidx & (NCHUNK - 1);
    const int bh = cidx >> 5;
    const int h = bh & 15, b = bh >> 4;
    const int m0 = b * SEQ + c * CHUNK;
    const int tid = threadIdx.x;

    for (int idx = tid; idx < 1024; idx += 256) {
        int t = idx >> 4, dq = (idx & 15) << 2;
        const float* row = g_qkv + (size_t)(m0 + t) * NQKV + h * 64 + dq;
        cp16(smem_u32(Q + t * RST + dq), row);
        cp16(smem_u32(V + t * RST + dq), row + 2048);
    }
    cp_commit();
    for (int idx = tid; idx < 4096; idx += 256) {
        int t = idx >> 6, d = idx & 63;
        Kt[d * RST + t] = to_tf32(g_qkv[(size_t)(m0 + t) * NQKV + 1024 + h * 64 + d]);
    }
    if (tid < 64) {
        Wi[tid] = g_gates[(size_t)(m0 + tid) * NGATE + h];
        LF[tid] = g_gates[(size_t)(m0 + tid) * NGATE + 16 + h];
    }
    cp_wait<0>();
    __syncthreads();

    // round Q, V to tf32 in place
    for (int idx = tid; idx < 1024; idx += 256) {
        int t = idx >> 4, dq = (idx & 15) << 2;
        float4 qv = *(float4*)(Q + t * RST + dq);
        qv.x = to_tf32(qv.x); qv.y = to_tf32(qv.y); qv.z = to_tf32(qv.z); qv.w = to_tf32(qv.w);
        *(float4*)(Q + t * RST + dq) = qv;
        float4 vv = *(float4*)(V + t * RST + dq);
        vv.x = to_tf32(vv.x); vv.y = to_tf32(vv.y); vv.z = to_tf32(vv.z); vv.w = to_tf32(vv.w);
        *(float4*)(V + t * RST + dq) = vv;
    }
    if (tid < 64) LF[tid] = __logf(LF[tid]);
    __syncthreads();
    if (tid == 0) {
        float r = 0.f;
        for (int t = 0; t < 64; ++t) { r += LF[t]; LF[t] = r; }
    }
    __syncthreads();
    if (tid < 64) Wc[tid] = __expf(LF[63] - LF[tid]) * Wi[tid];
    if (tid == 0) g_Fc[cidx] = __expf(LF[63]);
    __syncthreads();

    // qs = exp(LF_t) * q_t (before Q is reused)
    for (int idx = tid; idx < 1024; idx += 256) {
        int t = idx >> 4, dq = (idx & 15) << 2;
        float4 qv = *(const float4*)(Q + t * RST + dq);
        const float sc = __expf(LF[t]);
        qv.x *= sc; qv.y *= sc; qv.z *= sc; qv.w *= sc;
        *(float4*)(g_qs + (size_t)(m0 + t) * DIM + h * 64 + dq) = qv;
    }

    const int lane = tid & 31, wid = tid >> 5;
    const int gr = lane >> 2, tg = lane & 3;
    const int wm = (wid >> 1) * 16, wn = (wid & 1) * 32;

    // GEMM1: S_A[t][s] = sum_d Q[t][d]*Kt[d][s]
    float acc1[4][4];
    #pragma unroll
    for (int j = 0; j < 4; ++j)
        #pragma unroll
        for (int q = 0; q < 4; ++q) acc1[j][q] = 0.f;
    #pragma unroll
    for (int ks = 0; ks < 8; ++ks) {
        const int kc0 = ks * 8 + tg, kc1 = kc0 + 4;
        uint32_t a0 = FU(Q[(wm + gr) * RST + kc0]);
        uint32_t a1 = FU(Q[(wm + 8 + gr) * RST + kc0]);
        uint32_t a2 = FU(Q[(wm + gr) * RST + kc1]);
        uint32_t a3 = FU(Q[(wm + 8 + gr) * RST + kc1]);
        #pragma unroll
        for (int j = 0; j < 4; ++j) {
            const int n = wn + j * 8 + gr;
            mma_tf32(acc1[j], a0, a1, a2, a3,
                     FU(Kt[kc0 * RST + n]), FU(Kt[kc1 * RST + n]));
        }
    }
    #pragma unroll
    for (int j = 0; j < 4; ++j)
        #pragma unroll
        for (int q = 0; q < 4; ++q) {
            const int t = wm + gr + (q >> 1) * 8;
            const int s = wn + j * 8 + tg * 2 + (q & 1);
            float v = 0.f;
            if (s <= t) v = acc1[j][q] * __expf(LF[t] - LF[s]) * Wi[s];
            A[t * RST + s] = to_tf32(v);
        }
    __syncthreads();

    // Vw into Q buffer
    for (int idx = tid; idx < 1024; idx += 256) {
        int s = idx >> 4, e4 = (idx & 15) << 2;
        float4 vv = *(const float4*)(V + s * RST + e4);
        const float w = Wc[s];
        vv.x = to_tf32(w * vv.x); vv.y = to_tf32(w * vv.y);
        vv.z = to_tf32(w * vv.z); vv.w = to_tf32(w * vv.w);
        *(float4*)(Q + s * RST + e4) = vv;
    }
    __syncthreads();

    // GEMM2: h[t][e] = sum_s A[t][s]*V[s][e];  GEMM3: U[d][e] = sum_s Kt[d][s]*Vw[s][e]
    float hacc[4][4], uacc[4][4];
    #pragma unroll
    for (int j = 0; j < 4; ++j)
        #pragma unroll
        for (int q = 0; q < 4; ++q) { hacc[j][q] = 0.f; uacc[j][q] = 0.f; }
    #pragma unroll
    for (int ks = 0; ks < 8; ++ks) {
        const int kc0 = ks * 8 + tg, kc1 = kc0 + 4;
        uint32_t ha0 = FU(A[(wm + gr) * RST + kc0]);
        uint32_t ha1 = FU(A[(wm + 8 + gr) * RST + kc0]);
        uint32_t ha2 = FU(A[(wm + gr) * RST + kc1]);
        uint32_t ha3 = FU(A[(wm + 8 + gr) * RST + kc1]);
        uint32_t ka0 = FU(Kt[(wm + gr) * RST + kc0]);
        uint32_t ka1 = FU(Kt[(wm + 8 + gr) * RST + kc0]);
        uint32_t ka2 = FU(Kt[(wm + gr) * RST + kc1]);
        uint32_t ka3 = FU(Kt[(wm + 8 + gr) * RST + kc1]);
        #pragma unroll
        for (int j = 0; j < 4; ++j) {
            const int n = wn + j * 8 + gr;
            mma_tf32(hacc[j], ha0, ha1, ha2, ha3,
                     FU(V[kc0 * RST + n]), FU(V[kc1 * RST + n]));
            mma_tf32(uacc[j], ka0, ka1, ka2, ka3,
                     FU(Q[kc0 * RST + n]), FU(Q[kc1 * RST + n]));
        }
    }
    #pragma unroll
    for (int j = 0; j < 4; ++j)
        #pragma unroll
        for (int q = 0; q < 4; ++q) {
            const int row = wm + gr + (q >> 1) * 8;
            const int col = wn + j * 8 + tg * 2 + (q & 1);
            g_h[(size_t)(m0 + row) * DIM + h * 64 + col] = hacc[j][q];
            g_U[(size_t)cidx * 4096 + row * 64 + col] = uacc[j][q];
        }
}

// ---- chunkwise phase 2 (scan); final h written in A-fragment layout ----
__global__ void __launch_bounds__(256) chunk_scan_kernel(const float* __restrict__ hidden) {
    extern __shared__ float sm2[];
    float* S    = sm2;                 // [64][32]
    float* QS   = S   + 2048;          // 3 x [64][64]
    float* Ub   = QS  + 3 * 4096;      // 3 x [64][32]
    float* Hb   = Ub  + 3 * 2048;      // 3 x [64][32]
    float* Ob   = Hb  + 3 * 2048;      // 3 x [64]

    const int eh = blockIdx.x & 1;
    const int bh = blockIdx.x >> 1;
    const int h = bh & 15, b = bh >> 4;
    const int tid = threadIdx.x;
    const int tx = tid & 15, ty = tid >> 4;
    const int t0 = ty * 4, el = tx * 2;

    for (int idx = tid; idx < 512; idx += 256) {
        int d = idx >> 3, e4 = (idx & 7) << 2;
        *(float4*)(S + d * 32 + e4) =
            *(const float4*)(hidden + (size_t)(bh * 64 + d) * 64 + eh * 32 + e4);
    }

    auto prefetch = [&](int c) {
        if (c < NCHUNK) {
            const int st = c % 3;
            const int m0 = b * SEQ + c * CHUNK;
            const int cidx = bh * NCHUNK + c;
            float* qb = QS + st * 4096;
            float* ub = Ub + st * 2048;
            float* hb = Hb + st * 2048;
            float* ob = Ob + st * 64;
            for (int idx = tid; idx < 1024; idx += 256) {
                int t = idx >> 4, d4 = (idx & 15) << 2;
                cp16(smem_u32(qb + t * 64 + d4),
                     g_qs + (size_t)(m0 + t) * DIM + h * 64 + d4);
            }
            for (int idx = tid; idx < 512; idx += 256) {
                int t = idx >> 3, e4 = (idx & 7) << 2;
                cp16(smem_u32(ub + t * 32 + e4),
                     g_U + (size_t)cidx * 4096 + t * 64 + eh * 32 + e4);
                cp16(smem_u32(hb + t * 32 + e4),
                     g_h + (size_t)(m0 + t) * DIM + h * 64 + eh * 32 + e4);
            }
            if (tid < 64)
                cp4(smem_u32(ob + tid),
                    g_gates + (size_t)(m0 + tid) * NGATE + 32 + h);
        }
        cp_commit();
    };

    prefetch(0);
    prefetch(1);

    const int kt = h * 2 + eh;                  // constant k-tile for this block
    const int kg = el >> 3, sel = (el >> 2) & 1, tgc = el & 3;

    for (int c = 0; c < NCHUNK; ++c) {
        cp_wait<1>();
        __syncthreads();
        prefetch(c + 2);
        const int st = c % 3;
        const int m0 = b * SEQ + c * CHUNK;
        const float* qb = QS + st * 4096;
        const float* ub = Ub + st * 2048;
        const float* hb = Hb + st * 2048;
        const float* ob = Ob + st * 64;

        float acc[4][2];
        #pragma unroll
        for (int i = 0; i < 4; ++i) {
            float2 hv = *(const float2*)(hb + (t0 + i) * 32 + el);
            acc[i][0] = hv.x; acc[i][1] = hv.y;
        }
        #pragma unroll 4
        for (int d = 0; d < 64; ++d) {
            float2 Sv = *(const float2*)(S + d * 32 + el);
            #pragma unroll
            for (int i = 0; i < 4; ++i) {
                const float qd = qb[(t0 + i) * 64 + d];
                acc[i][0] += qd * Sv.x;
                acc[i][1] += qd * Sv.y;
            }
        }
        #pragma unroll
        for (int i = 0; i < 4; ++i) {
            const float og = ob[t0 + i];
            const int m = m0 + t0 + i;
            const int mb = m >> 7, R = (m >> 4) & 7, gr = m & 7, half = (m >> 3) & 1;
            size_t base = (((size_t)(mb*32 + kt)*8 + R)*4 + kg)*128
                        + gr*16 + 2*half + sel;
            g_hf[base + tgc*4]       = to_tf32(acc[i][0] * og);
            g_hf[base + (tgc+1)*4]   = to_tf32(acc[i][1] * og);
        }
        __syncthreads();
        const float Fc = g_Fc[bh * NCHUNK + c];
        for (int idx = tid; idx < 512; idx += 256) {
            float4 s4 = ((float4*)S)[idx];
            float4 u4 = ((const float4*)ub)[idx];
            s4.x = Fc * s4.x + u4.x;
            s4.y = Fc * s4.y + u4.y;
            s4.z = Fc * s4.z + u4.z;
            s4.w = Fc * s4.w + u4.w;
            ((float4*)S)[idx] = s4;
        }
    }
}

extern "C" void kernel_launch(void* const* d_in, const int* in_sizes, int n_in,
                              void* d_out, int out_size) {
    const float* x      = (const float*)d_in[0];
    const float* hidden = (const float*)d_in[1];
    const float* w_rms  = (const float*)d_in[2];
    const float* w_qkv  = (const float*)d_in[3];
    const float* w_gate = (const float*)d_in[4];
    const float* w_out  = (const float*)d_in[5];
    float* out = (float*)d_out;

    static bool attr_done = false;
    if (!attr_done) {
        cudaFuncSetAttribute(gemm_tf32_kernel<0>,
            cudaFuncAttributeMaxDynamicSharedMemorySize, 98304);
        cudaFuncSetAttribute(gemm_tf32_kernel<1>,
            cudaFuncAttributeMaxDynamicSharedMemorySize, 98304);
        cudaFuncSetAttribute(chunk_intra_kernel,
            cudaFuncAttributeMaxDynamicSharedMemorySize, 71000);
        cudaFuncSetAttribute(chunk_scan_kernel,
            cudaFuncAttributeMaxDynamicSharedMemorySize, 108000);
        attr_done = true;
    }

    const int PAIRS = DIM * N1 / 2 + DIM * DIM / 2;
    prep_weights_kernel<<<(PAIRS + 255) / 256, 256>>>(w_qkv, w_gate, w_out);
    rmsnorm_kernel<<<MTOK, 256>>>(x, w_rms);
    {
        dim3 grid(N1 / 128, MTOK / 128);
        gemm_tf32_kernel<0><<<grid, 256, 98304>>>(nullptr, nullptr);
    }
    chunk_intra_kernel<<<TOTCHUNK, 256, 71000>>>();
    chunk_scan_kernel<<<BATCH * NH * 2, 256, 108000>>>(hidden);
    {
        dim3 grid(DIM / 128, MTOK / 128);
        gemm_tf32_kernel<1><<<grid, 256, 98304>>>(x, out);
    }
}

// round 5
// speedup vs baseline: 2.3502x; 1.0238x over previous
#include <cuda_runtime.h>
#include <cstdint>
#include <cmath>

#define BATCH 4
#define SEQ   2048
#define DIM   1024
#define NH    16
#define DH    64
#define MTOK  (BATCH*SEQ)
#define N1    3200
#define NQKV  3072
#define NGATE 48
#define CHUNK 64
#define NCHUNK (SEQ/CHUNK)              // 32
#define TOTCHUNK (BATCH*NH*NCHUNK)      // 2048

// fragment-packed buffers
__device__ float g_xn  [MTOK * DIM];          // A-fragments of rmsnormed x
__device__ float g_w1  [DIM * N1];            // B-fragments of [wqkv|wgate|0]
__device__ float g_w2  [DIM * DIM];           // B-fragments of w_out
__device__ float g_hf  [MTOK * DIM];          // A-fragments of final h
// plain buffers
__device__ float g_qkv [MTOK * NQKV];
__device__ float g_gates[MTOK * NGATE];
__device__ float g_h   [MTOK * DIM];          // h_intra (plain)
__device__ float g_qs  [MTOK * DIM];
__device__ float g_U   [TOTCHUNK * 64 * 64];
__device__ float g_S   [TOTCHUNK * 64 * 64];  // state before each chunk
__device__ float g_Fc  [TOTCHUNK];

__device__ __forceinline__ float to_tf32(float x) {
    uint32_t u; asm("cvt.rna.tf32.f32 %0, %1;\n" : "=r"(u) : "f"(x));
    return __uint_as_float(u);
}
__device__ __forceinline__ uint32_t smem_u32(const void* p) {
    return (uint32_t)__cvta_generic_to_shared(p);
}
__device__ __forceinline__ void cp16(uint32_t s, const void* g) {
    asm volatile("cp.async.cg.shared.global [%0], [%1], 16;\n" :: "r"(s), "l"(g));
}
__device__ __forceinline__ void cp4(uint32_t s, const void* g) {
    asm volatile("cp.async.ca.shared.global [%0], [%1], 4;\n" :: "r"(s), "l"(g));
}
__device__ __forceinline__ void cp_commit() {
    asm volatile("cp.async.commit_group;\n" ::: "memory");
}
template<int N> __device__ __forceinline__ void cp_wait() {
    asm volatile("cp.async.wait_group %0;\n" :: "n"(N) : "memory");
}
__device__ __forceinline__ void mma_tf32(float c[4],
        uint32_t a0, uint32_t a1, uint32_t a2, uint32_t a3,
        uint32_t b0, uint32_t b1) {
    asm volatile(
        "mma.sync.aligned.m16n8k8.row.col.f32.tf32.tf32.f32 "
        "{%0,%1,%2,%3},{%4,%5,%6,%7},{%8,%9},{%0,%1,%2,%3};\n"
        : "+f"(c[0]), "+f"(c[1]), "+f"(c[2]), "+f"(c[3])
        : "r"(a0), "r"(a1), "r"(a2), "r"(a3), "r"(b0), "r"(b1));
}
#define FU(x) __float_as_uint(x)

// ---- prep: pack weights into B-fragment layout ----
__global__ void __launch_bounds__(256) prep_weights_kernel(
        const float* __restrict__ wqkv, const float* __restrict__ wgate,
        const float* __restrict__ wout) {
    const int P1 = DIM * N1 / 2;
    const int P2 = DIM * DIM / 2;
    int idx = blockIdx.x * 256 + threadIdx.x;
    if (idx < P1) {
        const int ppk = N1 * 16;
        int kt = idx / ppk, r = idx - kt * ppk;
        int nb = r >> 7, r2 = r & 127;
        int kg = r2 >> 5, lane = r2 & 31, gr = lane >> 2, tg = lane & 3;
        int k0 = kt * 32 + kg * 8 + tg;
        int n  = nb * 8 + gr;
        float v0 = 0.f, v1 = 0.f;
        if (n < NQKV)              { v0 = wqkv[k0 * NQKV + n];       v1 = wqkv[(k0+4) * NQKV + n]; }
        else if (n < NQKV + NGATE) { v0 = wgate[k0 * NGATE + n-NQKV]; v1 = wgate[(k0+4) * NGATE + n-NQKV]; }
        g_w1[idx*2]   = to_tf32(v0);
        g_w1[idx*2+1] = to_tf32(v1);
    } else if (idx < P1 + P2) {
        int j = idx - P1;
        const int ppk = DIM * 16;
        int kt = j / ppk, r = j - kt * ppk;
        int nb = r >> 7, r2 = r & 127;
        int kg = r2 >> 5, lane = r2 & 31, gr = lane >> 2, tg = lane & 3;
        int k0 = kt * 32 + kg * 8 + tg;
        int n  = nb * 8 + gr;
        g_w2[j*2]   = to_tf32(wout[k0 * DIM + n]);
        g_w2[j*2+1] = to_tf32(wout[(k0+4) * DIM + n]);
    }
}

// ---- rmsnorm -> A-fragment layout ----
__global__ void __launch_bounds__(256) rmsnorm_kernel(
        const float* __restrict__ x, const float* __restrict__ w) {
    const int row = blockIdx.x;
    const int tid = threadIdx.x;
    const float4 xv = ((const float4*)(x + (size_t)row * DIM))[tid];
    float ss = xv.x*xv.x + xv.y*xv.y + xv.z*xv.z + xv.w*xv.w;
    #pragma unroll
    for (int off = 16; off > 0; off >>= 1)
        ss += __shfl_xor_sync(0xffffffffu, ss, off);
    __shared__ float wsum[8];
    const int lane = tid & 31, wid = tid >> 5;
    if (lane == 0) wsum[wid] = ss;
    __syncthreads();
    if (tid == 0) {
        float t = 0.f;
        #pragma unroll
        for (int i = 0; i < 8; ++i) t += wsum[i];
        wsum[0] = rsqrtf(t * (1.0f / DIM) + 1e-6f);
    }
    __syncthreads();
    const float scale = wsum[0];
    const float4 wv = ((const float4*)w)[tid];
    float o[4];
    o[0] = to_tf32(wv.x * (xv.x * scale));
    o[1] = to_tf32(wv.y * (xv.y * scale));
    o[2] = to_tf32(wv.z * (xv.z * scale));
    o[3] = to_tf32(wv.w * (xv.w * scale));
    const int mb = row >> 7, R = (row >> 4) & 7, gr = row & 7, half = (row >> 3) & 1;
    const int kt = tid >> 3, kg = (tid >> 1) & 3, sel = tid & 1;
    size_t base = (((size_t)(mb*32 + kt)*8 + R)*4 + kg)*128 + gr*16 + 2*half + sel;
    #pragma unroll
    for (int c = 0; c < 4; ++c) g_xn[base + c*4] = o[c];
}

// ---- fragment-packed tf32 GEMM (128x128x32, 8 warps) ----
template<int MODE>
__global__ void __launch_bounds__(256) gemm_tf32_kernel(
        const float* __restrict__ X, float* __restrict__ Out) {
    constexpr int K = DIM, KT = K / 32;
    constexpr int N = (MODE == 0) ? N1 : DIM;
    const float* __restrict__ Af = (MODE == 0) ? g_xn : g_hf;
    const float* __restrict__ Bf = (MODE == 0) ? g_w1 : g_w2;

    extern __shared__ float smem[];
    const int tid = threadIdx.x;
    const int mb = blockIdx.y, n0 = blockIdx.x * 128;
    const int m0 = mb * 128;
    const uint32_t smem_base = smem_u32(smem);

    auto issue = [&](int kt) {
        if (kt < KT) {
            const int stage = kt % 3;
            uint32_t sA = smem_base + (uint32_t)stage * 32768u;
            uint32_t sB = sA + 16384u;
            const float* srcA = Af + ((size_t)(mb * 32 + kt)) * 4096;
            const float* srcB = Bf + ((size_t)kt * (N >> 3) + (n0 >> 3)) * 256;
            #pragma unroll
            for (int q = 0; q < 4; ++q)
                cp16(sA + (uint32_t)(tid + q*256) * 16u, srcA + (tid + q*256) * 4);
            #pragma unroll
            for (int q = 0; q < 4; ++q)
                cp16(sB + (uint32_t)(tid + q*256) * 16u, srcB + (tid + q*256) * 4);
        }
        cp_commit();
    };

    float acc[4][4][4];
    #pragma unroll
    for (int i = 0; i < 4; ++i)
        #pragma unroll
        for (int j = 0; j < 4; ++j)
            #pragma unroll
            for (int q = 0; q < 4; ++q) acc[i][j][q] = 0.f;

    issue(0); issue(1);

    const int lane = tid & 31, wid = tid >> 5;
    const int R0 = (wid >> 2) * 4;
    const int nb0 = (wid & 3) * 4;
    const int wm = R0 * 16, wn = nb0 * 8;
    const int gr = lane >> 2, tg = lane & 3;

    for (int kt = 0; kt < KT; ++kt) {
        cp_wait<1>();
        __syncthreads();
        issue(kt + 2);
        const float* As = smem + (kt % 3) * 8192;
        const float* Bs = As + 4096;
        #pragma unroll
        for (int kg = 0; kg < 4; ++kg) {
            float4 af[4]; float2 bf[4];
            #pragma unroll
            for (int i = 0; i < 4; ++i)
                af[i] = *(const float4*)(As + ((R0 + i)*4 + kg)*128 + lane*4);
            #pragma unroll
            for (int j = 0; j < 4; ++j)
                bf[j] = *(const float2*)(Bs + ((nb0 + j)*4 + kg)*64 + lane*2);
            #pragma unroll
            for (int i = 0; i < 4; ++i)
                #pragma unroll
                for (int j = 0; j < 4; ++j)
                    mma_tf32(acc[i][j], FU(af[i].x), FU(af[i].z), FU(af[i].y), FU(af[i].w),
                             FU(bf[j].x), FU(bf[j].y));
        }
    }

    #pragma unroll
    for (int i = 0; i < 4; ++i) {
        #pragma unroll
        for (int j = 0; j < 4; ++j) {
            const int r0 = m0 + wm + i * 16 + gr;
            const int c0 = n0 + wn + j * 8 + tg * 2;
            #pragma unroll
            for (int q = 0; q < 4; ++q) {
                const int r = r0 + (q >> 1) * 8;
                const int c = c0 + (q & 1);
                const float v = acc[i][j][q];
                if (MODE == 0) {
                    if (c < NQKV) {
                        g_qkv[(size_t)r * NQKV + c] = v;
                    } else if (c < NQKV + NGATE) {
                        float t = tanhf(v * (1.0f / 15.0f));
                        g_gates[r * NGATE + (c - NQKV)] = 1.0f / (1.0f + expf(-15.0f * t));
                    }
                } else {
                    Out[(size_t)r * DIM + c] = X[(size_t)r * DIM + c] + v;
                }
            }
        }
    }
}

// ---- chunkwise phase 1: intra-chunk (tensor cores) ----
#define RST 68
__global__ void __launch_bounds__(256) chunk_intra_kernel() {
    extern __shared__ float sm[];
    float* Q  = sm;                  // [64][68] (t,d); reused as Vw (s,e)
    float* Kt = Q  + 64 * RST;       // [64][68] (d,s)
    float* V  = Kt + 64 * RST;       // [64][68] (s,e)
    float* A  = V  + 64 * RST;       // [64][68] (t,s)
    float* LF = A  + 64 * RST;
    float* Wi = LF + 64;
    float* Wc = Wi + 64;

    const int cidx = blockIdx.x;
    const int c = cidx & (NCHUNK - 1);
    const int bh = cidx >> 5;
    const int h = bh & 15, b = bh >> 4;
    const int m0 = b * SEQ + c * CHUNK;
    const int tid = threadIdx.x;

    for (int idx = tid; idx < 1024; idx += 256) {
        int t = idx >> 4, dq = (idx & 15) << 2;
        const float* row = g_qkv + (size_t)(m0 + t) * NQKV + h * 64 + dq;
        cp16(smem_u32(Q + t * RST + dq), row);
        cp16(smem_u32(V + t * RST + dq), row + 2048);
    }
    cp_commit();
    for (int idx = tid; idx < 4096; idx += 256) {
        int t = idx >> 6, d = idx & 63;
        Kt[d * RST + t] = to_tf32(g_qkv[(size_t)(m0 + t) * NQKV + 1024 + h * 64 + d]);
    }
    if (tid < 64) {
        Wi[tid] = g_gates[(size_t)(m0 + tid) * NGATE + h];
        LF[tid] = g_gates[(size_t)(m0 + tid) * NGATE + 16 + h];
    }
    cp_wait<0>();
    __syncthreads();

    for (int idx = tid; idx < 1024; idx += 256) {
        int t = idx >> 4, dq = (idx & 15) << 2;
        float4 qv = *(float4*)(Q + t * RST + dq);
        qv.x = to_tf32(qv.x); qv.y = to_tf32(qv.y); qv.z = to_tf32(qv.z); qv.w = to_tf32(qv.w);
        *(float4*)(Q + t * RST + dq) = qv;
        float4 vv = *(float4*)(V + t * RST + dq);
        vv.x = to_tf32(vv.x); vv.y = to_tf32(vv.y); vv.z = to_tf32(vv.z); vv.w = to_tf32(vv.w);
        *(float4*)(V + t * RST + dq) = vv;
    }
    if (tid < 64) LF[tid] = __logf(LF[tid]);
    __syncthreads();
    if (tid == 0) {
        float r = 0.f;
        for (int t = 0; t < 64; ++t) { r += LF[t]; LF[t] = r; }
    }
    __syncthreads();
    if (tid < 64) Wc[tid] = __expf(LF[63] - LF[tid]) * Wi[tid];
    if (tid == 0) g_Fc[cidx] = __expf(LF[63]);
    __syncthreads();

    for (int idx = tid; idx < 1024; idx += 256) {
        int t = idx >> 4, dq = (idx & 15) << 2;
        float4 qv = *(const float4*)(Q + t * RST + dq);
        const float sc = __expf(LF[t]);
        qv.x *= sc; qv.y *= sc; qv.z *= sc; qv.w *= sc;
        *(float4*)(g_qs + (size_t)(m0 + t) * DIM + h * 64 + dq) = qv;
    }

    const int lane = tid & 31, wid = tid >> 5;
    const int gr = lane >> 2, tg = lane & 3;
    const int wm = (wid >> 1) * 16, wn = (wid & 1) * 32;

    float acc1[4][4];
    #pragma unroll
    for (int j = 0; j < 4; ++j)
        #pragma unroll
        for (int q = 0; q < 4; ++q) acc1[j][q] = 0.f;
    #pragma unroll
    for (int ks = 0; ks < 8; ++ks) {
        const int kc0 = ks * 8 + tg, kc1 = kc0 + 4;
        uint32_t a0 = FU(Q[(wm + gr) * RST + kc0]);
        uint32_t a1 = FU(Q[(wm + 8 + gr) * RST + kc0]);
        uint32_t a2 = FU(Q[(wm + gr) * RST + kc1]);
        uint32_t a3 = FU(Q[(wm + 8 + gr) * RST + kc1]);
        #pragma unroll
        for (int j = 0; j < 4; ++j) {
            const int n = wn + j * 8 + gr;
            mma_tf32(acc1[j], a0, a1, a2, a3,
                     FU(Kt[kc0 * RST + n]), FU(Kt[kc1 * RST + n]));
        }
    }
    #pragma unroll
    for (int j = 0; j < 4; ++j)
        #pragma unroll
        for (int q = 0; q < 4; ++q) {
            const int t = wm + gr + (q >> 1) * 8;
            const int s = wn + j * 8 + tg * 2 + (q & 1);
            float v = 0.f;
            if (s <= t) v = acc1[j][q] * __expf(LF[t] - LF[s]) * Wi[s];
            A[t * RST + s] = to_tf32(v);
        }
    __syncthreads();

    for (int idx = tid; idx < 1024; idx += 256) {
        int s = idx >> 4, e4 = (idx & 15) << 2;
        float4 vv = *(const float4*)(V + s * RST + e4);
        const float w = Wc[s];
        vv.x = to_tf32(w * vv.x); vv.y = to_tf32(w * vv.y);
        vv.z = to_tf32(w * vv.z); vv.w = to_tf32(w * vv.w);
        *(float4*)(Q + s * RST + e4) = vv;
    }
    __syncthreads();

    float hacc[4][4], uacc[4][4];
    #pragma unroll
    for (int j = 0; j < 4; ++j)
        #pragma unroll
        for (int q = 0; q < 4; ++q) { hacc[j][q] = 0.f; uacc[j][q] = 0.f; }
    #pragma unroll
    for (int ks = 0; ks < 8; ++ks) {
        const int kc0 = ks * 8 + tg, kc1 = kc0 + 4;
        uint32_t ha0 = FU(A[(wm + gr) * RST + kc0]);
        uint32_t ha1 = FU(A[(wm + 8 + gr) * RST + kc0]);
        uint32_t ha2 = FU(A[(wm + gr) * RST + kc1]);
        uint32_t ha3 = FU(A[(wm + 8 + gr) * RST + kc1]);
        uint32_t ka0 = FU(Kt[(wm + gr) * RST + kc0]);
        uint32_t ka1 = FU(Kt[(wm + 8 + gr) * RST + kc0]);
        uint32_t ka2 = FU(Kt[(wm + gr) * RST + kc1]);
        uint32_t ka3 = FU(Kt[(wm + 8 + gr) * RST + kc1]);
        #pragma unroll
        for (int j = 0; j < 4; ++j) {
            const int n = wn + j * 8 + gr;
            mma_tf32(hacc[j], ha0, ha1, ha2, ha3,
                     FU(V[kc0 * RST + n]), FU(V[kc1 * RST + n]));
            mma_tf32(uacc[j], ka0, ka1, ka2, ka3,
                     FU(Q[kc0 * RST + n]), FU(Q[kc1 * RST + n]));
        }
    }
    #pragma unroll
    for (int j = 0; j < 4; ++j)
        #pragma unroll
        for (int q = 0; q < 4; ++q) {
            const int row = wm + gr + (q >> 1) * 8;
            const int col = wn + j * 8 + tg * 2 + (q & 1);
            g_h[(size_t)(m0 + row) * DIM + h * 64 + col] = hacc[j][q];
            g_U[(size_t)cidx * 4096 + row * 64 + col] = uacc[j][q];
        }
}

// ---- phase 2a: element-parallel state prefix over chunks ----
// thread -> (bh, 4 consecutive state elems); serial over 32 chunks.
__global__ void __launch_bounds__(256) state_prefix_kernel(const float* __restrict__ hidden) {
    const int gid = blockIdx.x * 256 + threadIdx.x;   // 65536 threads
    const int bh = gid >> 10;
    const int off = (gid & 1023) * 4;
    float4 S = *(const float4*)(hidden + (size_t)bh * 4096 + off);
    const float* fc = g_Fc + bh * NCHUNK;
    #pragma unroll 4
    for (int c = 0; c < NCHUNK; ++c) {
        const size_t p = (size_t)(bh * NCHUNK + c) * 4096 + off;
        *(float4*)(g_S + p) = S;
        const float4 U = *(const float4*)(g_U + p);
        const float F = fc[c];
        S.x = F * S.x + U.x;
        S.y = F * S.y + U.y;
        S.z = F * S.z + U.z;
        S.w = F * S.w + U.w;
    }
}

// ---- phase 2b: h = (Qs @ S_c + h_intra) * o, packed to A-fragment layout ----
__global__ void __launch_bounds__(256) chunk_inter_kernel() {
    extern __shared__ float sm3[];
    float* Qs = sm3;                 // [64][RST] (t,d)
    float* Sb = Qs + 64 * RST;       // [64][RST] (d,e)
    float* Og = Sb + 64 * RST;       // [64]

    const int cidx = blockIdx.x;
    const int c = cidx & (NCHUNK - 1);
    const int bh = cidx >> 5;
    const int h = bh & 15, b = bh >> 4;
    const int m0 = b * SEQ + c * CHUNK;
    const int tid = threadIdx.x;

    for (int idx = tid; idx < 1024; idx += 256) {
        int t = idx >> 4, d4 = (idx & 15) << 2;
        cp16(smem_u32(Qs + t * RST + d4), g_qs + (size_t)(m0 + t) * DIM + h * 64 + d4);
        cp16(smem_u32(Sb + t * RST + d4), g_S + (size_t)cidx * 4096 + t * 64 + d4);
    }
    if (tid < 64)
        cp4(smem_u32(Og + tid), g_gates + (size_t)(m0 + tid) * NGATE + 32 + h);
    cp_commit();
    cp_wait<0>();
    __syncthreads();

    // round both operands to tf32 in place
    for (int idx = tid; idx < 2048; idx += 256) {
        float* p = (idx < 1024) ? Qs : Sb;
        int r = (idx & 1023) >> 4, d4 = (idx & 15) << 2;
        float4 v = *(float4*)(p + r * RST + d4);
        v.x = to_tf32(v.x); v.y = to_tf32(v.y); v.z = to_tf32(v.z); v.w = to_tf32(v.w);
        *(float4*)(p + r * RST + d4) = v;
    }
    __syncthreads();

    const int lane = tid & 31, wid = tid >> 5;
    const int gr = lane >> 2, tg = lane & 3;
    const int wm = (wid >> 1) * 16, wn = (wid & 1) * 32;

    float acc[4][4];
    #pragma unroll
    for (int j = 0; j < 4; ++j)
        #pragma unroll
        for (int q = 0; q < 4; ++q) acc[j][q] = 0.f;
    #pragma unroll
    for (int ks = 0; ks < 8; ++ks) {
        const int kc0 = ks * 8 + tg, kc1 = kc0 + 4;
        uint32_t a0 = FU(Qs[(wm + gr) * RST + kc0]);
        uint32_t a1 = FU(Qs[(wm + 8 + gr) * RST + kc0]);
        uint32_t a2 = FU(Qs[(wm + gr) * RST + kc1]);
        uint32_t a3 = FU(Qs[(wm + 8 + gr) * RST + kc1]);
        #pragma unroll
        for (int j = 0; j < 4; ++j) {
            const int n = wn + j * 8 + gr;
            mma_tf32(acc[j], a0, a1, a2, a3,
                     FU(Sb[kc0 * RST + n]), FU(Sb[kc1 * RST + n]));
        }
    }

    #pragma unroll
    for (int j = 0; j < 4; ++j)
        #pragma unroll
        for (int q = 0; q < 4; ++q) {
            const int row = wm + gr + (q >> 1) * 8;
            const int col = wn + j * 8 + tg * 2 + (q & 1);
            const int m = m0 + row;
            const float hv = (acc[j][q] +
                g_h[(size_t)m * DIM + h * 64 + col]) * Og[row];
            const int k = h * 64 + col;
            const int mb = m >> 7, R = (m >> 4) & 7, grm = m & 7, half = (m >> 3) & 1;
            const int kt = k >> 5, kg = (k >> 3) & 3, sel = (k >> 2) & 1, tgc = k & 3;
            g_hf[(((size_t)(mb*32 + kt)*8 + R)*4 + kg)*128
                 + grm*16 + 2*half + sel + tgc*4] = to_tf32(hv);
        }
}

extern "C" void kernel_launch(void* const* d_in, const int* in_sizes, int n_in,
                              void* d_out, int out_size) {
    const float* x      = (const float*)d_in[0];
    const float* hidden = (const float*)d_in[1];
    const float* w_rms  = (const float*)d_in[2];
    const float* w_qkv  = (const float*)d_in[3];
    const float* w_gate = (const float*)d_in[4];
    const float* w_out  = (const float*)d_in[5];
    float* out = (float*)d_out;

    static bool attr_done = false;
    if (!attr_done) {
        cudaFuncSetAttribute(gemm_tf32_kernel<0>,
            cudaFuncAttributeMaxDynamicSharedMemorySize, 98304);
        cudaFuncSetAttribute(gemm_tf32_kernel<1>,
            cudaFuncAttributeMaxDynamicSharedMemorySize, 98304);
        cudaFuncSetAttribute(chunk_intra_kernel,
            cudaFuncAttributeMaxDynamicSharedMemorySize, 71000);
        cudaFuncSetAttribute(chunk_inter_kernel,
            cudaFuncAttributeMaxDynamicSharedMemorySize, 36000);
        attr_done = true;
    }

    const int PAIRS = DIM * N1 / 2 + DIM * DIM / 2;
    prep_weights_kernel<<<(PAIRS + 255) / 256, 256>>>(w_qkv, w_gate, w_out);
    rmsnorm_kernel<<<MTOK, 256>>>(x, w_rms);
    {
        dim3 grid(N1 / 128, MTOK / 128);
        gemm_tf32_kernel<0><<<grid, 256, 98304>>>(nullptr, nullptr);
    }
    chunk_intra_kernel<<<TOTCHUNK, 256, 71000>>>();
    state_prefix_kernel<<<256, 256>>>(hidden);
    chunk_inter_kernel<<<TOTCHUNK, 256, 36000>>>();
    {
        dim3 grid(DIM / 128, MTOK / 128);
        gemm_tf32_kernel<1><<<grid, 256, 98304>>>(x, out);
    }
}

// round 7
// speedup vs baseline: 3.5869x; 1.5262x over previous
#include <cuda_runtime.h>
#include <cuda_fp16.h>
#include <cstdint>
#include <cmath>

#define BATCH 4
#define SEQ   2048
#define DIM   1024
#define NH    16
#define DH    64
#define MTOK  (BATCH*SEQ)
#define N1    3200
#define NQKV  3072
#define NGATE 48
#define CHUNK 64
#define NCHUNK (SEQ/CHUNK)              // 32
#define TOTCHUNK (BATCH*NH*NCHUNK)      // 2048

// fp16 fragment-packed GEMM operands
__device__ __half2 g_xnh [MTOK * DIM / 2];    // A-fragments of rmsnormed x
__device__ __half2 g_w1h [N1 * DIM / 2];      // B-fragments of [wqkv|wgate|0]
__device__ __half2 g_w2h [DIM * DIM / 2];     // B-fragments of w_out
__device__ __half2 g_hfh [MTOK * DIM / 2];    // A-fragments of final h
// plain buffers
__device__ float g_qkv [MTOK * NQKV];
__device__ float g_gates[MTOK * NGATE];
__device__ float g_h   [MTOK * DIM];          // h_intra
__device__ float g_qs  [MTOK * DIM];
__device__ float g_U   [TOTCHUNK * 64 * 64];
__device__ float g_S   [TOTCHUNK * 64 * 64];
__device__ float g_Fc  [TOTCHUNK];

__device__ __forceinline__ float to_tf32(float x) {
    uint32_t u; asm("cvt.rna.tf32.f32 %0, %1;\n" : "=r"(u) : "f"(x));
    return __uint_as_float(u);
}
__device__ __forceinline__ uint32_t smem_u32(const void* p) {
    return (uint32_t)__cvta_generic_to_shared(p);
}
__device__ __forceinline__ void cp16(uint32_t s, const void* g) {
    asm volatile("cp.async.cg.shared.global [%0], [%1], 16;\n" :: "r"(s), "l"(g));
}
__device__ __forceinline__ void cp4(uint32_t s, const void* g) {
    asm volatile("cp.async.ca.shared.global [%0], [%1], 4;\n" :: "r"(s), "l"(g));
}
__device__ __forceinline__ void cp_commit() {
    asm volatile("cp.async.commit_group;\n" ::: "memory");
}
template<int N> __device__ __forceinline__ void cp_wait() {
    asm volatile("cp.async.wait_group %0;\n" :: "n"(N) : "memory");
}
__device__ __forceinline__ void mma_tf32(float c[4],
        uint32_t a0, uint32_t a1, uint32_t a2, uint32_t a3,
        uint32_t b0, uint32_t b1) {
    asm volatile(
        "mma.sync.aligned.m16n8k8.row.col.f32.tf32.tf32.f32 "
        "{%0,%1,%2,%3},{%4,%5,%6,%7},{%8,%9},{%0,%1,%2,%3};\n"
        : "+f"(c[0]), "+f"(c[1]), "+f"(c[2]), "+f"(c[3])
        : "r"(a0), "r"(a1), "r"(a2), "r"(a3), "r"(b0), "r"(b1));
}
__device__ __forceinline__ void mma_f16(float c[4],
        uint32_t a0, uint32_t a1, uint32_t a2, uint32_t a3,
        uint32_t b0, uint32_t b1) {
    asm volatile(
        "mma.sync.aligned.m16n8k16.row.col.f32.f16.f16.f32 "
        "{%0,%1,%2,%3},{%4,%5,%6,%7},{%8,%9},{%0,%1,%2,%3};\n"
        : "+f"(c[0]), "+f"(c[1]), "+f"(c[2]), "+f"(c[3])
        : "r"(a0), "r"(a1), "r"(a2), "r"(a3), "r"(b0), "r"(b1));
}
#define FU(x) __float_as_uint(x)

// A-fragment half2 offset for (m, k even): layout (mb, kt, R, ks, lane, reg)
__device__ __forceinline__ size_t afrag_off(int m, int k) {
    const int mb = m >> 7, kt = k >> 5, R = (m >> 4) & 7, ks = (k >> 4) & 1;
    const int gr = m & 7, hb = (m >> 3) & 1, tg = (k & 7) >> 1, kh = (k >> 3) & 1;
    return ((((size_t)(mb * 32 + kt) * 8 + R) * 2 + ks) * 128)
         + (gr * 4 + tg) * 4 + (hb + 2 * kh);
}

// ---- prep: pack weights into fp16 B-fragment layout ----
// offset = ((kt*(N/8)+nb)*2+ks)*64 + lane*2 + kh ; n=nb*8+gr ; k=kt*32+ks*16+kh*8+tg*2
__global__ void __launch_bounds__(256) prep_weights_kernel(
        const float* __restrict__ wqkv, const float* __restrict__ wgate,
        const float* __restrict__ wout) {
    const int P1 = N1 * DIM / 2;
    const int P2 = DIM * DIM / 2;
    const int idx = blockIdx.x * 256 + threadIdx.x;
    if (idx < P1) {
        const int kh = idx & 1, lane = (idx >> 1) & 31, ks = (idx >> 6) & 1;
        const int nbkt = idx >> 7, nb = nbkt % 400, kt = nbkt / 400;
        const int gr = lane >> 2, tg = lane & 3;
        const int n = nb * 8 + gr;
        const int k = kt * 32 + ks * 16 + kh * 8 + tg * 2;
        float v0 = 0.f, v1 = 0.f;
        if (n < NQKV)              { v0 = wqkv[k * NQKV + n];        v1 = wqkv[(k+1) * NQKV + n]; }
        else if (n < NQKV + NGATE) { v0 = wgate[k * NGATE + n-NQKV]; v1 = wgate[(k+1) * NGATE + n-NQKV]; }
        g_w1h[idx] = __floats2half2_rn(v0, v1);
    } else if (idx < P1 + P2) {
        const int j = idx - P1;
        const int kh = j & 1, lane = (j >> 1) & 31, ks = (j >> 6) & 1;
        const int nbkt = j >> 7, nb = nbkt % 128, kt = nbkt / 128;
        const int gr = lane >> 2, tg = lane & 3;
        const int n = nb * 8 + gr;
        const int k = kt * 32 + ks * 16 + kh * 8 + tg * 2;
        g_w2h[j] = __floats2half2_rn(wout[k * DIM + n], wout[(k+1) * DIM + n]);
    }
}

// ---- rmsnorm -> fp16 A-fragment layout ----
__global__ void __launch_bounds__(256) rmsnorm_kernel(
        const float* __restrict__ x, const float* __restrict__ w) {
    const int row = blockIdx.x;
    const int tid = threadIdx.x;
    const float4 xv = ((const float4*)(x + (size_t)row * DIM))[tid];
    float ss = xv.x*xv.x + xv.y*xv.y + xv.z*xv.z + xv.w*xv.w;
    #pragma unroll
    for (int off = 16; off > 0; off >>= 1)
        ss += __shfl_xor_sync(0xffffffffu, ss, off);
    __shared__ float wsum[8];
    const int lane = tid & 31, wid = tid >> 5;
    if (lane == 0) wsum[wid] = ss;
    __syncthreads();
    if (tid == 0) {
        float t = 0.f;
        #pragma unroll
        for (int i = 0; i < 8; ++i) t += wsum[i];
        wsum[0] = rsqrtf(t * (1.0f / DIM) + 1e-6f);
    }
    __syncthreads();
    const float scale = wsum[0];
    const float4 wv = ((const float4*)w)[tid];
    const int k0 = tid * 4;
    g_xnh[afrag_off(row, k0)]     = __floats2half2_rn(wv.x * (xv.x * scale), wv.y * (xv.y * scale));
    g_xnh[afrag_off(row, k0 + 2)] = __floats2half2_rn(wv.z * (xv.z * scale), wv.w * (xv.w * scale));
}

// ---- fp16 fragment-packed GEMM (128x128x32 tiles, m16n8k16, 8 warps) ----
// MODE 0: A=g_xnh, B=g_w1h -> qkv + gates    MODE 1: A=g_hfh, B=g_w2h -> Out = X + A@B^T
template<int MODE>
__global__ void __launch_bounds__(256) gemm_f16_kernel(
        const float* __restrict__ X, float* __restrict__ Out) {
    constexpr int KT = DIM / 32;
    constexpr int N = (MODE == 0) ? N1 : DIM;
    const __half2* __restrict__ Af = (MODE == 0) ? g_xnh : g_hfh;
    const __half2* __restrict__ Bf = (MODE == 0) ? g_w1h : g_w2h;

    extern __shared__ float smem[];
    const int tid = threadIdx.x;
    const int mb = blockIdx.y, n0 = blockIdx.x * 128;
    const int m0 = mb * 128;
    const uint32_t smem_base = smem_u32(smem);

    auto issue = [&](int kt) {
        if (kt < KT) {
            const uint32_t st = smem_base + (uint32_t)(kt % 3) * 16384u;
            const __half2* sA = Af + (size_t)(mb * 32 + kt) * 2048;
            const __half2* sB = Bf + ((size_t)kt * (N >> 3) + (n0 >> 3)) * 128;
            cp16(st + (uint32_t)tid * 16u,           sA + tid * 4);
            cp16(st + (uint32_t)(tid + 256) * 16u,   sA + (tid + 256) * 4);
            cp16(st + 8192u + (uint32_t)tid * 16u,         sB + tid * 4);
            cp16(st + 8192u + (uint32_t)(tid + 256) * 16u, sB + (tid + 256) * 4);
        }
        cp_commit();
    };

    float acc[4][4][4];
    #pragma unroll
    for (int i = 0; i < 4; ++i)
        #pragma unroll
        for (int j = 0; j < 4; ++j)
            #pragma unroll
            for (int q = 0; q < 4; ++q) acc[i][j][q] = 0.f;

    issue(0); issue(1);

    const int lane = tid & 31, wid = tid >> 5;
    const int R0 = (wid >> 2) * 4;     // m-blocks of 16
    const int nb0 = (wid & 3) * 4;     // n-blocks of 8
    const int wm = R0 * 16, wn = nb0 * 8;
    const int gr = lane >> 2, tg = lane & 3;

    for (int kt = 0; kt < KT; ++kt) {
        cp_wait<1>();
        __syncthreads();
        issue(kt + 2);
        const __half2* As = (const __half2*)((const char*)smem + (kt % 3) * 16384);
        const __half2* Bs = As + 2048;
        #pragma unroll
        for (int ks = 0; ks < 2; ++ks) {
            float4 af[4]; float2 bf[4];
            #pragma unroll
            for (int i = 0; i < 4; ++i)
                af[i] = *(const float4*)(As + ((R0 + i) * 2 + ks) * 128 + lane * 4);
            #pragma unroll
            for (int j = 0; j < 4; ++j)
                bf[j] = *(const float2*)(Bs + ((nb0 + j) * 2 + ks) * 64 + lane * 2);
            #pragma unroll
            for (int i = 0; i < 4; ++i)
                #pragma unroll
                for (int j = 0; j < 4; ++j)
                    mma_f16(acc[i][j], FU(af[i].x), FU(af[i].y), FU(af[i].z), FU(af[i].w),
                            FU(bf[j].x), FU(bf[j].y));
        }
    }

    #pragma unroll
    for (int i = 0; i < 4; ++i) {
        #pragma unroll
        for (int j = 0; j < 4; ++j) {
            const int r0 = m0 + wm + i * 16 + gr;
            const int c0 = n0 + wn + j * 8 + tg * 2;
            #pragma unroll
            for (int q = 0; q < 4; ++q) {
                const int r = r0 + (q >> 1) * 8;
                const int c = c0 + (q & 1);
                const float v = acc[i][j][q];
                if (MODE == 0) {
                    if (c < NQKV) {
                        g_qkv[(size_t)r * NQKV + c] = v;
                    } else if (c < NQKV + NGATE) {
                        float t = tanhf(v * (1.0f / 15.0f));
                        g_gates[r * NGATE + (c - NQKV)] = 1.0f / (1.0f + expf(-15.0f * t));
                    }
                } else {
                    Out[(size_t)r * DIM + c] = X[(size_t)r * DIM + c] + v;
                }
            }
        }
    }
}

// ---- chunkwise phase 1: intra-chunk (tf32 mma.sync) ----
#define RST 68
__global__ void __launch_bounds__(256) chunk_intra_kernel() {
    extern __shared__ float sm[];
    float* Q  = sm;
    float* Kt = Q  + 64 * RST;
    float* V  = Kt + 64 * RST;
    float* A  = V  + 64 * RST;
    float* LF = A  + 64 * RST;
    float* Wi = LF + 64;
    float* Wc = Wi + 64;

    const int cidx = blockIdx.x;
    const int c = cidx & (NCHUNK - 1);
    const int bh = cidx >> 5;
    const int h = bh & 15, b = bh >> 4;
    const int m0 = b * SEQ + c * CHUNK;
    const int tid = threadIdx.x;

    for (int idx = tid; idx < 1024; idx += 256) {
        int t = idx >> 4, dq = (idx & 15) << 2;
        const float* row = g_qkv + (size_t)(m0 + t) * NQKV + h * 64 + dq;
        cp16(smem_u32(Q + t * RST + dq), row);
        cp16(smem_u32(V + t * RST + dq), row + 2048);
    }
    cp_commit();
    for (int idx = tid; idx < 4096; idx += 256) {
        int t = idx >> 6, d = idx & 63;
        Kt[d * RST + t] = to_tf32(g_qkv[(size_t)(m0 + t) * NQKV + 1024 + h * 64 + d]);
    }
    if (tid < 64) {
        Wi[tid] = g_gates[(size_t)(m0 + tid) * NGATE + h];
        LF[tid] = g_gates[(size_t)(m0 + tid) * NGATE + 16 + h];
    }
    cp_wait<0>();
    __syncthreads();

    for (int idx = tid; idx < 1024; idx += 256) {
        int t = idx >> 4, dq = (idx & 15) << 2;
        float4 qv = *(float4*)(Q + t * RST + dq);
        qv.x = to_tf32(qv.x); qv.y = to_tf32(qv.y); qv.z = to_tf32(qv.z); qv.w = to_tf32(qv.w);
        *(float4*)(Q + t * RST + dq) = qv;
        float4 vv = *(float4*)(V + t * RST + dq);
        vv.x = to_tf32(vv.x); vv.y = to_tf32(vv.y); vv.z = to_tf32(vv.z); vv.w = to_tf32(vv.w);
        *(float4*)(V + t * RST + dq) = vv;
    }
    if (tid < 64) LF[tid] = __logf(LF[tid]);
    __syncthreads();
    if (tid == 0) {
        float r = 0.f;
        for (int t = 0; t < 64; ++t) { r += LF[t]; LF[t] = r; }
    }
    __syncthreads();
    if (tid < 64) Wc[tid] = __expf(LF[63] - LF[tid]) * Wi[tid];
    if (tid == 0) g_Fc[cidx] = __expf(LF[63]);
    __syncthreads();

    for (int idx = tid; idx < 1024; idx += 256) {
        int t = idx >> 4, dq = (idx & 15) << 2;
        float4 qv = *(const float4*)(Q + t * RST + dq);
        const float sc = __expf(LF[t]);
        qv.x *= sc; qv.y *= sc; qv.z *= sc; qv.w *= sc;
        *(float4*)(g_qs + (size_t)(m0 + t) * DIM + h * 64 + dq) = qv;
    }

    const int lane = tid & 31, wid = tid >> 5;
    const int gr = lane >> 2, tg = lane & 3;
    const int wm = (wid >> 1) * 16, wn = (wid & 1) * 32;

    float acc1[4][4];
    #pragma unroll
    for (int j = 0; j < 4; ++j)
        #pragma unroll
        for (int q = 0; q < 4; ++q) acc1[j][q] = 0.f;
    #pragma unroll
    for (int ks = 0; ks < 8; ++ks) {
        const int kc0 = ks * 8 + tg, kc1 = kc0 + 4;
        uint32_t a0 = FU(Q[(wm + gr) * RST + kc0]);
        uint32_t a1 = FU(Q[(wm + 8 + gr) * RST + kc0]);
        uint32_t a2 = FU(Q[(wm + gr) * RST + kc1]);
        uint32_t a3 = FU(Q[(wm + 8 + gr) * RST + kc1]);
        #pragma unroll
        for (int j = 0; j < 4; ++j) {
            const int n = wn + j * 8 + gr;
            mma_tf32(acc1[j], a0, a1, a2, a3,
                     FU(Kt[kc0 * RST + n]), FU(Kt[kc1 * RST + n]));
        }
    }
    #pragma unroll
    for (int j = 0; j < 4; ++j)
        #pragma unroll
        for (int q = 0; q < 4; ++q) {
            const int t = wm + gr + (q >> 1) * 8;
            const int s = wn + j * 8 + tg * 2 + (q & 1);
            float v = 0.f;
            if (s <= t) v = acc1[j][q] * __expf(LF[t] - LF[s]) * Wi[s];
            A[t * RST + s] = to_tf32(v);
        }
    __syncthreads();

    for (int idx = tid; idx < 1024; idx += 256) {
        int s = idx >> 4, e4 = (idx & 15) << 2;
        float4 vv = *(const float4*)(V + s * RST + e4);
        const float w = Wc[s];
        vv.x = to_tf32(w * vv.x); vv.y = to_tf32(w * vv.y);
        vv.z = to_tf32(w * vv.z); vv.w = to_tf32(w * vv.w);
        *(float4*)(Q + s * RST + e4) = vv;
    }
    __syncthreads();

    float hacc[4][4], uacc[4][4];
    #pragma unroll
    for (int j = 0; j < 4; ++j)
        #pragma unroll
        for (int q = 0; q < 4; ++q) { hacc[j][q] = 0.f; uacc[j][q] = 0.f; }
    #pragma unroll
    for (int ks = 0; ks < 8; ++ks) {
        const int kc0 = ks * 8 + tg, kc1 = kc0 + 4;
        uint32_t ha0 = FU(A[(wm + gr) * RST + kc0]);
        uint32_t ha1 = FU(A[(wm + 8 + gr) * RST + kc0]);
        uint32_t ha2 = FU(A[(wm + gr) * RST + kc1]);
        uint32_t ha3 = FU(A[(wm + 8 + gr) * RST + kc1]);
        uint32_t ka0 = FU(Kt[(wm + gr) * RST + kc0]);
        uint32_t ka1 = FU(Kt[(wm + 8 + gr) * RST + kc0]);
        uint32_t ka2 = FU(Kt[(wm + gr) * RST + kc1]);
        uint32_t ka3 = FU(Kt[(wm + 8 + gr) * RST + kc1]);
        #pragma unroll
        for (int j = 0; j < 4; ++j) {
            const int n = wn + j * 8 + gr;
            mma_tf32(hacc[j], ha0, ha1, ha2, ha3,
                     FU(V[kc0 * RST + n]), FU(V[kc1 * RST + n]));
            mma_tf32(uacc[j], ka0, ka1, ka2, ka3,
                     FU(Q[kc0 * RST + n]), FU(Q[kc1 * RST + n]));
        }
    }
    #pragma unroll
    for (int j = 0; j < 4; ++j)
        #pragma unroll
        for (int q = 0; q < 4; ++q) {
            const int row = wm + gr + (q >> 1) * 8;
            const int col = wn + j * 8 + tg * 2 + (q & 1);
            g_h[(size_t)(m0 + row) * DIM + h * 64 + col] = hacc[j][q];
            g_U[(size_t)cidx * 4096 + row * 64 + col] = uacc[j][q];
        }
}

// ---- phase 2a: element-parallel state prefix ----
__global__ void __launch_bounds__(256) state_prefix_kernel(const float* __restrict__ hidden) {
    const int gid = blockIdx.x * 256 + threadIdx.x;
    const int bh = gid >> 10;
    const int off = (gid & 1023) * 4;
    float4 S = *(const float4*)(hidden + (size_t)bh * 4096 + off);
    const float* fc = g_Fc + bh * NCHUNK;
    #pragma unroll 4
    for (int c = 0; c < NCHUNK; ++c) {
        const size_t p = (size_t)(bh * NCHUNK + c) * 4096 + off;
        *(float4*)(g_S + p) = S;
        const float4 U = *(const float4*)(g_U + p);
        const float F = fc[c];
        S.x = F * S.x + U.x;
        S.y = F * S.y + U.y;
        S.z = F * S.z + U.z;
        S.w = F * S.w + U.w;
    }
}

// ---- phase 2b: h = (Qs @ S_c + h_intra) * o -> fp16 A-fragments ----
__global__ void __launch_bounds__(256) chunk_inter_kernel() {
    extern __shared__ float sm3[];
    float* Qs = sm3;
    float* Sb = Qs + 64 * RST;
    float* Og = Sb + 64 * RST;

    const int cidx = blockIdx.x;
    const int c = cidx & (NCHUNK - 1);
    const int bh = cidx >> 5;
    const int h = bh & 15, b = bh >> 4;
    const int m0 = b * SEQ + c * CHUNK;
    const int tid = threadIdx.x;

    for (int idx = tid; idx < 1024; idx += 256) {
        int t = idx >> 4, d4 = (idx & 15) << 2;
        cp16(smem_u32(Qs + t * RST + d4), g_qs + (size_t)(m0 + t) * DIM + h * 64 + d4);
        cp16(smem_u32(Sb + t * RST + d4), g_S + (size_t)cidx * 4096 + t * 64 + d4);
    }
    if (tid < 64)
        cp4(smem_u32(Og + tid), g_gates + (size_t)(m0 + tid) * NGATE + 32 + h);
    cp_commit();
    cp_wait<0>();
    __syncthreads();

    for (int idx = tid; idx < 2048; idx += 256) {
        float* p = (idx < 1024) ? Qs : Sb;
        int r = (idx & 1023) >> 4, d4 = (idx & 15) << 2;
        float4 v = *(float4*)(p + r * RST + d4);
        v.x = to_tf32(v.x); v.y = to_tf32(v.y); v.z = to_tf32(v.z); v.w = to_tf32(v.w);
        *(float4*)(p + r * RST + d4) = v;
    }
    __syncthreads();

    const int lane = tid & 31, wid = tid >> 5;
    const int gr = lane >> 2, tg = lane & 3;
    const int wm = (wid >> 1) * 16, wn = (wid & 1) * 32;

    float acc[4][4];
    #pragma unroll
    for (int j = 0; j < 4; ++j)
        #pragma unroll
        for (int q = 0; q < 4; ++q) acc[j][q] = 0.f;
    #pragma unroll
    for (int ks = 0; ks < 8; ++ks) {
        const int kc0 = ks * 8 + tg, kc1 = kc0 + 4;
        uint32_t a0 = FU(Qs[(wm + gr) * RST + kc0]);
        uint32_t a1 = FU(Qs[(wm + 8 + gr) * RST + kc0]);
        uint32_t a2 = FU(Qs[(wm + gr) * RST + kc1]);
        uint32_t a3 = FU(Qs[(wm + 8 + gr) * RST + kc1]);
        #pragma unroll
        for (int j = 0; j < 4; ++j) {
            const int n = wn + j * 8 + gr;
            mma_tf32(acc[j], a0, a1, a2, a3,
                     FU(Sb[kc0 * RST + n]), FU(Sb[kc1 * RST + n]));
        }
    }

    #pragma unroll
    for (int j = 0; j < 4; ++j)
        #pragma unroll
        for (int qp = 0; qp < 2; ++qp) {
            const int row = wm + gr + qp * 8;
            const int col = wn + j * 8 + tg * 2;
            const int m = m0 + row;
            const float og = Og[row];
            const float hv0 = (acc[j][qp*2]   + g_h[(size_t)m * DIM + h * 64 + col])     * og;
            const float hv1 = (acc[j][qp*2+1] + g_h[(size_t)m * DIM + h * 64 + col + 1]) * og;
            g_hfh[afrag_off(m, h * 64 + col)] = __floats2half2_rn(hv0, hv1);
        }
}

extern "C" void kernel_launch(void* const* d_in, const int* in_sizes, int n_in,
                              void* d_out, int out_size) {
    const float* x      = (const float*)d_in[0];
    const float* hidden = (const float*)d_in[1];
    const float* w_rms  = (const float*)d_in[2];
    const float* w_qkv  = (const float*)d_in[3];
    const float* w_gate = (const float*)d_in[4];
    const float* w_out  = (const float*)d_in[5];
    float* out = (float*)d_out;

    static bool attr_done = false;
    if (!attr_done) {
        cudaFuncSetAttribute(gemm_f16_kernel<0>,
            cudaFuncAttributeMaxDynamicSharedMemorySize, 49152);
        cudaFuncSetAttribute(gemm_f16_kernel<1>,
            cudaFuncAttributeMaxDynamicSharedMemorySize, 49152);
        cudaFuncSetAttribute(chunk_intra_kernel,
            cudaFuncAttributeMaxDynamicSharedMemorySize, 71000);
        cudaFuncSetAttribute(chunk_inter_kernel,
            cudaFuncAttributeMaxDynamicSharedMemorySize, 36000);
        attr_done = true;
    }

    const int PAIRS = N1 * DIM / 2 + DIM * DIM / 2;
    prep_weights_kernel<<<(PAIRS + 255) / 256, 256>>>(w_qkv, w_gate, w_out);
    rmsnorm_kernel<<<MTOK, 256>>>(x, w_rms);
    {
        dim3 grid(N1 / 128, MTOK / 128);
        gemm_f16_kernel<0><<<grid, 256, 49152>>>(nullptr, nullptr);
    }
    chunk_intra_kernel<<<TOTCHUNK, 256, 71000>>>();
    state_prefix_kernel<<<256, 256>>>(hidden);
    chunk_inter_kernel<<<TOTCHUNK, 256, 36000>>>();
    {
        dim3 grid(DIM / 128, MTOK / 128);
        gemm_f16_kernel<1><<<grid, 256, 49152>>>(x, out);
    }
}

// round 8
// speedup vs baseline: 4.1455x; 1.1557x over previous
#include <cuda_runtime.h>
#include <cuda_fp16.h>
#include <cstdint>
#include <cmath>

#define BATCH 4
#define SEQ   2048
#define DIM   1024
#define NH    16
#define DH    64
#define MTOK  (BATCH*SEQ)
#define N1    3200
#define NQKV  3072
#define NGATE 48
#define CHUNK 64
#define NCHUNK (SEQ/CHUNK)              // 32
#define TOTCHUNK (BATCH*NH*NCHUNK)      // 2048

// fp16 fragment-packed GEMM operands
__device__ __half2 g_xnh [MTOK * DIM / 2];    // A-fragments of rmsnormed x
__device__ __half2 g_w1h [N1 * DIM / 2];      // B-fragments of [wqkv|wgate|0]
__device__ __half2 g_w2h [DIM * DIM / 2];     // B-fragments of w_out
__device__ __half2 g_hfh [MTOK * DIM / 2];    // A-fragments of final h
// plain buffers
__device__ float g_qkv [MTOK * NQKV];
__device__ float g_gates[MTOK * NGATE];
__device__ float g_h   [MTOK * DIM];          // h_intra
__device__ float g_el  [MTOK * NH];           // exp(LF_t) per (m, h)
__device__ float g_U   [TOTCHUNK * 64 * 64];
__device__ float g_S   [TOTCHUNK * 64 * 64];
__device__ float g_Fc  [TOTCHUNK];

__device__ __forceinline__ float to_tf32(float x) {
    uint32_t u; asm("cvt.rna.tf32.f32 %0, %1;\n" : "=r"(u) : "f"(x));
    return __uint_as_float(u);
}
__device__ __forceinline__ uint32_t smem_u32(const void* p) {
    return (uint32_t)__cvta_generic_to_shared(p);
}
__device__ __forceinline__ void cp16(uint32_t s, const void* g) {
    asm volatile("cp.async.cg.shared.global [%0], [%1], 16;\n" :: "r"(s), "l"(g));
}
__device__ __forceinline__ void cp4(uint32_t s, const void* g) {
    asm volatile("cp.async.ca.shared.global [%0], [%1], 4;\n" :: "r"(s), "l"(g));
}
__device__ __forceinline__ void cp_commit() {
    asm volatile("cp.async.commit_group;\n" ::: "memory");
}
template<int N> __device__ __forceinline__ void cp_wait() {
    asm volatile("cp.async.wait_group %0;\n" :: "n"(N) : "memory");
}
__device__ __forceinline__ void mma_tf32(float c[4],
        uint32_t a0, uint32_t a1, uint32_t a2, uint32_t a3,
        uint32_t b0, uint32_t b1) {
    asm volatile(
        "mma.sync.aligned.m16n8k8.row.col.f32.tf32.tf32.f32 "
        "{%0,%1,%2,%3},{%4,%5,%6,%7},{%8,%9},{%0,%1,%2,%3};\n"
        : "+f"(c[0]), "+f"(c[1]), "+f"(c[2]), "+f"(c[3])
        : "r"(a0), "r"(a1), "r"(a2), "r"(a3), "r"(b0), "r"(b1));
}
__device__ __forceinline__ void mma_f16(float c[4],
        uint32_t a0, uint32_t a1, uint32_t a2, uint32_t a3,
        uint32_t b0, uint32_t b1) {
    asm volatile(
        "mma.sync.aligned.m16n8k16.row.col.f32.f16.f16.f32 "
        "{%0,%1,%2,%3},{%4,%5,%6,%7},{%8,%9},{%0,%1,%2,%3};\n"
        : "+f"(c[0]), "+f"(c[1]), "+f"(c[2]), "+f"(c[3])
        : "r"(a0), "r"(a1), "r"(a2), "r"(a3), "r"(b0), "r"(b1));
}
#define FU(x) __float_as_uint(x)
__device__ __forceinline__ uint32_t H2U(__half2 v) {
    return *(uint32_t*)&v;
}

// A-fragment half2 offset for (m, k even)
__device__ __forceinline__ size_t afrag_off(int m, int k) {
    const int mb = m >> 7, kt = k >> 5, R = (m >> 4) & 7, ks = (k >> 4) & 1;
    const int gr = m & 7, hb = (m >> 3) & 1, tg = (k & 7) >> 1, kh = (k >> 3) & 1;
    return ((((size_t)(mb * 32 + kt) * 8 + R) * 2 + ks) * 128)
         + (gr * 4 + tg) * 4 + (hb + 2 * kh);
}

// ---- prep: pack weights into fp16 B-fragment layout ----
__global__ void __launch_bounds__(256) prep_weights_kernel(
        const float* __restrict__ wqkv, const float* __restrict__ wgate,
        const float* __restrict__ wout) {
    const int P1 = N1 * DIM / 2;
    const int P2 = DIM * DIM / 2;
    const int idx = blockIdx.x * 256 + threadIdx.x;
    if (idx < P1) {
        const int kh = idx & 1, lane = (idx >> 1) & 31, ks = (idx >> 6) & 1;
        const int nbkt = idx >> 7, nb = nbkt % 400, kt = nbkt / 400;
        const int gr = lane >> 2, tg = lane & 3;
        const int n = nb * 8 + gr;
        const int k = kt * 32 + ks * 16 + kh * 8 + tg * 2;
        float v0 = 0.f, v1 = 0.f;
        if (n < NQKV)              { v0 = wqkv[k * NQKV + n];        v1 = wqkv[(k+1) * NQKV + n]; }
        else if (n < NQKV + NGATE) { v0 = wgate[k * NGATE + n-NQKV]; v1 = wgate[(k+1) * NGATE + n-NQKV]; }
        g_w1h[idx] = __floats2half2_rn(v0, v1);
    } else if (idx < P1 + P2) {
        const int j = idx - P1;
        const int kh = j & 1, lane = (j >> 1) & 31, ks = (j >> 6) & 1;
        const int nbkt = j >> 7, nb = nbkt % 128, kt = nbkt / 128;
        const int gr = lane >> 2, tg = lane & 3;
        const int n = nb * 8 + gr;
        const int k = kt * 32 + ks * 16 + kh * 8 + tg * 2;
        g_w2h[j] = __floats2half2_rn(wout[k * DIM + n], wout[(k+1) * DIM + n]);
    }
}

// ---- rmsnorm -> fp16 A-fragment layout ----
__global__ void __launch_bounds__(256) rmsnorm_kernel(
        const float* __restrict__ x, const float* __restrict__ w) {
    const int row = blockIdx.x;
    const int tid = threadIdx.x;
    const float4 xv = ((const float4*)(x + (size_t)row * DIM))[tid];
    float ss = xv.x*xv.x + xv.y*xv.y + xv.z*xv.z + xv.w*xv.w;
    #pragma unroll
    for (int off = 16; off > 0; off >>= 1)
        ss += __shfl_xor_sync(0xffffffffu, ss, off);
    __shared__ float wsum[8];
    const int lane = tid & 31, wid = tid >> 5;
    if (lane == 0) wsum[wid] = ss;
    __syncthreads();
    if (tid == 0) {
        float t = 0.f;
        #pragma unroll
        for (int i = 0; i < 8; ++i) t += wsum[i];
        wsum[0] = rsqrtf(t * (1.0f / DIM) + 1e-6f);
    }
    __syncthreads();
    const float scale = wsum[0];
    const float4 wv = ((const float4*)w)[tid];
    const int k0 = tid * 4;
    g_xnh[afrag_off(row, k0)]     = __floats2half2_rn(wv.x * (xv.x * scale), wv.y * (xv.y * scale));
    g_xnh[afrag_off(row, k0 + 2)] = __floats2half2_rn(wv.z * (xv.z * scale), wv.w * (xv.w * scale));
}

// ---- fp16 fragment-packed GEMM (128x128x32 tiles, m16n8k16, 8 warps) ----
template<int MODE>
__global__ void __launch_bounds__(256) gemm_f16_kernel(
        const float* __restrict__ X, float* __restrict__ Out) {
    constexpr int KT = DIM / 32;
    constexpr int N = (MODE == 0) ? N1 : DIM;
    const __half2* __restrict__ Af = (MODE == 0) ? g_xnh : g_hfh;
    const __half2* __restrict__ Bf = (MODE == 0) ? g_w1h : g_w2h;

    extern __shared__ float smem[];
    const int tid = threadIdx.x;
    const int mb = blockIdx.y, n0 = blockIdx.x * 128;
    const int m0 = mb * 128;
    const uint32_t smem_base = smem_u32(smem);

    auto issue = [&](int kt) {
        if (kt < KT) {
            const uint32_t st = smem_base + (uint32_t)(kt % 3) * 16384u;
            const __half2* sA = Af + (size_t)(mb * 32 + kt) * 2048;
            const __half2* sB = Bf + ((size_t)kt * (N >> 3) + (n0 >> 3)) * 128;
            cp16(st + (uint32_t)tid * 16u,           sA + tid * 4);
            cp16(st + (uint32_t)(tid + 256) * 16u,   sA + (tid + 256) * 4);
            cp16(st + 8192u + (uint32_t)tid * 16u,         sB + tid * 4);
            cp16(st + 8192u + (uint32_t)(tid + 256) * 16u, sB + (tid + 256) * 4);
        }
        cp_commit();
    };

    float acc[4][4][4];
    #pragma unroll
    for (int i = 0; i < 4; ++i)
        #pragma unroll
        for (int j = 0; j < 4; ++j)
            #pragma unroll
            for (int q = 0; q < 4; ++q) acc[i][j][q] = 0.f;

    issue(0); issue(1);

    const int lane = tid & 31, wid = tid >> 5;
    const int R0 = (wid >> 2) * 4;
    const int nb0 = (wid & 3) * 4;
    const int wm = R0 * 16, wn = nb0 * 8;
    const int gr = lane >> 2, tg = lane & 3;

    for (int kt = 0; kt < KT; ++kt) {
        cp_wait<1>();
        __syncthreads();
        issue(kt + 2);
        const __half2* As = (const __half2*)((const char*)smem + (kt % 3) * 16384);
        const __half2* Bs = As + 2048;
        #pragma unroll
        for (int ks = 0; ks < 2; ++ks) {
            float4 af[4]; float2 bf[4];
            #pragma unroll
            for (int i = 0; i < 4; ++i)
                af[i] = *(const float4*)(As + ((R0 + i) * 2 + ks) * 128 + lane * 4);
            #pragma unroll
            for (int j = 0; j < 4; ++j)
                bf[j] = *(const float2*)(Bs + ((nb0 + j) * 2 + ks) * 64 + lane * 2);
            #pragma unroll
            for (int i = 0; i < 4; ++i)
                #pragma unroll
                for (int j = 0; j < 4; ++j)
                    mma_f16(acc[i][j], FU(af[i].x), FU(af[i].y), FU(af[i].z), FU(af[i].w),
                            FU(bf[j].x), FU(bf[j].y));
        }
    }

    #pragma unroll
    for (int i = 0; i < 4; ++i) {
        #pragma unroll
        for (int j = 0; j < 4; ++j) {
            const int r0 = m0 + wm + i * 16 + gr;
            const int c0 = n0 + wn + j * 8 + tg * 2;
            #pragma unroll
            for (int q = 0; q < 4; ++q) {
                const int r = r0 + (q >> 1) * 8;
                const int c = c0 + (q & 1);
                const float v = acc[i][j][q];
                if (MODE == 0) {
                    if (c < NQKV) {
                        g_qkv[(size_t)r * NQKV + c] = v;
                    } else if (c < NQKV + NGATE) {
                        float t = tanhf(v * (1.0f / 15.0f));
                        g_gates[r * NGATE + (c - NQKV)] = 1.0f / (1.0f + expf(-15.0f * t));
                    }
                } else {
                    Out[(size_t)r * DIM + c] = X[(size_t)r * DIM + c] + v;
                }
            }
        }
    }
}

// ---- chunkwise phase 1: intra-chunk, fp16 m16n8k16 ----
#define SP 72     // half pitch
#define SP2 36    // half2 pitch
__global__ void __launch_bounds__(256) chunk_intra_kernel() {
    __shared__ __half Qh [64 * SP];   // (t,d); after GEMM1 reused as Ah (t,s)
    __shared__ __half Kh [64 * SP];   // (s,d)
    __shared__ __half Kth[64 * SP];   // (d,s) * Wc[s], col-swizzled
    __shared__ __half Vth[64 * SP];   // (e,s), col-swizzled
    __shared__ float LF[64], Wi[64], Wc[64];

    const int cidx = blockIdx.x;
    const int c = cidx & (NCHUNK - 1);
    const int bh = cidx >> 5;
    const int h = bh & 15, b = bh >> 4;
    const int m0 = b * SEQ + c * CHUNK;
    const int tid = threadIdx.x;

    // gate loads (issued first)
    float gi = 0.f, gf = 0.f;
    if (tid < 64) {
        gi = g_gates[(size_t)(m0 + tid) * NGATE + h];
        gf = g_gates[(size_t)(m0 + tid) * NGATE + 16 + h];
    }
    // qkv staging loads (4 chunks/thread/tensor)
    float4 q4[4], k4[4], v4[4];
    #pragma unroll
    for (int qq = 0; qq < 4; ++qq) {
        const int idx = tid + qq * 256;
        const int t = idx >> 4, d4 = (idx & 15) << 2;
        const float* row = g_qkv + (size_t)(m0 + t) * NQKV + h * 64 + d4;
        q4[qq] = *(const float4*)row;
        k4[qq] = *(const float4*)(row + 1024);
        v4[qq] = *(const float4*)(row + 2048);
    }
    if (tid < 64) { Wi[tid] = gi; LF[tid] = __logf(gf); }
    __syncthreads();

    // warp-parallel inclusive scan of LF over 64 elements (warp 0)
    if (tid < 32) {
        float x0 = LF[tid], x1 = LF[tid + 32];
        #pragma unroll
        for (int off = 1; off < 32; off <<= 1) {
            float y = __shfl_up_sync(0xffffffffu, x0, off);
            if (tid >= off) x0 += y;
        }
        const float tot = __shfl_sync(0xffffffffu, x0, 31);
        #pragma unroll
        for (int off = 1; off < 32; off <<= 1) {
            float y = __shfl_up_sync(0xffffffffu, x1, off);
            if (tid >= off) x1 += y;
        }
        x1 += tot;
        LF[tid] = x0; LF[tid + 32] = x1;
        g_el[(size_t)(m0 + tid) * NH + h]      = __expf(x0);
        g_el[(size_t)(m0 + tid + 32) * NH + h] = __expf(x1);
    }
    __syncthreads();
    if (tid < 64) Wc[tid] = __expf(LF[63] - LF[tid]) * Wi[tid];
    if (tid == 0) g_Fc[cidx] = __expf(LF[63]);
    __syncthreads();

    // convert: Qh/Kh natural, Kth (Wc-scaled) & Vth transposed+swizzled
    #pragma unroll
    for (int qq = 0; qq < 4; ++qq) {
        const int idx = tid + qq * 256;
        const int t = idx >> 4, d4 = (idx & 15) << 2;
        __half2* qrow = (__half2*)Qh + t * SP2 + (d4 >> 1);
        qrow[0] = __floats2half2_rn(q4[qq].x, q4[qq].y);
        qrow[1] = __floats2half2_rn(q4[qq].z, q4[qq].w);
        __half2* krow = (__half2*)Kh + t * SP2 + (d4 >> 1);
        krow[0] = __floats2half2_rn(k4[qq].x, k4[qq].y);
        krow[1] = __floats2half2_rn(k4[qq].z, k4[qq].w);
        const float wcs = Wc[t];
        const float kk[4] = {k4[qq].x, k4[qq].y, k4[qq].z, k4[qq].w};
        const float vv[4] = {v4[qq].x, v4[qq].y, v4[qq].z, v4[qq].w};
        #pragma unroll
        for (int jj = 0; jj < 4; ++jj) {
            const int d = d4 + jj;
            const int sw = t ^ (((d >> 2) & 15) << 1);
            Kth[d * SP + sw] = __float2half(wcs * kk[jj]);
            Vth[d * SP + sw] = __float2half(vv[jj]);
        }
    }
    __syncthreads();

    const int lane = tid & 31, wid = tid >> 5;
    const int gr = lane >> 2, tg = lane & 3;
    const int wm = (wid >> 1) * 16, wn = (wid & 1) * 32;
    const int ra = wm + gr, rb = wm + 8 + gr;

    // GEMM1: raw[t][s] = sum_d Q[t][d] K[s][d]
    float acc1[4][4];
    #pragma unroll
    for (int j = 0; j < 4; ++j)
        #pragma unroll
        for (int q = 0; q < 4; ++q) acc1[j][q] = 0.f;
    {
        const __half2* Q2 = (const __half2*)Qh;
        const __half2* K2 = (const __half2*)Kh;
        #pragma unroll
        for (int ks = 0; ks < 4; ++ks) {
            const int kh2 = ks * 8 + tg;
            uint32_t a0 = H2U(Q2[ra * SP2 + kh2]);
            uint32_t a1 = H2U(Q2[rb * SP2 + kh2]);
            uint32_t a2 = H2U(Q2[ra * SP2 + kh2 + 4]);
            uint32_t a3 = H2U(Q2[rb * SP2 + kh2 + 4]);
            #pragma unroll
            for (int j = 0; j < 4; ++j) {
                const int n = wn + j * 8 + gr;
                mma_f16(acc1[j], a0, a1, a2, a3,
                        H2U(K2[n * SP2 + kh2]), H2U(K2[n * SP2 + kh2 + 4]));
            }
        }
    }
    __syncthreads();   // all GEMM1 smem reads done before Ah overwrites Qh

    // A[t][s] = mask * exp(LF[t]-LF[s]) * Wi[s] * raw
    {
        __half* Ah = Qh;
        #pragma unroll
        for (int j = 0; j < 4; ++j)
            #pragma unroll
            for (int q = 0; q < 4; ++q) {
                const int t = wm + gr + (q >> 1) * 8;
                const int s = wn + j * 8 + tg * 2 + (q & 1);
                float v = 0.f;
                if (s <= t) v = acc1[j][q] * __expf(LF[t] - LF[s]) * Wi[s];
                Ah[t * SP + s] = __float2half(v);
            }
    }
    __syncthreads();

    // GEMM2: h[t][e] = sum_s A[t][s] V[s][e]
    // GEMM3: U[d][e] = sum_s (Wc[s] K[s][d]) V[s][e]
    float hacc[4][4], uacc[4][4];
    #pragma unroll
    for (int j = 0; j < 4; ++j)
        #pragma unroll
        for (int q = 0; q < 4; ++q) { hacc[j][q] = 0.f; uacc[j][q] = 0.f; }
    {
        const __half2* A2  = (const __half2*)Qh;
        const __half2* Kt2 = (const __half2*)Kth;
        const __half2* Vt2 = (const __half2*)Vth;
        const int swa = (ra >> 2) & 15, swb = (rb >> 2) & 15;
        #pragma unroll
        for (int ks = 0; ks < 4; ++ks) {
            const int kh2 = ks * 8 + tg;
            uint32_t ha0 = H2U(A2[ra * SP2 + kh2]);
            uint32_t ha1 = H2U(A2[rb * SP2 + kh2]);
            uint32_t ha2 = H2U(A2[ra * SP2 + kh2 + 4]);
            uint32_t ha3 = H2U(A2[rb * SP2 + kh2 + 4]);
            uint32_t ua0 = H2U(Kt2[ra * SP2 + (kh2 ^ swa)]);
            uint32_t ua1 = H2U(Kt2[rb * SP2 + (kh2 ^ swb)]);
            uint32_t ua2 = H2U(Kt2[ra * SP2 + ((kh2 + 4) ^ swa)]);
            uint32_t ua3 = H2U(Kt2[rb * SP2 + ((kh2 + 4) ^ swb)]);
            #pragma unroll
            for (int j = 0; j < 4; ++j) {
                const int n = wn + j * 8 + gr;
                const int swn = (n >> 2) & 15;
                uint32_t b0 = H2U(Vt2[n * SP2 + (kh2 ^ swn)]);
                uint32_t b1 = H2U(Vt2[n * SP2 + ((kh2 + 4) ^ swn)]);
                mma_f16(hacc[j], ha0, ha1, ha2, ha3, b0, b1);
                mma_f16(uacc[j], ua0, ua1, ua2, ua3, b0, b1);
            }
        }
    }
    #pragma unroll
    for (int j = 0; j < 4; ++j)
        #pragma unroll
        for (int q = 0; q < 4; ++q) {
            const int row = wm + gr + (q >> 1) * 8;
            const int col = wn + j * 8 + tg * 2 + (q & 1);
            g_h[(size_t)(m0 + row) * DIM + h * 64 + col] = hacc[j][q];
            g_U[(size_t)cidx * 4096 + row * 64 + col] = uacc[j][q];
        }
}

// ---- phase 2a: element-parallel state prefix ----
__global__ void __launch_bounds__(256) state_prefix_kernel(const float* __restrict__ hidden) {
    const int gid = blockIdx.x * 256 + threadIdx.x;
    const int bh = gid >> 10;
    const int off = (gid & 1023) * 4;
    float4 S = *(const float4*)(hidden + (size_t)bh * 4096 + off);
    const float* fc = g_Fc + bh * NCHUNK;
    #pragma unroll 4
    for (int c = 0; c < NCHUNK; ++c) {
        const size_t p = (size_t)(bh * NCHUNK + c) * 4096 + off;
        *(float4*)(g_S + p) = S;
        const float4 U = *(const float4*)(g_U + p);
        const float F = fc[c];
        S.x = F * S.x + U.x;
        S.y = F * S.y + U.y;
        S.z = F * S.z + U.z;
        S.w = F * S.w + U.w;
    }
}

// ---- phase 2b: h = (exp(LF)*q @ S_c + h_intra) * o -> fp16 A-fragments ----
#define RST 68
__global__ void __launch_bounds__(256) chunk_inter_kernel() {
    extern __shared__ float sm3[];
    float* Qs = sm3;                 // [64][RST]
    float* Sb = Qs + 64 * RST;
    float* Og = Sb + 64 * RST;       // [64]
    float* Eb = Og + 64;             // [64]

    const int cidx = blockIdx.x;
    const int c = cidx & (NCHUNK - 1);
    const int bh = cidx >> 5;
    const int h = bh & 15, b = bh >> 4;
    const int m0 = b * SEQ + c * CHUNK;
    const int tid = threadIdx.x;

    for (int idx = tid; idx < 1024; idx += 256) {
        int t = idx >> 4, d4 = (idx & 15) << 2;
        cp16(smem_u32(Qs + t * RST + d4), g_qkv + (size_t)(m0 + t) * NQKV + h * 64 + d4);
        cp16(smem_u32(Sb + t * RST + d4), g_S + (size_t)cidx * 4096 + t * 64 + d4);
    }
    if (tid < 64) {
        cp4(smem_u32(Og + tid), g_gates + (size_t)(m0 + tid) * NGATE + 32 + h);
        cp4(smem_u32(Eb + tid), g_el + (size_t)(m0 + tid) * NH + h);
    }
    cp_commit();
    cp_wait<0>();
    __syncthreads();

    for (int idx = tid; idx < 2048; idx += 256) {
        const bool isQ = idx < 1024;
        float* p = isQ ? Qs : Sb;
        int r = (idx & 1023) >> 4, d4 = (idx & 15) << 2;
        float4 v = *(float4*)(p + r * RST + d4);
        if (isQ) {
            const float e = Eb[r];
            v.x *= e; v.y *= e; v.z *= e; v.w *= e;
        }
        v.x = to_tf32(v.x); v.y = to_tf32(v.y); v.z = to_tf32(v.z); v.w = to_tf32(v.w);
        *(float4*)(p + r * RST + d4) = v;
    }
    __syncthreads();

    const int lane = tid & 31, wid = tid >> 5;
    const int gr = lane >> 2, tg = lane & 3;
    const int wm = (wid >> 1) * 16, wn = (wid & 1) * 32;

    float acc[4][4];
    #pragma unroll
    for (int j = 0; j < 4; ++j)
        #pragma unroll
        for (int q = 0; q < 4; ++q) acc[j][q] = 0.f;
    #pragma unroll
    for (int ks = 0; ks < 8; ++ks) {
        const int kc0 = ks * 8 + tg, kc1 = kc0 + 4;
        uint32_t a0 = FU(Qs[(wm + gr) * RST + kc0]);
        uint32_t a1 = FU(Qs[(wm + 8 + gr) * RST + kc0]);
        uint32_t a2 = FU(Qs[(wm + gr) * RST + kc1]);
        uint32_t a3 = FU(Qs[(wm + 8 + gr) * RST + kc1]);
        #pragma unroll
        for (int j = 0; j < 4; ++j) {
            const int n = wn + j * 8 + gr;
            mma_tf32(acc[j], a0, a1, a2, a3,
                     FU(Sb[kc0 * RST + n]), FU(Sb[kc1 * RST + n]));
        }
    }

    #pragma unroll
    for (int j = 0; j < 4; ++j)
        #pragma unroll
        for (int qp = 0; qp < 2; ++qp) {
            const int row = wm + gr + qp * 8;
            const int col = wn + j * 8 + tg * 2;
            const int m = m0 + row;
            const float og = Og[row];
            const float hv0 = (acc[j][qp*2]   + g_h[(size_t)m * DIM + h * 64 + col])     * og;
            const float hv1 = (acc[j][qp*2+1] + g_h[(size_t)m * DIM + h * 64 + col + 1]) * og;
            g_hfh[afrag_off(m, h * 64 + col)] = __floats2half2_rn(hv0, hv1);
        }
}

extern "C" void kernel_launch(void* const* d_in, const int* in_sizes, int n_in,
                              void* d_out, int out_size) {
    const float* x      = (const float*)d_in[0];
    const float* hidden = (const float*)d_in[1];
    const float* w_rms  = (const float*)d_in[2];
    const float* w_qkv  = (const float*)d_in[3];
    const float* w_gate = (const float*)d_in[4];
    const float* w_out  = (const float*)d_in[5];
    float* out = (float*)d_out;

    static bool attr_done = false;
    if (!attr_done) {
        cudaFuncSetAttribute(gemm_f16_kernel<0>,
            cudaFuncAttributeMaxDynamicSharedMemorySize, 49152);
        cudaFuncSetAttribute(gemm_f16_kernel<1>,
            cudaFuncAttributeMaxDynamicSharedMemorySize, 49152);
        cudaFuncSetAttribute(chunk_inter_kernel,
            cudaFuncAttributeMaxDynamicSharedMemorySize, 36000);
        attr_done = true;
    }

    const int PAIRS = N1 * DIM / 2 + DIM * DIM / 2;
    prep_weights_kernel<<<(PAIRS + 255) / 256, 256>>>(w_qkv, w_gate, w_out);
    rmsnorm_kernel<<<MTOK, 256>>>(x, w_rms);
    {
        dim3 grid(N1 / 128, MTOK / 128);
        gemm_f16_kernel<0><<<grid, 256, 49152>>>(nullptr, nullptr);
    }
    chunk_intra_kernel<<<TOTCHUNK, 256>>>();
    state_prefix_kernel<<<256, 256>>>(hidden);
    chunk_inter_kernel<<<TOTCHUNK, 256, 36000>>>();
    {
        dim3 grid(DIM / 128, MTOK / 128);
        gemm_f16_kernel<1><<<grid, 256, 49152>>>(x, out);
    }
}

// round 9
// speedup vs baseline: 4.5056x; 1.0869x over previous
#include <cuda_runtime.h>
#include <cuda_fp16.h>
#include <cstdint>
#include <cmath>

#define BATCH 4
#define SEQ   2048
#define DIM   1024
#define NH    16
#define DH    64
#define MTOK  (BATCH*SEQ)
#define N1    3200
#define NQKV  3072
#define NGATE 48
#define CHUNK 64
#define NCHUNK (SEQ/CHUNK)              // 32
#define TOTCHUNK (BATCH*NH*NCHUNK)      // 2048

// fp16 fragment-packed GEMM operands
__device__ __half2 g_xnh [MTOK * DIM / 2];    // A-fragments of rmsnormed x
__device__ __half2 g_w1h [N1 * DIM / 2];      // B-fragments of [wqkv|wgate|0]
__device__ __half2 g_w2h [DIM * DIM / 2];     // B-fragments of w_out
__device__ __half2 g_hfh [MTOK * DIM / 2];    // A-fragments of final h
// plain buffers
__device__ __half g_qkvh[MTOK * NQKV];        // qkv in fp16, [m][3072]
__device__ float g_gates[MTOK * NGATE];
__device__ float g_h   [MTOK * DIM];          // h_intra (fp32)
__device__ float g_el  [MTOK * NH];           // exp(LF_t) per (m, h)
__device__ float g_U   [TOTCHUNK * 64 * 64];
__device__ float g_S   [TOTCHUNK * 64 * 64];
__device__ float g_Fc  [TOTCHUNK];

__device__ __forceinline__ uint32_t smem_u32(const void* p) {
    return (uint32_t)__cvta_generic_to_shared(p);
}
__device__ __forceinline__ void cp16(uint32_t s, const void* g) {
    asm volatile("cp.async.cg.shared.global [%0], [%1], 16;\n" :: "r"(s), "l"(g));
}
__device__ __forceinline__ void cp_commit() {
    asm volatile("cp.async.commit_group;\n" ::: "memory");
}
template<int N> __device__ __forceinline__ void cp_wait() {
    asm volatile("cp.async.wait_group %0;\n" :: "n"(N) : "memory");
}
__device__ __forceinline__ void mma_f16(float c[4],
        uint32_t a0, uint32_t a1, uint32_t a2, uint32_t a3,
        uint32_t b0, uint32_t b1) {
    asm volatile(
        "mma.sync.aligned.m16n8k16.row.col.f32.f16.f16.f32 "
        "{%0,%1,%2,%3},{%4,%5,%6,%7},{%8,%9},{%0,%1,%2,%3};\n"
        : "+f"(c[0]), "+f"(c[1]), "+f"(c[2]), "+f"(c[3])
        : "r"(a0), "r"(a1), "r"(a2), "r"(a3), "r"(b0), "r"(b1));
}
#define FU(x) __float_as_uint(x)
__device__ __forceinline__ uint32_t H2U(__half2 v) { return *(uint32_t*)&v; }

// A-fragment half2 offset for (m, k even)
__device__ __forceinline__ size_t afrag_off(int m, int k) {
    const int mb = m >> 7, kt = k >> 5, R = (m >> 4) & 7, ks = (k >> 4) & 1;
    const int gr = m & 7, hb = (m >> 3) & 1, tg = (k & 7) >> 1, kh = (k >> 3) & 1;
    return ((((size_t)(mb * 32 + kt) * 8 + R) * 2 + ks) * 128)
         + (gr * 4 + tg) * 4 + (hb + 2 * kh);
}

// ---- prep: pack weights into fp16 B-fragment layout ----
__global__ void __launch_bounds__(256) prep_weights_kernel(
        const float* __restrict__ wqkv, const float* __restrict__ wgate,
        const float* __restrict__ wout) {
    const int P1 = N1 * DIM / 2;
    const int P2 = DIM * DIM / 2;
    const int idx = blockIdx.x * 256 + threadIdx.x;
    if (idx < P1) {
        const int kh = idx & 1, lane = (idx >> 1) & 31, ks = (idx >> 6) & 1;
        const int nbkt = idx >> 7, nb = nbkt % 400, kt = nbkt / 400;
        const int gr = lane >> 2, tg = lane & 3;
        const int n = nb * 8 + gr;
        const int k = kt * 32 + ks * 16 + kh * 8 + tg * 2;
        float v0 = 0.f, v1 = 0.f;
        if (n < NQKV)              { v0 = wqkv[k * NQKV + n];        v1 = wqkv[(k+1) * NQKV + n]; }
        else if (n < NQKV + NGATE) { v0 = wgate[k * NGATE + n-NQKV]; v1 = wgate[(k+1) * NGATE + n-NQKV]; }
        g_w1h[idx] = __floats2half2_rn(v0, v1);
    } else if (idx < P1 + P2) {
        const int j = idx - P1;
        const int kh = j & 1, lane = (j >> 1) & 31, ks = (j >> 6) & 1;
        const int nbkt = j >> 7, nb = nbkt % 128, kt = nbkt / 128;
        const int gr = lane >> 2, tg = lane & 3;
        const int n = nb * 8 + gr;
        const int k = kt * 32 + ks * 16 + kh * 8 + tg * 2;
        g_w2h[j] = __floats2half2_rn(wout[k * DIM + n], wout[(k+1) * DIM + n]);
    }
}

// ---- rmsnorm -> fp16 A-fragment layout ----
__global__ void __launch_bounds__(256) rmsnorm_kernel(
        const float* __restrict__ x, const float* __restrict__ w) {
    const int row = blockIdx.x;
    const int tid = threadIdx.x;
    const float4 xv = ((const float4*)(x + (size_t)row * DIM))[tid];
    float ss = xv.x*xv.x + xv.y*xv.y + xv.z*xv.z + xv.w*xv.w;
    #pragma unroll
    for (int off = 16; off > 0; off >>= 1)
        ss += __shfl_xor_sync(0xffffffffu, ss, off);
    __shared__ float wsum[8];
    const int lane = tid & 31, wid = tid >> 5;
    if (lane == 0) wsum[wid] = ss;
    __syncthreads();
    if (tid == 0) {
        float t = 0.f;
        #pragma unroll
        for (int i = 0; i < 8; ++i) t += wsum[i];
        wsum[0] = rsqrtf(t * (1.0f / DIM) + 1e-6f);
    }
    __syncthreads();
    const float scale = wsum[0];
    const float4 wv = ((const float4*)w)[tid];
    const int k0 = tid * 4;
    g_xnh[afrag_off(row, k0)]     = __floats2half2_rn(wv.x * (xv.x * scale), wv.y * (xv.y * scale));
    g_xnh[afrag_off(row, k0 + 2)] = __floats2half2_rn(wv.z * (xv.z * scale), wv.w * (xv.w * scale));
}

// ---- fp16 fragment-packed GEMM (128x128x32 tiles, m16n8k16, 4-stage) ----
template<int MODE>
__global__ void __launch_bounds__(256) gemm_f16_kernel(
        const float* __restrict__ X, float* __restrict__ Out) {
    constexpr int KT = DIM / 32;
    constexpr int N = (MODE == 0) ? N1 : DIM;
    const __half2* __restrict__ Af = (MODE == 0) ? g_xnh : g_hfh;
    const __half2* __restrict__ Bf = (MODE == 0) ? g_w1h : g_w2h;

    extern __shared__ float smem[];
    const int tid = threadIdx.x;
    const int mb = blockIdx.y, n0 = blockIdx.x * 128;
    const int m0 = mb * 128;
    const uint32_t smem_base = smem_u32(smem);

    auto issue = [&](int kt) {
        if (kt < KT) {
            const uint32_t st = smem_base + (uint32_t)(kt & 3) * 16384u;
            const __half2* sA = Af + (size_t)(mb * 32 + kt) * 2048;
            const __half2* sB = Bf + ((size_t)kt * (N >> 3) + (n0 >> 3)) * 128;
            cp16(st + (uint32_t)tid * 16u,           sA + tid * 4);
            cp16(st + (uint32_t)(tid + 256) * 16u,   sA + (tid + 256) * 4);
            cp16(st + 8192u + (uint32_t)tid * 16u,         sB + tid * 4);
            cp16(st + 8192u + (uint32_t)(tid + 256) * 16u, sB + (tid + 256) * 4);
        }
        cp_commit();
    };

    float acc[4][4][4];
    #pragma unroll
    for (int i = 0; i < 4; ++i)
        #pragma unroll
        for (int j = 0; j < 4; ++j)
            #pragma unroll
            for (int q = 0; q < 4; ++q) acc[i][j][q] = 0.f;

    issue(0); issue(1); issue(2);

    const int lane = tid & 31, wid = tid >> 5;
    const int R0 = (wid >> 2) * 4;
    const int nb0 = (wid & 3) * 4;
    const int wm = R0 * 16, wn = nb0 * 8;
    const int gr = lane >> 2, tg = lane & 3;

    for (int kt = 0; kt < KT; ++kt) {
        cp_wait<2>();
        __syncthreads();
        issue(kt + 3);
        const __half2* As = (const __half2*)((const char*)smem + (kt & 3) * 16384);
        const __half2* Bs = As + 2048;
        #pragma unroll
        for (int ks = 0; ks < 2; ++ks) {
            float4 af[4]; float2 bf[4];
            #pragma unroll
            for (int i = 0; i < 4; ++i)
                af[i] = *(const float4*)(As + ((R0 + i) * 2 + ks) * 128 + lane * 4);
            #pragma unroll
            for (int j = 0; j < 4; ++j)
                bf[j] = *(const float2*)(Bs + ((nb0 + j) * 2 + ks) * 64 + lane * 2);
            #pragma unroll
            for (int i = 0; i < 4; ++i)
                #pragma unroll
                for (int j = 0; j < 4; ++j)
                    mma_f16(acc[i][j], FU(af[i].x), FU(af[i].y), FU(af[i].z), FU(af[i].w),
                            FU(bf[j].x), FU(bf[j].y));
        }
    }

    #pragma unroll
    for (int i = 0; i < 4; ++i) {
        #pragma unroll
        for (int j = 0; j < 4; ++j) {
            const int r0 = m0 + wm + i * 16 + gr;
            const int c0 = n0 + wn + j * 8 + tg * 2;
            if (MODE == 0) {
                if (c0 < NQKV) {
                    *(__half2*)(g_qkvh + (size_t)r0 * NQKV + c0) =
                        __floats2half2_rn(acc[i][j][0], acc[i][j][1]);
                    *(__half2*)(g_qkvh + (size_t)(r0 + 8) * NQKV + c0) =
                        __floats2half2_rn(acc[i][j][2], acc[i][j][3]);
                } else {
                    #pragma unroll
                    for (int q = 0; q < 4; ++q) {
                        const int r = r0 + (q >> 1) * 8;
                        const int c = c0 + (q & 1);
                        if (c < NQKV + NGATE) {
                            float t = tanhf(acc[i][j][q] * (1.0f / 15.0f));
                            g_gates[(size_t)r * NGATE + (c - NQKV)] =
                                1.0f / (1.0f + expf(-15.0f * t));
                        }
                    }
                }
            } else {
                #pragma unroll
                for (int q = 0; q < 4; ++q) {
                    const int r = r0 + (q >> 1) * 8;
                    const int c = c0 + (q & 1);
                    Out[(size_t)r * DIM + c] = X[(size_t)r * DIM + c] + acc[i][j][q];
                }
            }
        }
    }
}

// ---- chunkwise phase 1: intra-chunk, fp16 m16n8k16 ----
#define SP 72     // half pitch
#define SP2 36    // half2 pitch
__global__ void __launch_bounds__(256) chunk_intra_kernel() {
    __shared__ __half Qh [64 * SP];   // (t,d); after GEMM1 reused as Ah (t,s)
    __shared__ __half Kh [64 * SP];   // (s,d)
    __shared__ __half Kth[64 * SP];   // (d,s) * Wc[s], col-swizzled
    __shared__ __half Vth[64 * SP];   // (e,s), col-swizzled
    __shared__ float LF[64], Wi[64], Wc[64];

    const int cidx = blockIdx.x;
    const int c = cidx & (NCHUNK - 1);
    const int bh = cidx >> 5;
    const int h = bh & 15, b = bh >> 4;
    const int m0 = b * SEQ + c * CHUNK;
    const int tid = threadIdx.x;

    float gi = 0.f, gf = 0.f;
    if (tid < 64) {
        gi = g_gates[(size_t)(m0 + tid) * NGATE + h];
        gf = g_gates[(size_t)(m0 + tid) * NGATE + 16 + h];
    }
    // qkv loads: 8 halves per load, 2 per tensor per thread
    uint4 hq[2], hk[2], hv[2];
    #pragma unroll
    for (int qq = 0; qq < 2; ++qq) {
        const int idx = tid + qq * 256;
        const int t = idx >> 3, d8 = (idx & 7) << 3;
        const __half* row = g_qkvh + (size_t)(m0 + t) * NQKV + h * 64 + d8;
        hq[qq] = *(const uint4*)row;
        hk[qq] = *(const uint4*)(row + 1024);
        hv[qq] = *(const uint4*)(row + 2048);
    }
    // direct stores: Qh, Kh natural; Vth transposed+swizzled
    #pragma unroll
    for (int qq = 0; qq < 2; ++qq) {
        const int idx = tid + qq * 256;
        const int t = idx >> 3, d8 = (idx & 7) << 3;
        *(uint4*)(Qh + t * SP + d8) = hq[qq];
        *(uint4*)(Kh + t * SP + d8) = hk[qq];
        const __half* pv = (const __half*)&hv[qq];
        #pragma unroll
        for (int jj = 0; jj < 8; ++jj) {
            const int d = d8 + jj;
            Vth[d * SP + (t ^ (((d >> 2) & 15) << 1))] = pv[jj];
        }
    }
    if (tid < 64) { Wi[tid] = gi; LF[tid] = __logf(gf); }
    __syncthreads();

    // warp-parallel inclusive scan of LF (warp 0)
    if (tid < 32) {
        float x0 = LF[tid], x1 = LF[tid + 32];
        #pragma unroll
        for (int off = 1; off < 32; off <<= 1) {
            float y = __shfl_up_sync(0xffffffffu, x0, off);
            if (tid >= off) x0 += y;
        }
        const float tot = __shfl_sync(0xffffffffu, x0, 31);
        #pragma unroll
        for (int off = 1; off < 32; off <<= 1) {
            float y = __shfl_up_sync(0xffffffffu, x1, off);
            if (tid >= off) x1 += y;
        }
        x1 += tot;
        LF[tid] = x0; LF[tid + 32] = x1;
        g_el[(size_t)(m0 + tid) * NH + h]      = __expf(x0);
        g_el[(size_t)(m0 + tid + 32) * NH + h] = __expf(x1);
    }
    __syncthreads();
    if (tid < 64) Wc[tid] = __expf(LF[63] - LF[tid]) * Wi[tid];
    if (tid == 0) g_Fc[cidx] = __expf(LF[63]);
    __syncthreads();

    // Kth = Wc[t] * K[t][d], transposed+swizzled (from registers)
    #pragma unroll
    for (int qq = 0; qq < 2; ++qq) {
        const int idx = tid + qq * 256;
        const int t = idx >> 3, d8 = (idx & 7) << 3;
        const float wcs = Wc[t];
        const __half* pk = (const __half*)&hk[qq];
        #pragma unroll
        for (int jj = 0; jj < 8; ++jj) {
            const int d = d8 + jj;
            Kth[d * SP + (t ^ (((d >> 2) & 15) << 1))] =
                __float2half(wcs * __half2float(pk[jj]));
        }
    }
    __syncthreads();

    const int lane = tid & 31, wid = tid >> 5;
    const int gr = lane >> 2, tg = lane & 3;
    const int wm = (wid >> 1) * 16, wn = (wid & 1) * 32;
    const int ra = wm + gr, rb = wm + 8 + gr;

    // GEMM1: raw[t][s] = sum_d Q[t][d] K[s][d]
    float acc1[4][4];
    #pragma unroll
    for (int j = 0; j < 4; ++j)
        #pragma unroll
        for (int q = 0; q < 4; ++q) acc1[j][q] = 0.f;
    {
        const __half2* Q2 = (const __half2*)Qh;
        const __half2* K2 = (const __half2*)Kh;
        #pragma unroll
        for (int ks = 0; ks < 4; ++ks) {
            const int kh2 = ks * 8 + tg;
            uint32_t a0 = H2U(Q2[ra * SP2 + kh2]);
            uint32_t a1 = H2U(Q2[rb * SP2 + kh2]);
            uint32_t a2 = H2U(Q2[ra * SP2 + kh2 + 4]);
            uint32_t a3 = H2U(Q2[rb * SP2 + kh2 + 4]);
            #pragma unroll
            for (int j = 0; j < 4; ++j) {
                const int n = wn + j * 8 + gr;
                mma_f16(acc1[j], a0, a1, a2, a3,
                        H2U(K2[n * SP2 + kh2]), H2U(K2[n * SP2 + kh2 + 4]));
            }
        }
    }
    __syncthreads();

    {
        __half* Ah = Qh;
        #pragma unroll
        for (int j = 0; j < 4; ++j)
            #pragma unroll
            for (int q = 0; q < 4; ++q) {
                const int t = wm + gr + (q >> 1) * 8;
                const int s = wn + j * 8 + tg * 2 + (q & 1);
                float v = 0.f;
                if (s <= t) v = acc1[j][q] * __expf(LF[t] - LF[s]) * Wi[s];
                Ah[t * SP + s] = __float2half(v);
            }
    }
    __syncthreads();

    // GEMM2: h[t][e] = sum_s A[t][s] V[s][e];  GEMM3: U[d][e] = sum_s Kth V
    float hacc[4][4], uacc[4][4];
    #pragma unroll
    for (int j = 0; j < 4; ++j)
        #pragma unroll
        for (int q = 0; q < 4; ++q) { hacc[j][q] = 0.f; uacc[j][q] = 0.f; }
    {
        const __half2* A2  = (const __half2*)Qh;
        const __half2* Kt2 = (const __half2*)Kth;
        const __half2* Vt2 = (const __half2*)Vth;
        const int swa = (ra >> 2) & 15, swb = (rb >> 2) & 15;
        #pragma unroll
        for (int ks = 0; ks < 4; ++ks) {
            const int kh2 = ks * 8 + tg;
            uint32_t ha0 = H2U(A2[ra * SP2 + kh2]);
            uint32_t ha1 = H2U(A2[rb * SP2 + kh2]);
            uint32_t ha2 = H2U(A2[ra * SP2 + kh2 + 4]);
            uint32_t ha3 = H2U(A2[rb * SP2 + kh2 + 4]);
            uint32_t ua0 = H2U(Kt2[ra * SP2 + (kh2 ^ swa)]);
            uint32_t ua1 = H2U(Kt2[rb * SP2 + (kh2 ^ swb)]);
            uint32_t ua2 = H2U(Kt2[ra * SP2 + ((kh2 + 4) ^ swa)]);
            uint32_t ua3 = H2U(Kt2[rb * SP2 + ((kh2 + 4) ^ swb)]);
            #pragma unroll
            for (int j = 0; j < 4; ++j) {
                const int n = wn + j * 8 + gr;
                const int swn = (n >> 2) & 15;
                uint32_t b0 = H2U(Vt2[n * SP2 + (kh2 ^ swn)]);
                uint32_t b1 = H2U(Vt2[n * SP2 + ((kh2 + 4) ^ swn)]);
                mma_f16(hacc[j], ha0, ha1, ha2, ha3, b0, b1);
                mma_f16(uacc[j], ua0, ua1, ua2, ua3, b0, b1);
            }
        }
    }
    #pragma unroll
    for (int j = 0; j < 4; ++j)
        #pragma unroll
        for (int q = 0; q < 4; ++q) {
            const int row = wm + gr + (q >> 1) * 8;
            const int col = wn + j * 8 + tg * 2 + (q & 1);
            g_h[(size_t)(m0 + row) * DIM + h * 64 + col] = hacc[j][q];
            g_U[(size_t)cidx * 4096 + row * 64 + col] = uacc[j][q];
        }
}

// ---- phase 2a: element-parallel state prefix ----
__global__ void __launch_bounds__(256) state_prefix_kernel(const float* __restrict__ hidden) {
    const int gid = blockIdx.x * 256 + threadIdx.x;
    const int bh = gid >> 10;
    const int off = (gid & 1023) * 4;
    float4 S = *(const float4*)(hidden + (size_t)bh * 4096 + off);
    const float* fc = g_Fc + bh * NCHUNK;
    #pragma unroll 4
    for (int c = 0; c < NCHUNK; ++c) {
        const size_t p = (size_t)(bh * NCHUNK + c) * 4096 + off;
        *(float4*)(g_S + p) = S;
        const float4 U = *(const float4*)(g_U + p);
        const float F = fc[c];
        S.x = F * S.x + U.x;
        S.y = F * S.y + U.y;
        S.z = F * S.z + U.z;
        S.w = F * S.w + U.w;
    }
}

// ---- phase 2b: h = (exp(LF)*q @ S_c + h_intra) * o, fp16 m16n8k16 ----
__global__ void __launch_bounds__(256) chunk_inter_kernel() {
    __shared__ __half Qsh[64 * SP];   // (t,d) = exp(LF_t) * q
    __shared__ __half Sth[64 * SP];   // (e,d) transposed S, col-swizzled
    __shared__ float Og[64], Eb[64];

    const int cidx = blockIdx.x;
    const int c = cidx & (NCHUNK - 1);
    const int bh = cidx >> 5;
    const int h = bh & 15, b = bh >> 4;
    const int m0 = b * SEQ + c * CHUNK;
    const int tid = threadIdx.x;

    uint4 hq[2];
    float4 s0[2], s1[2];
    #pragma unroll
    for (int qq = 0; qq < 2; ++qq) {
        const int idx = tid + qq * 256;
        const int t = idx >> 3, d8 = (idx & 7) << 3;
        hq[qq] = *(const uint4*)(g_qkvh + (size_t)(m0 + t) * NQKV + h * 64 + d8);
        s0[qq] = *(const float4*)(g_S + (size_t)cidx * 4096 + t * 64 + d8);
        s1[qq] = *(const float4*)(g_S + (size_t)cidx * 4096 + t * 64 + d8 + 4);
    }
    if (tid < 64) {
        Og[tid] = g_gates[(size_t)(m0 + tid) * NGATE + 32 + h];
        Eb[tid] = g_el[(size_t)(m0 + tid) * NH + h];
    }
    __syncthreads();

    #pragma unroll
    for (int qq = 0; qq < 2; ++qq) {
        const int idx = tid + qq * 256;
        const int t = idx >> 3, d8 = (idx & 7) << 3;
        // Qsh: scale q by Eb[t]
        {
            const float e = Eb[t];
            const __half2* pq = (const __half2*)&hq[qq];
            __half2* dst = (__half2*)(Qsh + t * SP + d8);
            #pragma unroll
            for (int jj = 0; jj < 4; ++jj) {
                float2 f = __half22float2(pq[jj]);
                dst[jj] = __floats2half2_rn(f.x * e, f.y * e);
            }
        }
        // Sth: transpose S[t=d][e] -> Sth[e][d] swizzled
        {
            const int d = t;
            const float sv[8] = {s0[qq].x, s0[qq].y, s0[qq].z, s0[qq].w,
                                 s1[qq].x, s1[qq].y, s1[qq].z, s1[qq].w};
            #pragma unroll
            for (int jj = 0; jj < 8; ++jj) {
                const int e = d8 + jj;
                Sth[e * SP + (d ^ (((e >> 2) & 15) << 1))] = __float2half(sv[jj]);
            }
        }
    }
    __syncthreads();

    const int lane = tid & 31, wid = tid >> 5;
    const int gr = lane >> 2, tg = lane & 3;
    const int wm = (wid >> 1) * 16, wn = (wid & 1) * 32;
    const int ra = wm + gr, rb = wm + 8 + gr;

    float acc[4][4];
    #pragma unroll
    for (int j = 0; j < 4; ++j)
        #pragma unroll
        for (int q = 0; q < 4; ++q) acc[j][q] = 0.f;
    {
        const __half2* Q2 = (const __half2*)Qsh;
        const __half2* St2 = (const __half2*)Sth;
        #pragma unroll
        for (int ks = 0; ks < 4; ++ks) {
            const int kh2 = ks * 8 + tg;
            uint32_t a0 = H2U(Q2[ra * SP2 + kh2]);
            uint32_t a1 = H2U(Q2[rb * SP2 + kh2]);
            uint32_t a2 = H2U(Q2[ra * SP2 + kh2 + 4]);
            uint32_t a3 = H2U(Q2[rb * SP2 + kh2 + 4]);
            #pragma unroll
            for (int j = 0; j < 4; ++j) {
                const int n = wn + j * 8 + gr;
                const int swn = (n >> 2) & 15;
                mma_f16(acc[j], a0, a1, a2, a3,
                        H2U(St2[n * SP2 + (kh2 ^ swn)]),
                        H2U(St2[n * SP2 + ((kh2 + 4) ^ swn)]));
            }
        }
    }

    #pragma unroll
    for (int j = 0; j < 4; ++j)
        #pragma unroll
        for (int qp = 0; qp < 2; ++qp) {
            const int row = wm + gr + qp * 8;
            const int col = wn + j * 8 + tg * 2;
            const int m = m0 + row;
            const float og = Og[row];
            const float hv0 = (acc[j][qp*2]   + g_h[(size_t)m * DIM + h * 64 + col])     * og;
            const float hv1 = (acc[j][qp*2+1] + g_h[(size_t)m * DIM + h * 64 + col + 1]) * og;
            g_hfh[afrag_off(m, h * 64 + col)] = __floats2half2_rn(hv0, hv1);
        }
}

extern "C" void kernel_launch(void* const* d_in, const int* in_sizes, int n_in,
                              void* d_out, int out_size) {
    const float* x      = (const float*)d_in[0];
    const float* hidden = (const float*)d_in[1];
    const float* w_rms  = (const float*)d_in[2];
    const float* w_qkv  = (const float*)d_in[3];
    const float* w_gate = (const float*)d_in[4];
    const float* w_out  = (const float*)d_in[5];
    float* out = (float*)d_out;

    static bool attr_done = false;
    if (!attr_done) {
        cudaFuncSetAttribute(gemm_f16_kernel<0>,
            cudaFuncAttributeMaxDynamicSharedMemorySize, 65536);
        cudaFuncSetAttribute(gemm_f16_kernel<1>,
            cudaFuncAttributeMaxDynamicSharedMemorySize, 65536);
        attr_done = true;
    }

    const int PAIRS = N1 * DIM / 2 + DIM * DIM / 2;
    prep_weights_kernel<<<(PAIRS + 255) / 256, 256>>>(w_qkv, w_gate, w_out);
    rmsnorm_kernel<<<MTOK, 256>>>(x, w_rms);
    {
        dim3 grid(N1 / 128, MTOK / 128);
        gemm_f16_kernel<0><<<grid, 256, 65536>>>(nullptr, nullptr);
    }
    chunk_intra_kernel<<<TOTCHUNK, 256>>>();
    state_prefix_kernel<<<256, 256>>>(hidden);
    chunk_inter_kernel<<<TOTCHUNK, 256>>>();
    {
        dim3 grid(DIM / 128, MTOK / 128);
        gemm_f16_kernel<1><<<grid, 256, 65536>>>(x, out);
    }
}

// round 10
// speedup vs baseline: 4.6219x; 1.0258x over previous
#include <cuda_runtime.h>
#include <cuda_fp16.h>
#include <cstdint>
#include <cmath>

#define BATCH 4
#define SEQ   2048
#define DIM   1024
#define NH    16
#define DH    64
#define MTOK  (BATCH*SEQ)
#define N1    3200
#define NQKV  3072
#define NGATE 48
#define CHUNK 64
#define NCHUNK (SEQ/CHUNK)              // 32
#define TOTCHUNK (BATCH*NH*NCHUNK)      // 2048

// fp16 fragment-packed GEMM operands
__device__ __half2 g_xnh [MTOK * DIM / 2];    // A-fragments of rmsnormed x
__device__ __half2 g_w1h [N1 * DIM / 2];      // B-fragments of [wqkv|wgate|0]
__device__ __half2 g_w2h [DIM * DIM / 2];     // B-fragments of w_out
__device__ __half2 g_hfh [MTOK * DIM / 2];    // A-fragments of final h
// plain buffers
__device__ __half g_qkvh[MTOK * NQKV];        // qkv in fp16, [m][3072]
__device__ float g_gates[MTOK * NGATE];
__device__ float g_h   [MTOK * DIM];          // h_intra (fp32)
__device__ float g_el  [MTOK * NH];           // exp(LF_t) per (m, h)
__device__ float g_U   [TOTCHUNK * 64 * 64];
__device__ float g_S   [TOTCHUNK * 64 * 64];
__device__ float g_Fc  [TOTCHUNK];

__device__ __forceinline__ uint32_t smem_u32(const void* p) {
    return (uint32_t)__cvta_generic_to_shared(p);
}
__device__ __forceinline__ void cp16(uint32_t s, const void* g) {
    asm volatile("cp.async.cg.shared.global [%0], [%1], 16;\n" :: "r"(s), "l"(g));
}
__device__ __forceinline__ void cp_commit() {
    asm volatile("cp.async.commit_group;\n" ::: "memory");
}
template<int N> __device__ __forceinline__ void cp_wait() {
    asm volatile("cp.async.wait_group %0;\n" :: "n"(N) : "memory");
}
__device__ __forceinline__ void mma_f16(float c[4],
        uint32_t a0, uint32_t a1, uint32_t a2, uint32_t a3,
        uint32_t b0, uint32_t b1) {
    asm volatile(
        "mma.sync.aligned.m16n8k16.row.col.f32.f16.f16.f32 "
        "{%0,%1,%2,%3},{%4,%5,%6,%7},{%8,%9},{%0,%1,%2,%3};\n"
        : "+f"(c[0]), "+f"(c[1]), "+f"(c[2]), "+f"(c[3])
        : "r"(a0), "r"(a1), "r"(a2), "r"(a3), "r"(b0), "r"(b1));
}
#define FU(x) __float_as_uint(x)
__device__ __forceinline__ uint32_t H2U(__half2 v) { return *(uint32_t*)&v; }

// A-fragment half2 offset for (m, k even)
__device__ __forceinline__ size_t afrag_off(int m, int k) {
    const int mb = m >> 7, kt = k >> 5, R = (m >> 4) & 7, ks = (k >> 4) & 1;
    const int gr = m & 7, hb = (m >> 3) & 1, tg = (k & 7) >> 1, kh = (k >> 3) & 1;
    return ((((size_t)(mb * 32 + kt) * 8 + R) * 2 + ks) * 128)
         + (gr * 4 + tg) * 4 + (hb + 2 * kh);
}

// ---- prep: pack weights into fp16 B-fragment layout ----
__global__ void __launch_bounds__(256) prep_weights_kernel(
        const float* __restrict__ wqkv, const float* __restrict__ wgate,
        const float* __restrict__ wout) {
    const int P1 = N1 * DIM / 2;
    const int P2 = DIM * DIM / 2;
    const int idx = blockIdx.x * 256 + threadIdx.x;
    if (idx < P1) {
        const int kh = idx & 1, lane = (idx >> 1) & 31, ks = (idx >> 6) & 1;
        const int nbkt = idx >> 7, nb = nbkt % 400, kt = nbkt / 400;
        const int gr = lane >> 2, tg = lane & 3;
        const int n = nb * 8 + gr;
        const int k = kt * 32 + ks * 16 + kh * 8 + tg * 2;
        float v0 = 0.f, v1 = 0.f;
        if (n < NQKV)              { v0 = wqkv[k * NQKV + n];        v1 = wqkv[(k+1) * NQKV + n]; }
        else if (n < NQKV + NGATE) { v0 = wgate[k * NGATE + n-NQKV]; v1 = wgate[(k+1) * NGATE + n-NQKV]; }
        g_w1h[idx] = __floats2half2_rn(v0, v1);
    } else if (idx < P1 + P2) {
        const int j = idx - P1;
        const int kh = j & 1, lane = (j >> 1) & 31, ks = (j >> 6) & 1;
        const int nbkt = j >> 7, nb = nbkt % 128, kt = nbkt / 128;
        const int gr = lane >> 2, tg = lane & 3;
        const int n = nb * 8 + gr;
        const int k = kt * 32 + ks * 16 + kh * 8 + tg * 2;
        g_w2h[j] = __floats2half2_rn(wout[k * DIM + n], wout[(k+1) * DIM + n]);
    }
}

// ---- rmsnorm -> fp16 A-fragment layout ----
__global__ void __launch_bounds__(256) rmsnorm_kernel(
        const float* __restrict__ x, const float* __restrict__ w) {
    const int row = blockIdx.x;
    const int tid = threadIdx.x;
    const float4 xv = ((const float4*)(x + (size_t)row * DIM))[tid];
    float ss = xv.x*xv.x + xv.y*xv.y + xv.z*xv.z + xv.w*xv.w;
    #pragma unroll
    for (int off = 16; off > 0; off >>= 1)
        ss += __shfl_xor_sync(0xffffffffu, ss, off);
    __shared__ float wsum[8];
    const int lane = tid & 31, wid = tid >> 5;
    if (lane == 0) wsum[wid] = ss;
    __syncthreads();
    if (tid == 0) {
        float t = 0.f;
        #pragma unroll
        for (int i = 0; i < 8; ++i) t += wsum[i];
        wsum[0] = rsqrtf(t * (1.0f / DIM) + 1e-6f);
    }
    __syncthreads();
    const float scale = wsum[0];
    const float4 wv = ((const float4*)w)[tid];
    const int k0 = tid * 4;
    g_xnh[afrag_off(row, k0)]     = __floats2half2_rn(wv.x * (xv.x * scale), wv.y * (xv.y * scale));
    g_xnh[afrag_off(row, k0 + 2)] = __floats2half2_rn(wv.z * (xv.z * scale), wv.w * (xv.w * scale));
}

// ---- fp16 fragment-packed GEMM: 128x128x32 tiles, 4 warps of 64x64, 4-stage ----
template<int MODE>
__global__ void __launch_bounds__(128, 2) gemm_f16_kernel(
        const float* __restrict__ X, float* __restrict__ Out) {
    constexpr int KT = DIM / 32;
    constexpr int N = (MODE == 0) ? N1 : DIM;
    const __half2* __restrict__ Af = (MODE == 0) ? g_xnh : g_hfh;
    const __half2* __restrict__ Bf = (MODE == 0) ? g_w1h : g_w2h;

    extern __shared__ float smem[];
    const int tid = threadIdx.x;
    const int mb = blockIdx.y, n0 = blockIdx.x * 128;
    const int m0 = mb * 128;
    const uint32_t smem_base = smem_u32(smem);

    auto issue = [&](int kt) {
        if (kt < KT) {
            const uint32_t st = smem_base + (uint32_t)(kt & 3) * 16384u;
            const __half2* sA = Af + (size_t)(mb * 32 + kt) * 2048;
            const __half2* sB = Bf + ((size_t)kt * (N >> 3) + (n0 >> 3)) * 128;
            #pragma unroll
            for (int q = 0; q < 4; ++q)
                cp16(st + (uint32_t)(tid + q * 128) * 16u, sA + (tid + q * 128) * 4);
            #pragma unroll
            for (int q = 0; q < 4; ++q)
                cp16(st + 8192u + (uint32_t)(tid + q * 128) * 16u, sB + (tid + q * 128) * 4);
        }
        cp_commit();
    };

    float acc[4][8][4];
    #pragma unroll
    for (int i = 0; i < 4; ++i)
        #pragma unroll
        for (int j = 0; j < 8; ++j)
            #pragma unroll
            for (int q = 0; q < 4; ++q) acc[i][j][q] = 0.f;

    issue(0); issue(1); issue(2);

    const int lane = tid & 31, wid = tid >> 5;
    const int R0 = (wid >> 1) * 4;     // 4 m-blocks of 16
    const int nb0 = (wid & 1) * 8;     // 8 n-blocks of 8
    const int wm = R0 * 16, wn = nb0 * 8;
    const int gr = lane >> 2, tg = lane & 3;

    for (int kt = 0; kt < KT; ++kt) {
        cp_wait<2>();
        __syncthreads();
        issue(kt + 3);
        const __half2* As = (const __half2*)((const char*)smem + (kt & 3) * 16384);
        const __half2* Bs = As + 2048;
        #pragma unroll
        for (int ks = 0; ks < 2; ++ks) {
            float4 af[4]; float2 bf[8];
            #pragma unroll
            for (int i = 0; i < 4; ++i)
                af[i] = *(const float4*)(As + ((R0 + i) * 2 + ks) * 128 + lane * 4);
            #pragma unroll
            for (int j = 0; j < 8; ++j)
                bf[j] = *(const float2*)(Bs + ((nb0 + j) * 2 + ks) * 64 + lane * 2);
            #pragma unroll
            for (int i = 0; i < 4; ++i)
                #pragma unroll
                for (int j = 0; j < 8; ++j)
                    mma_f16(acc[i][j], FU(af[i].x), FU(af[i].y), FU(af[i].z), FU(af[i].w),
                            FU(bf[j].x), FU(bf[j].y));
        }
    }

    #pragma unroll
    for (int i = 0; i < 4; ++i) {
        #pragma unroll
        for (int j = 0; j < 8; ++j) {
            const int r0 = m0 + wm + i * 16 + gr;
            const int c0 = n0 + wn + j * 8 + tg * 2;
            if (MODE == 0) {
                if (c0 < NQKV) {
                    *(__half2*)(g_qkvh + (size_t)r0 * NQKV + c0) =
                        __floats2half2_rn(acc[i][j][0], acc[i][j][1]);
                    *(__half2*)(g_qkvh + (size_t)(r0 + 8) * NQKV + c0) =
                        __floats2half2_rn(acc[i][j][2], acc[i][j][3]);
                } else {
                    #pragma unroll
                    for (int q = 0; q < 4; ++q) {
                        const int r = r0 + (q >> 1) * 8;
                        const int c = c0 + (q & 1);
                        if (c < NQKV + NGATE) {
                            float t = tanhf(acc[i][j][q] * (1.0f / 15.0f));
                            g_gates[(size_t)r * NGATE + (c - NQKV)] =
                                1.0f / (1.0f + expf(-15.0f * t));
                        }
                    }
                }
            } else {
                #pragma unroll
                for (int q = 0; q < 4; ++q) {
                    const int r = r0 + (q >> 1) * 8;
                    const int c = c0 + (q & 1);
                    Out[(size_t)r * DIM + c] = X[(size_t)r * DIM + c] + acc[i][j][q];
                }
            }
        }
    }
}

// ---- chunkwise phase 1: intra-chunk, fp16 m16n8k16 ----
#define SP 72     // half pitch
#define SP2 36    // half2 pitch
__global__ void __launch_bounds__(256) chunk_intra_kernel() {
    __shared__ __half Qh [64 * SP];   // (t,d); after GEMM1 reused as Ah (t,s)
    __shared__ __half Kh [64 * SP];   // (s,d)
    __shared__ __half Kth[64 * SP];   // (d,s) * Wc[s], col-swizzled
    __shared__ __half Vth[64 * SP];   // (e,s), col-swizzled
    __shared__ float LF[64], Wi[64], Wc[64];

    const int cidx = blockIdx.x;
    const int c = cidx & (NCHUNK - 1);
    const int bh = cidx >> 5;
    const int h = bh & 15, b = bh >> 4;
    const int m0 = b * SEQ + c * CHUNK;
    const int tid = threadIdx.x;

    float gi = 0.f, gf = 0.f;
    if (tid < 64) {
        gi = g_gates[(size_t)(m0 + tid) * NGATE + h];
        gf = g_gates[(size_t)(m0 + tid) * NGATE + 16 + h];
    }
    uint4 hq[2], hk[2], hv[2];
    #pragma unroll
    for (int qq = 0; qq < 2; ++qq) {
        const int idx = tid + qq * 256;
        const int t = idx >> 3, d8 = (idx & 7) << 3;
        const __half* row = g_qkvh + (size_t)(m0 + t) * NQKV + h * 64 + d8;
        hq[qq] = *(const uint4*)row;
        hk[qq] = *(const uint4*)(row + 1024);
        hv[qq] = *(const uint4*)(row + 2048);
    }
    #pragma unroll
    for (int qq = 0; qq < 2; ++qq) {
        const int idx = tid + qq * 256;
        const int t = idx >> 3, d8 = (idx & 7) << 3;
        *(uint4*)(Qh + t * SP + d8) = hq[qq];
        *(uint4*)(Kh + t * SP + d8) = hk[qq];
        const __half* pv = (const __half*)&hv[qq];
        #pragma unroll
        for (int jj = 0; jj < 8; ++jj) {
            const int d = d8 + jj;
            Vth[d * SP + (t ^ (((d >> 2) & 15) << 1))] = pv[jj];
        }
    }
    if (tid < 64) { Wi[tid] = gi; LF[tid] = __logf(gf); }
    __syncthreads();

    if (tid < 32) {
        float x0 = LF[tid], x1 = LF[tid + 32];
        #pragma unroll
        for (int off = 1; off < 32; off <<= 1) {
            float y = __shfl_up_sync(0xffffffffu, x0, off);
            if (tid >= off) x0 += y;
        }
        const float tot = __shfl_sync(0xffffffffu, x0, 31);
        #pragma unroll
        for (int off = 1; off < 32; off <<= 1) {
            float y = __shfl_up_sync(0xffffffffu, x1, off);
            if (tid >= off) x1 += y;
        }
        x1 += tot;
        LF[tid] = x0; LF[tid + 32] = x1;
        g_el[(size_t)(m0 + tid) * NH + h]      = __expf(x0);
        g_el[(size_t)(m0 + tid + 32) * NH + h] = __expf(x1);
    }
    __syncthreads();
    if (tid < 64) Wc[tid] = __expf(LF[63] - LF[tid]) * Wi[tid];
    if (tid == 0) g_Fc[cidx] = __expf(LF[63]);
    __syncthreads();

    #pragma unroll
    for (int qq = 0; qq < 2; ++qq) {
        const int idx = tid + qq * 256;
        const int t = idx >> 3, d8 = (idx & 7) << 3;
        const float wcs = Wc[t];
        const __half* pk = (const __half*)&hk[qq];
        #pragma unroll
        for (int jj = 0; jj < 8; ++jj) {
            const int d = d8 + jj;
            Kth[d * SP + (t ^ (((d >> 2) & 15) << 1))] =
                __float2half(wcs * __half2float(pk[jj]));
        }
    }
    __syncthreads();

    const int lane = tid & 31, wid = tid >> 5;
    const int gr = lane >> 2, tg = lane & 3;
    const int wm = (wid >> 1) * 16, wn = (wid & 1) * 32;
    const int ra = wm + gr, rb = wm + 8 + gr;

    float acc1[4][4];
    #pragma unroll
    for (int j = 0; j < 4; ++j)
        #pragma unroll
        for (int q = 0; q < 4; ++q) acc1[j][q] = 0.f;
    {
        const __half2* Q2 = (const __half2*)Qh;
        const __half2* K2 = (const __half2*)Kh;
        #pragma unroll
        for (int ks = 0; ks < 4; ++ks) {
            const int kh2 = ks * 8 + tg;
            uint32_t a0 = H2U(Q2[ra * SP2 + kh2]);
            uint32_t a1 = H2U(Q2[rb * SP2 + kh2]);
            uint32_t a2 = H2U(Q2[ra * SP2 + kh2 + 4]);
            uint32_t a3 = H2U(Q2[rb * SP2 + kh2 + 4]);
            #pragma unroll
            for (int j = 0; j < 4; ++j) {
                const int n = wn + j * 8 + gr;
                mma_f16(acc1[j], a0, a1, a2, a3,
                        H2U(K2[n * SP2 + kh2]), H2U(K2[n * SP2 + kh2 + 4]));
            }
        }
    }
    __syncthreads();

    {
        __half* Ah = Qh;
        #pragma unroll
        for (int j = 0; j < 4; ++j)
            #pragma unroll
            for (int q = 0; q < 4; ++q) {
                const int t = wm + gr + (q >> 1) * 8;
                const int s = wn + j * 8 + tg * 2 + (q & 1);
                float v = 0.f;
                if (s <= t) v = acc1[j][q] * __expf(LF[t] - LF[s]) * Wi[s];
                Ah[t * SP + s] = __float2half(v);
            }
    }
    __syncthreads();

    float hacc[4][4], uacc[4][4];
    #pragma unroll
    for (int j = 0; j < 4; ++j)
        #pragma unroll
        for (int q = 0; q < 4; ++q) { hacc[j][q] = 0.f; uacc[j][q] = 0.f; }
    {
        const __half2* A2  = (const __half2*)Qh;
        const __half2* Kt2 = (const __half2*)Kth;
        const __half2* Vt2 = (const __half2*)Vth;
        const int swa = (ra >> 2) & 15, swb = (rb >> 2) & 15;
        #pragma unroll
        for (int ks = 0; ks < 4; ++ks) {
            const int kh2 = ks * 8 + tg;
            uint32_t ha0 = H2U(A2[ra * SP2 + kh2]);
            uint32_t ha1 = H2U(A2[rb * SP2 + kh2]);
            uint32_t ha2 = H2U(A2[ra * SP2 + kh2 + 4]);
            uint32_t ha3 = H2U(A2[rb * SP2 + kh2 + 4]);
            uint32_t ua0 = H2U(Kt2[ra * SP2 + (kh2 ^ swa)]);
            uint32_t ua1 = H2U(Kt2[rb * SP2 + (kh2 ^ swb)]);
            uint32_t ua2 = H2U(Kt2[ra * SP2 + ((kh2 + 4) ^ swa)]);
            uint32_t ua3 = H2U(Kt2[rb * SP2 + ((kh2 + 4) ^ swb)]);
            #pragma unroll
            for (int j = 0; j < 4; ++j) {
                const int n = wn + j * 8 + gr;
                const int swn = (n >> 2) & 15;
                uint32_t b0 = H2U(Vt2[n * SP2 + (kh2 ^ swn)]);
                uint32_t b1 = H2U(Vt2[n * SP2 + ((kh2 + 4) ^ swn)]);
                mma_f16(hacc[j], ha0, ha1, ha2, ha3, b0, b1);
                mma_f16(uacc[j], ua0, ua1, ua2, ua3, b0, b1);
            }
        }
    }
    #pragma unroll
    for (int j = 0; j < 4; ++j)
        #pragma unroll
        for (int q = 0; q < 4; ++q) {
            const int row = wm + gr + (q >> 1) * 8;
            const int col = wn + j * 8 + tg * 2 + (q & 1);
            g_h[(size_t)(m0 + row) * DIM + h * 64 + col] = hacc[j][q];
            g_U[(size_t)cidx * 4096 + row * 64 + col] = uacc[j][q];
        }
}

// ---- phase 2a: element-parallel state prefix ----
__global__ void __launch_bounds__(256) state_prefix_kernel(const float* __restrict__ hidden) {
    const int gid = blockIdx.x * 256 + threadIdx.x;
    const int bh = gid >> 10;
    const int off = (gid & 1023) * 4;
    float4 S = *(const float4*)(hidden + (size_t)bh * 4096 + off);
    const float* fc = g_Fc + bh * NCHUNK;
    #pragma unroll 4
    for (int c = 0; c < NCHUNK; ++c) {
        const size_t p = (size_t)(bh * NCHUNK + c) * 4096 + off;
        *(float4*)(g_S + p) = S;
        const float4 U = *(const float4*)(g_U + p);
        const float F = fc[c];
        S.x = F * S.x + U.x;
        S.y = F * S.y + U.y;
        S.z = F * S.z + U.z;
        S.w = F * S.w + U.w;
    }
}

// ---- phase 2b: h = (exp(LF)*q @ S_c + h_intra) * o, fp16 m16n8k16 ----
__global__ void __launch_bounds__(256) chunk_inter_kernel() {
    __shared__ __half Qsh[64 * SP];   // (t,d) = exp(LF_t) * q
    __shared__ __half Sth[64 * SP];   // (e,d) transposed S, col-swizzled
    __shared__ float Og[64], Eb[64];

    const int cidx = blockIdx.x;
    const int c = cidx & (NCHUNK - 1);
    const int bh = cidx >> 5;
    const int h = bh & 15, b = bh >> 4;
    const int m0 = b * SEQ + c * CHUNK;
    const int tid = threadIdx.x;

    uint4 hq[2];
    float4 s0[2], s1[2];
    #pragma unroll
    for (int qq = 0; qq < 2; ++qq) {
        const int idx = tid + qq * 256;
        const int t = idx >> 3, d8 = (idx & 7) << 3;
        hq[qq] = *(const uint4*)(g_qkvh + (size_t)(m0 + t) * NQKV + h * 64 + d8);
        s0[qq] = *(const float4*)(g_S + (size_t)cidx * 4096 + t * 64 + d8);
        s1[qq] = *(const float4*)(g_S + (size_t)cidx * 4096 + t * 64 + d8 + 4);
    }
    if (tid < 64) {
        Og[tid] = g_gates[(size_t)(m0 + tid) * NGATE + 32 + h];
        Eb[tid] = g_el[(size_t)(m0 + tid) * NH + h];
    }
    __syncthreads();

    #pragma unroll
    for (int qq = 0; qq < 2; ++qq) {
        const int idx = tid + qq * 256;
        const int t = idx >> 3, d8 = (idx & 7) << 3;
        {
            const float e = Eb[t];
            const __half2* pq = (const __half2*)&hq[qq];
            __half2* dst = (__half2*)(Qsh + t * SP + d8);
            #pragma unroll
            for (int jj = 0; jj < 4; ++jj) {
                float2 f = __half22float2(pq[jj]);
                dst[jj] = __floats2half2_rn(f.x * e, f.y * e);
            }
        }
        {
            const int d = t;
            const float sv[8] = {s0[qq].x, s0[qq].y, s0[qq].z, s0[qq].w,
                                 s1[qq].x, s1[qq].y, s1[qq].z, s1[qq].w};
            #pragma unroll
            for (int jj = 0; jj < 8; ++jj) {
                const int e = d8 + jj;
                Sth[e * SP + (d ^ (((e >> 2) & 15) << 1))] = __float2half(sv[jj]);
            }
        }
    }
    __syncthreads();

    const int lane = tid & 31, wid = tid >> 5;
    const int gr = lane >> 2, tg = lane & 3;
    const int wm = (wid >> 1) * 16, wn = (wid & 1) * 32;
    const int ra = wm + gr, rb = wm + 8 + gr;

    float acc[4][4];
    #pragma unroll
    for (int j = 0; j < 4; ++j)
        #pragma unroll
        for (int q = 0; q < 4; ++q) acc[j][q] = 0.f;
    {
        const __half2* Q2 = (const __half2*)Qsh;
        const __half2* St2 = (const __half2*)Sth;
        #pragma unroll
        for (int ks = 0; ks < 4; ++ks) {
            const int kh2 = ks * 8 + tg;
            uint32_t a0 = H2U(Q2[ra * SP2 + kh2]);
            uint32_t a1 = H2U(Q2[rb * SP2 + kh2]);
            uint32_t a2 = H2U(Q2[ra * SP2 + kh2 + 4]);
            uint32_t a3 = H2U(Q2[rb * SP2 + kh2 + 4]);
            #pragma unroll
            for (int j = 0; j < 4; ++j) {
                const int n = wn + j * 8 + gr;
                const int swn = (n >> 2) & 15;
                mma_f16(acc[j], a0, a1, a2, a3,
                        H2U(St2[n * SP2 + (kh2 ^ swn)]),
                        H2U(St2[n * SP2 + ((kh2 + 4) ^ swn)]));
            }
        }
    }

    #pragma unroll
    for (int j = 0; j < 4; ++j)
        #pragma unroll
        for (int qp = 0; qp < 2; ++qp) {
            const int row = wm + gr + qp * 8;
            const int col = wn + j * 8 + tg * 2;
            const int m = m0 + row;
            const float og = Og[row];
            const float hv0 = (acc[j][qp*2]   + g_h[(size_t)m * DIM + h * 64 + col])     * og;
            const float hv1 = (acc[j][qp*2+1] + g_h[(size_t)m * DIM + h * 64 + col + 1]) * og;
            g_hfh[afrag_off(m, h * 64 + col)] = __floats2half2_rn(hv0, hv1);
        }
}

extern "C" void kernel_launch(void* const* d_in, const int* in_sizes, int n_in,
                              void* d_out, int out_size) {
    const float* x      = (const float*)d_in[0];
    const float* hidden = (const float*)d_in[1];
    const float* w_rms  = (const float*)d_in[2];
    const float* w_qkv  = (const float*)d_in[3];
    const float* w_gate = (const float*)d_in[4];
    const float* w_out  = (const float*)d_in[5];
    float* out = (float*)d_out;

    static bool attr_done = false;
    if (!attr_done) {
        cudaFuncSetAttribute(gemm_f16_kernel<0>,
            cudaFuncAttributeMaxDynamicSharedMemorySize, 65536);
        cudaFuncSetAttribute(gemm_f16_kernel<1>,
            cudaFuncAttributeMaxDynamicSharedMemorySize, 65536);
        attr_done = true;
    }

    const int PAIRS = N1 * DIM / 2 + DIM * DIM / 2;
    prep_weights_kernel<<<(PAIRS + 255) / 256, 256>>>(w_qkv, w_gate, w_out);
    rmsnorm_kernel<<<MTOK, 256>>>(x, w_rms);
    {
        dim3 grid(N1 / 128, MTOK / 128);
        gemm_f16_kernel<0><<<grid, 128, 65536>>>(nullptr, nullptr);
    }
    chunk_intra_kernel<<<TOTCHUNK, 256>>>();
    state_prefix_kernel<<<256, 256>>>(hidden);
    chunk_inter_kernel<<<TOTCHUNK, 256>>>();
    {
        dim3 grid(DIM / 128, MTOK / 128);
        gemm_f16_kernel<1><<<grid, 128, 65536>>>(x, out);
    }
}

// round 11
// speedup vs baseline: 4.9820x; 1.0779x over previous
#include <cuda_runtime.h>
#include <cuda_fp16.h>
#include <cstdint>
#include <cmath>

#define BATCH 4
#define SEQ   2048
#define DIM   1024
#define NH    16
#define DH    64
#define MTOK  (BATCH*SEQ)
#define N1    3200
#define NQKV  3072
#define NGATE 48
#define CHUNK 64
#define NCHUNK (SEQ/CHUNK)              // 32
#define TOTCHUNK (BATCH*NH*NCHUNK)      // 2048

// fp16 fragment-packed GEMM operands
__device__ __half2 g_xnh [MTOK * DIM / 2];    // A-fragments of rmsnormed x
__device__ __half2 g_w1h [N1 * DIM / 2];      // B-fragments of [wqkv|wgate|0]
__device__ __half2 g_w2h [DIM * DIM / 2];     // B-fragments of w_out
__device__ __half2 g_hfh [MTOK * DIM / 2];    // A-fragments of final h
// plain buffers
__device__ __half g_qkvh[MTOK * NQKV];        // qkv in fp16, [m][3072]
__device__ float  g_gt  [3 * NH * MTOK];      // gates transposed [gate][h][m]
__device__ float  g_el  [NH * MTOK];          // exp(LF_t), [h][m]
__device__ __half g_hh  [MTOK * DIM];         // h_intra (fp16)
__device__ __half g_Uh  [TOTCHUNK * 64 * 64]; // chunk increments (fp16)
__device__ __half g_Sh  [TOTCHUNK * 64 * 64]; // state before each chunk (fp16)
__device__ float  g_Fc  [TOTCHUNK];

__device__ __forceinline__ uint32_t smem_u32(const void* p) {
    return (uint32_t)__cvta_generic_to_shared(p);
}
__device__ __forceinline__ void cp16(uint32_t s, const void* g) {
    asm volatile("cp.async.cg.shared.global [%0], [%1], 16;\n" :: "r"(s), "l"(g));
}
__device__ __forceinline__ void cp_commit() {
    asm volatile("cp.async.commit_group;\n" ::: "memory");
}
template<int N> __device__ __forceinline__ void cp_wait() {
    asm volatile("cp.async.wait_group %0;\n" :: "n"(N) : "memory");
}
__device__ __forceinline__ void mma_f16(float c[4],
        uint32_t a0, uint32_t a1, uint32_t a2, uint32_t a3,
        uint32_t b0, uint32_t b1) {
    asm volatile(
        "mma.sync.aligned.m16n8k16.row.col.f32.f16.f16.f32 "
        "{%0,%1,%2,%3},{%4,%5,%6,%7},{%8,%9},{%0,%1,%2,%3};\n"
        : "+f"(c[0]), "+f"(c[1]), "+f"(c[2]), "+f"(c[3])
        : "r"(a0), "r"(a1), "r"(a2), "r"(a3), "r"(b0), "r"(b1));
}
#define FU(x) __float_as_uint(x)
__device__ __forceinline__ uint32_t H2U(__half2 v) { return *(uint32_t*)&v; }

// A-fragment half2 offset for (m, k even)
__device__ __forceinline__ size_t afrag_off(int m, int k) {
    const int mb = m >> 7, kt = k >> 5, R = (m >> 4) & 7, ks = (k >> 4) & 1;
    const int gr = m & 7, hb = (m >> 3) & 1, tg = (k & 7) >> 1, kh = (k >> 3) & 1;
    return ((((size_t)(mb * 32 + kt) * 8 + R) * 2 + ks) * 128)
         + (gr * 4 + tg) * 4 + (hb + 2 * kh);
}

// ---- prep: pack weights into fp16 B-fragment layout ----
__global__ void __launch_bounds__(256) prep_weights_kernel(
        const float* __restrict__ wqkv, const float* __restrict__ wgate,
        const float* __restrict__ wout) {
    const int P1 = N1 * DIM / 2;
    const int P2 = DIM * DIM / 2;
    const int idx = blockIdx.x * 256 + threadIdx.x;
    if (idx < P1) {
        const int kh = idx & 1, lane = (idx >> 1) & 31, ks = (idx >> 6) & 1;
        const int nbkt = idx >> 7, nb = nbkt % 400, kt = nbkt / 400;
        const int gr = lane >> 2, tg = lane & 3;
        const int n = nb * 8 + gr;
        const int k = kt * 32 + ks * 16 + kh * 8 + tg * 2;
        float v0 = 0.f, v1 = 0.f;
        if (n < NQKV)              { v0 = wqkv[k * NQKV + n];        v1 = wqkv[(k+1) * NQKV + n]; }
        else if (n < NQKV + NGATE) { v0 = wgate[k * NGATE + n-NQKV]; v1 = wgate[(k+1) * NGATE + n-NQKV]; }
        g_w1h[idx] = __floats2half2_rn(v0, v1);
    } else if (idx < P1 + P2) {
        const int j = idx - P1;
        const int kh = j & 1, lane = (j >> 1) & 31, ks = (j >> 6) & 1;
        const int nbkt = j >> 7, nb = nbkt % 128, kt = nbkt / 128;
        const int gr = lane >> 2, tg = lane & 3;
        const int n = nb * 8 + gr;
        const int k = kt * 32 + ks * 16 + kh * 8 + tg * 2;
        g_w2h[j] = __floats2half2_rn(wout[k * DIM + n], wout[(k+1) * DIM + n]);
    }
}

// ---- rmsnorm -> fp16 A-fragment layout ----
__global__ void __launch_bounds__(256) rmsnorm_kernel(
        const float* __restrict__ x, const float* __restrict__ w) {
    const int row = blockIdx.x;
    const int tid = threadIdx.x;
    const float4 xv = ((const float4*)(x + (size_t)row * DIM))[tid];
    float ss = xv.x*xv.x + xv.y*xv.y + xv.z*xv.z + xv.w*xv.w;
    #pragma unroll
    for (int off = 16; off > 0; off >>= 1)
        ss += __shfl_xor_sync(0xffffffffu, ss, off);
    __shared__ float wsum[8];
    const int lane = tid & 31, wid = tid >> 5;
    if (lane == 0) wsum[wid] = ss;
    __syncthreads();
    if (tid == 0) {
        float t = 0.f;
        #pragma unroll
        for (int i = 0; i < 8; ++i) t += wsum[i];
        wsum[0] = rsqrtf(t * (1.0f / DIM) + 1e-6f);
    }
    __syncthreads();
    const float scale = wsum[0];
    const float4 wv = ((const float4*)w)[tid];
    const int k0 = tid * 4;
    g_xnh[afrag_off(row, k0)]     = __floats2half2_rn(wv.x * (xv.x * scale), wv.y * (xv.y * scale));
    g_xnh[afrag_off(row, k0 + 2)] = __floats2half2_rn(wv.z * (xv.z * scale), wv.w * (xv.w * scale));
}

// ---- fp16 fragment-packed GEMM: 128x128x32 tiles, 4 warps of 64x64, 4-stage ----
template<int MODE>
__global__ void __launch_bounds__(128, 2) gemm_f16_kernel(
        const float* __restrict__ X, float* __restrict__ Out) {
    constexpr int KT = DIM / 32;
    constexpr int N = (MODE == 0) ? N1 : DIM;
    const __half2* __restrict__ Af = (MODE == 0) ? g_xnh : g_hfh;
    const __half2* __restrict__ Bf = (MODE == 0) ? g_w1h : g_w2h;

    extern __shared__ float smem[];
    const int tid = threadIdx.x;
    const int mb = blockIdx.y, n0 = blockIdx.x * 128;
    const int m0 = mb * 128;
    const uint32_t smem_base = smem_u32(smem);

    auto issue = [&](int kt) {
        if (kt < KT) {
            const uint32_t st = smem_base + (uint32_t)(kt & 3) * 16384u;
            const __half2* sA = Af + (size_t)(mb * 32 + kt) * 2048;
            const __half2* sB = Bf + ((size_t)kt * (N >> 3) + (n0 >> 3)) * 128;
            #pragma unroll
            for (int q = 0; q < 4; ++q)
                cp16(st + (uint32_t)(tid + q * 128) * 16u, sA + (tid + q * 128) * 4);
            #pragma unroll
            for (int q = 0; q < 4; ++q)
                cp16(st + 8192u + (uint32_t)(tid + q * 128) * 16u, sB + (tid + q * 128) * 4);
        }
        cp_commit();
    };

    float acc[4][8][4];
    #pragma unroll
    for (int i = 0; i < 4; ++i)
        #pragma unroll
        for (int j = 0; j < 8; ++j)
            #pragma unroll
            for (int q = 0; q < 4; ++q) acc[i][j][q] = 0.f;

    issue(0); issue(1); issue(2);

    const int lane = tid & 31, wid = tid >> 5;
    const int R0 = (wid >> 1) * 4;
    const int nb0 = (wid & 1) * 8;
    const int wm = R0 * 16, wn = nb0 * 8;
    const int gr = lane >> 2, tg = lane & 3;

    for (int kt = 0; kt < KT; ++kt) {
        cp_wait<2>();
        __syncthreads();
        issue(kt + 3);
        const __half2* As = (const __half2*)((const char*)smem + (kt & 3) * 16384);
        const __half2* Bs = As + 2048;
        #pragma unroll
        for (int ks = 0; ks < 2; ++ks) {
            float4 af[4]; float2 bf[8];
            #pragma unroll
            for (int i = 0; i < 4; ++i)
                af[i] = *(const float4*)(As + ((R0 + i) * 2 + ks) * 128 + lane * 4);
            #pragma unroll
            for (int j = 0; j < 8; ++j)
                bf[j] = *(const float2*)(Bs + ((nb0 + j) * 2 + ks) * 64 + lane * 2);
            #pragma unroll
            for (int i = 0; i < 4; ++i)
                #pragma unroll
                for (int j = 0; j < 8; ++j)
                    mma_f16(acc[i][j], FU(af[i].x), FU(af[i].y), FU(af[i].z), FU(af[i].w),
                            FU(bf[j].x), FU(bf[j].y));
        }
    }

    #pragma unroll
    for (int i = 0; i < 4; ++i) {
        #pragma unroll
        for (int j = 0; j < 8; ++j) {
            const int r0 = m0 + wm + i * 16 + gr;
            const int c0 = n0 + wn + j * 8 + tg * 2;
            if (MODE == 0) {
                if (c0 < NQKV) {
                    *(__half2*)(g_qkvh + (size_t)r0 * NQKV + c0) =
                        __floats2half2_rn(acc[i][j][0], acc[i][j][1]);
                    *(__half2*)(g_qkvh + (size_t)(r0 + 8) * NQKV + c0) =
                        __floats2half2_rn(acc[i][j][2], acc[i][j][3]);
                } else {
                    #pragma unroll
                    for (int q = 0; q < 4; ++q) {
                        const int r = r0 + (q >> 1) * 8;
                        const int c = c0 + (q & 1);
                        if (c < NQKV + NGATE) {
                            const int gl = c - NQKV;
                            float t = tanhf(acc[i][j][q] * (1.0f / 15.0f));
                            g_gt[(size_t)gl * MTOK + r] =
                                1.0f / (1.0f + expf(-15.0f * t));
                        }
                    }
                }
            } else {
                #pragma unroll
                for (int q = 0; q < 4; ++q) {
                    const int r = r0 + (q >> 1) * 8;
                    const int c = c0 + (q & 1);
                    Out[(size_t)r * DIM + c] = X[(size_t)r * DIM + c] + acc[i][j][q];
                }
            }
        }
    }
}

// ---- chunkwise phase 1: intra-chunk, fp16 m16n8k16 ----
#define SP 72     // half pitch
#define SP2 36    // half2 pitch
__global__ void __launch_bounds__(256) chunk_intra_kernel() {
    __shared__ __half Qh [64 * SP];   // (t,d); after GEMM1 reused as Ah (t,s)
    __shared__ __half Kh [64 * SP];   // (s,d)
    __shared__ __half Kth[64 * SP];   // (d,s) * Wc[s], col-swizzled
    __shared__ __half Vth[64 * SP];   // (e,s), col-swizzled
    __shared__ float LF[64], Wi[64], Wc[64];

    const int cidx = blockIdx.x;
    const int c = cidx & (NCHUNK - 1);
    const int bh = cidx >> 5;
    const int h = bh & 15, b = bh >> 4;
    const int m0 = b * SEQ + c * CHUNK;
    const int tid = threadIdx.x;

    float gi = 0.f, gf = 0.f;
    if (tid < 64) {
        gi = g_gt[(size_t)h * MTOK + m0 + tid];             // i gate
        gf = g_gt[(size_t)(NH + h) * MTOK + m0 + tid];      // f gate
    }
    uint4 hq[2], hk[2], hv[2];
    #pragma unroll
    for (int qq = 0; qq < 2; ++qq) {
        const int idx = tid + qq * 256;
        const int t = idx >> 3, d8 = (idx & 7) << 3;
        const __half* row = g_qkvh + (size_t)(m0 + t) * NQKV + h * 64 + d8;
        hq[qq] = *(const uint4*)row;
        hk[qq] = *(const uint4*)(row + 1024);
        hv[qq] = *(const uint4*)(row + 2048);
    }
    #pragma unroll
    for (int qq = 0; qq < 2; ++qq) {
        const int idx = tid + qq * 256;
        const int t = idx >> 3, d8 = (idx & 7) << 3;
        *(uint4*)(Qh + t * SP + d8) = hq[qq];
        *(uint4*)(Kh + t * SP + d8) = hk[qq];
        const __half* pv = (const __half*)&hv[qq];
        #pragma unroll
        for (int jj = 0; jj < 8; ++jj) {
            const int d = d8 + jj;
            Vth[d * SP + (t ^ (((d >> 2) & 15) << 1))] = pv[jj];
        }
    }
    if (tid < 64) { Wi[tid] = gi; LF[tid] = __logf(gf); }
    __syncthreads();

    if (tid < 32) {
        float x0 = LF[tid], x1 = LF[tid + 32];
        #pragma unroll
        for (int off = 1; off < 32; off <<= 1) {
            float y = __shfl_up_sync(0xffffffffu, x0, off);
            if (tid >= off) x0 += y;
        }
        const float tot = __shfl_sync(0xffffffffu, x0, 31);
        #pragma unroll
        for (int off = 1; off < 32; off <<= 1) {
            float y = __shfl_up_sync(0xffffffffu, x1, off);
            if (tid >= off) x1 += y;
        }
        x1 += tot;
        LF[tid] = x0; LF[tid + 32] = x1;
        g_el[(size_t)h * MTOK + m0 + tid]      = __expf(x0);
        g_el[(size_t)h * MTOK + m0 + tid + 32] = __expf(x1);
    }
    __syncthreads();
    if (tid < 64) Wc[tid] = __expf(LF[63] - LF[tid]) * Wi[tid];
    if (tid == 0) g_Fc[cidx] = __expf(LF[63]);
    __syncthreads();

    #pragma unroll
    for (int qq = 0; qq < 2; ++qq) {
        const int idx = tid + qq * 256;
        const int t = idx >> 3, d8 = (idx & 7) << 3;
        const float wcs = Wc[t];
        const __half* pk = (const __half*)&hk[qq];
        #pragma unroll
        for (int jj = 0; jj < 8; ++jj) {
            const int d = d8 + jj;
            Kth[d * SP + (t ^ (((d >> 2) & 15) << 1))] =
                __float2half(wcs * __half2float(pk[jj]));
        }
    }
    __syncthreads();

    const int lane = tid & 31, wid = tid >> 5;
    const int gr = lane >> 2, tg = lane & 3;
    const int wm = (wid >> 1) * 16, wn = (wid & 1) * 32;
    const int ra = wm + gr, rb = wm + 8 + gr;

    float acc1[4][4];
    #pragma unroll
    for (int j = 0; j < 4; ++j)
        #pragma unroll
        for (int q = 0; q < 4; ++q) acc1[j][q] = 0.f;
    {
        const __half2* Q2 = (const __half2*)Qh;
        const __half2* K2 = (const __half2*)Kh;
        #pragma unroll
        for (int ks = 0; ks < 4; ++ks) {
            const int kh2 = ks * 8 + tg;
            uint32_t a0 = H2U(Q2[ra * SP2 + kh2]);
            uint32_t a1 = H2U(Q2[rb * SP2 + kh2]);
            uint32_t a2 = H2U(Q2[ra * SP2 + kh2 + 4]);
            uint32_t a3 = H2U(Q2[rb * SP2 + kh2 + 4]);
            #pragma unroll
            for (int j = 0; j < 4; ++j) {
                const int n = wn + j * 8 + gr;
                mma_f16(acc1[j], a0, a1, a2, a3,
                        H2U(K2[n * SP2 + kh2]), H2U(K2[n * SP2 + kh2 + 4]));
            }
        }
    }
    __syncthreads();

    {
        __half* Ah = Qh;
        #pragma unroll
        for (int j = 0; j < 4; ++j)
            #pragma unroll
            for (int q = 0; q < 4; ++q) {
                const int t = wm + gr + (q >> 1) * 8;
                const int s = wn + j * 8 + tg * 2 + (q & 1);
                float v = 0.f;
                if (s <= t) v = acc1[j][q] * __expf(LF[t] - LF[s]) * Wi[s];
                Ah[t * SP + s] = __float2half(v);
            }
    }
    __syncthreads();

    float hacc[4][4], uacc[4][4];
    #pragma unroll
    for (int j = 0; j < 4; ++j)
        #pragma unroll
        for (int q = 0; q < 4; ++q) { hacc[j][q] = 0.f; uacc[j][q] = 0.f; }
    {
        const __half2* A2  = (const __half2*)Qh;
        const __half2* Kt2 = (const __half2*)Kth;
        const __half2* Vt2 = (const __half2*)Vth;
        const int swa = (ra >> 2) & 15, swb = (rb >> 2) & 15;
        #pragma unroll
        for (int ks = 0; ks < 4; ++ks) {
            const int kh2 = ks * 8 + tg;
            uint32_t ha0 = H2U(A2[ra * SP2 + kh2]);
            uint32_t ha1 = H2U(A2[rb * SP2 + kh2]);
            uint32_t ha2 = H2U(A2[ra * SP2 + kh2 + 4]);
            uint32_t ha3 = H2U(A2[rb * SP2 + kh2 + 4]);
            uint32_t ua0 = H2U(Kt2[ra * SP2 + (kh2 ^ swa)]);
            uint32_t ua1 = H2U(Kt2[rb * SP2 + (kh2 ^ swb)]);
            uint32_t ua2 = H2U(Kt2[ra * SP2 + ((kh2 + 4) ^ swa)]);
            uint32_t ua3 = H2U(Kt2[rb * SP2 + ((kh2 + 4) ^ swb)]);
            #pragma unroll
            for (int j = 0; j < 4; ++j) {
                const int n = wn + j * 8 + gr;
                const int swn = (n >> 2) & 15;
                uint32_t b0 = H2U(Vt2[n * SP2 + (kh2 ^ swn)]);
                uint32_t b1 = H2U(Vt2[n * SP2 + ((kh2 + 4) ^ swn)]);
                mma_f16(hacc[j], ha0, ha1, ha2, ha3, b0, b1);
                mma_f16(uacc[j], ua0, ua1, ua2, ua3, b0, b1);
            }
        }
    }
    #pragma unroll
    for (int j = 0; j < 4; ++j)
        #pragma unroll
        for (int qp = 0; qp < 2; ++qp) {
            const int row = wm + gr + qp * 8;
            const int col = wn + j * 8 + tg * 2;
            *(__half2*)(g_hh + (size_t)(m0 + row) * DIM + h * 64 + col) =
                __floats2half2_rn(hacc[j][qp*2], hacc[j][qp*2+1]);
            *(__half2*)(g_Uh + (size_t)cidx * 4096 + row * 64 + col) =
                __floats2half2_rn(uacc[j][qp*2], uacc[j][qp*2+1]);
        }
}

// ---- phase 2a: element-parallel state prefix (fp16 I/O, fp32 accum) ----
__global__ void __launch_bounds__(256) state_prefix_kernel(const float* __restrict__ hidden) {
    const int gid = blockIdx.x * 256 + threadIdx.x;   // 32768 threads
    const int bh = gid >> 9;
    const int off = (gid & 511) * 8;
    float S[8];
    {
        const float4 h0 = *(const float4*)(hidden + (size_t)bh * 4096 + off);
        const float4 h1 = *(const float4*)(hidden + (size_t)bh * 4096 + off + 4);
        S[0]=h0.x; S[1]=h0.y; S[2]=h0.z; S[3]=h0.w;
        S[4]=h1.x; S[5]=h1.y; S[6]=h1.z; S[7]=h1.w;
    }
    const float* fc = g_Fc + bh * NCHUNK;
    #pragma unroll 4
    for (int c = 0; c < NCHUNK; ++c) {
        const size_t p = (size_t)(bh * NCHUNK + c) * 4096 + off;
        uint4 so;
        __half2* ph = (__half2*)&so;
        #pragma unroll
        for (int e = 0; e < 4; ++e)
            ph[e] = __floats2half2_rn(S[e*2], S[e*2+1]);
        *(uint4*)(g_Sh + p) = so;
        const uint4 uu = *(const uint4*)(g_Uh + p);
        const __half2* pu = (const __half2*)&uu;
        const float F = fc[c];
        #pragma unroll
        for (int e = 0; e < 4; ++e) {
            const float2 uf = __half22float2(pu[e]);
            S[e*2]   = F * S[e*2]   + uf.x;
            S[e*2+1] = F * S[e*2+1] + uf.y;
        }
    }
}

// ---- phase 2b: h = (exp(LF)*q @ S_c + h_intra) * o, fp16 m16n8k16 ----
__global__ void __launch_bounds__(256) chunk_inter_kernel() {
    __shared__ __half Qsh[64 * SP];   // (t,d) = exp(LF_t) * q
    __shared__ __half Sth[64 * SP];   // (e,d) transposed S, col-swizzled
    __shared__ float Og[64], Eb[64];

    const int cidx = blockIdx.x;
    const int c = cidx & (NCHUNK - 1);
    const int bh = cidx >> 5;
    const int h = bh & 15, b = bh >> 4;
    const int m0 = b * SEQ + c * CHUNK;
    const int tid = threadIdx.x;

    uint4 hq[2], hs[2];
    #pragma unroll
    for (int qq = 0; qq < 2; ++qq) {
        const int idx = tid + qq * 256;
        const int t = idx >> 3, d8 = (idx & 7) << 3;
        hq[qq] = *(const uint4*)(g_qkvh + (size_t)(m0 + t) * NQKV + h * 64 + d8);
        hs[qq] = *(const uint4*)(g_Sh + (size_t)cidx * 4096 + t * 64 + d8);
    }
    if (tid < 64) {
        Og[tid] = g_gt[(size_t)(2 * NH + h) * MTOK + m0 + tid];
        Eb[tid] = g_el[(size_t)h * MTOK + m0 + tid];
    }
    __syncthreads();

    #pragma unroll
    for (int qq = 0; qq < 2; ++qq) {
        const int idx = tid + qq * 256;
        const int t = idx >> 3, d8 = (idx & 7) << 3;
        {
            const float e = Eb[t];
            const __half2* pq = (const __half2*)&hq[qq];
            __half2* dst = (__half2*)(Qsh + t * SP + d8);
            #pragma unroll
            for (int jj = 0; jj < 4; ++jj) {
                float2 f = __half22float2(pq[jj]);
                dst[jj] = __floats2half2_rn(f.x * e, f.y * e);
            }
        }
        {
            const int d = t;
            const __half* ps = (const __half*)&hs[qq];
            #pragma unroll
            for (int jj = 0; jj < 8; ++jj) {
                const int e = d8 + jj;
                Sth[e * SP + (d ^ (((e >> 2) & 15) << 1))] = ps[jj];
            }
        }
    }
    __syncthreads();

    const int lane = tid & 31, wid = tid >> 5;
    const int gr = lane >> 2, tg = lane & 3;
    const int wm = (wid >> 1) * 16, wn = (wid & 1) * 32;
    const int ra = wm + gr, rb = wm + 8 + gr;

    float acc[4][4];
    #pragma unroll
    for (int j = 0; j < 4; ++j)
        #pragma unroll
        for (int q = 0; q < 4; ++q) acc[j][q] = 0.f;
    {
        const __half2* Q2 = (const __half2*)Qsh;
        const __half2* St2 = (const __half2*)Sth;
        #pragma unroll
        for (int ks = 0; ks < 4; ++ks) {
            const int kh2 = ks * 8 + tg;
            uint32_t a0 = H2U(Q2[ra * SP2 + kh2]);
            uint32_t a1 = H2U(Q2[rb * SP2 + kh2]);
            uint32_t a2 = H2U(Q2[ra * SP2 + kh2 + 4]);
            uint32_t a3 = H2U(Q2[rb * SP2 + kh2 + 4]);
            #pragma unroll
            for (int j = 0; j < 4; ++j) {
                const int n = wn + j * 8 + gr;
                const int swn = (n >> 2) & 15;
                mma_f16(acc[j], a0, a1, a2, a3,
                        H2U(St2[n * SP2 + (kh2 ^ swn)]),
                        H2U(St2[n * SP2 + ((kh2 + 4) ^ swn)]));
            }
        }
    }

    #pragma unroll
    for (int j = 0; j < 4; ++j)
        #pragma unroll
        for (int qp = 0; qp < 2; ++qp) {
            const int row = wm + gr + qp * 8;
            const int col = wn + j * 8 + tg * 2;
            const int m = m0 + row;
            const float og = Og[row];
            const float2 hi = __half22float2(
                *(const __half2*)(g_hh + (size_t)m * DIM + h * 64 + col));
            const float hv0 = (acc[j][qp*2]   + hi.x) * og;
            const float hv1 = (acc[j][qp*2+1] + hi.y) * og;
            g_hfh[afrag_off(m, h * 64 + col)] = __floats2half2_rn(hv0, hv1);
        }
}

extern "C" void kernel_launch(void* const* d_in, const int* in_sizes, int n_in,
                              void* d_out, int out_size) {
    const float* x      = (const float*)d_in[0];
    const float* hidden = (const float*)d_in[1];
    const float* w_rms  = (const float*)d_in[2];
    const float* w_qkv  = (const float*)d_in[3];
    const float* w_gate = (const float*)d_in[4];
    const float* w_out  = (const float*)d_in[5];
    float* out = (float*)d_out;

    static bool attr_done = false;
    if (!attr_done) {
        cudaFuncSetAttribute(gemm_f16_kernel<0>,
            cudaFuncAttributeMaxDynamicSharedMemorySize, 65536);
        cudaFuncSetAttribute(gemm_f16_kernel<1>,
            cudaFuncAttributeMaxDynamicSharedMemorySize, 65536);
        attr_done = true;
    }

    const int PAIRS = N1 * DIM / 2 + DIM * DIM / 2;
    prep_weights_kernel<<<(PAIRS + 255) / 256, 256>>>(w_qkv, w_gate, w_out);
    rmsnorm_kernel<<<MTOK, 256>>>(x, w_rms);
    {
        dim3 grid(N1 / 128, MTOK / 128);
        gemm_f16_kernel<0><<<grid, 128, 65536>>>(nullptr, nullptr);
    }
    chunk_intra_kernel<<<TOTCHUNK, 256>>>();
    state_prefix_kernel<<<128, 256>>>(hidden);
    chunk_inter_kernel<<<TOTCHUNK, 256>>>();
    {
        dim3 grid(DIM / 128, MTOK / 128);
        gemm_f16_kernel<1><<<grid, 128, 65536>>>(x, out);
    }
}